// round 1
// baseline (speedup 1.0000x reference)
#include <cuda_runtime.h>

#define BB 2
#define SS 2048
#define DM 1024
#define HH 16
#define DH 64

// Scratch (allocation-free rule: __device__ globals)
__device__ float g_q[(size_t)BB * HH * SS * DH];     // [b,h,s,d]
__device__ float g_k[(size_t)BB * HH * SS * DH];     // [b,h,s,d]
__device__ float g_v[(size_t)BB * HH * SS * DH];     // [b,h,s,d]
__device__ float g_attn[(size_t)BB * SS * DM];       // [b,s,h*64+d]

// ---------------------------------------------------------------------------
// Kernel 1: per-head QKV projections.
// grid: (B*S/64 token tiles, H). 256 threads. Each CTA: 64 tokens x head h.
// ---------------------------------------------------------------------------
__global__ __launch_bounds__(256) void qkv_kernel(
    const float* __restrict__ x,
    const float* __restrict__ Wq, const float* __restrict__ bq,
    const float* __restrict__ Wk, const float* __restrict__ bk,
    const float* __restrict__ Wv, const float* __restrict__ bv)
{
    __shared__ float xs[64][65];
    __shared__ float ws[64][65];
    const int h    = blockIdx.y;
    const int tok0 = blockIdx.x * 64;
    const int tid  = threadIdx.x;
    const int ty = tid >> 4, tx = tid & 15;

    for (int idx = tid; idx < 64 * 64; idx += 256) {
        int t = idx >> 6, i = idx & 63;
        xs[t][i] = x[(size_t)(tok0 + t) * DM + h * DH + i];
    }

    const float* Wp[3] = {Wq, Wk, Wv};
    const float* bp[3] = {bq, bk, bv};
    float*       op[3] = {g_q, g_k, g_v};

    for (int p = 0; p < 3; p++) {
        __syncthreads();
        for (int idx = tid; idx < 64 * 64; idx += 256) {
            int o = idx >> 6, i = idx & 63;
            ws[o][i] = Wp[p][(size_t)(h * DH + o) * DH + i];
        }
        __syncthreads();

        float acc[4][4] = {};
#pragma unroll 8
        for (int i = 0; i < 64; i++) {
            float xv[4], wv[4];
#pragma unroll
            for (int a = 0; a < 4; a++) xv[a] = xs[ty * 4 + a][i];
#pragma unroll
            for (int b = 0; b < 4; b++) wv[b] = ws[tx * 4 + b][i];
#pragma unroll
            for (int a = 0; a < 4; a++)
#pragma unroll
                for (int b = 0; b < 4; b++)
                    acc[a][b] = fmaf(xv[a], wv[b], acc[a][b]);
        }

#pragma unroll
        for (int a = 0; a < 4; a++) {
            int g    = tok0 + ty * 4 + a;
            int bidx = g >> 11;          // / SS
            int s    = g & (SS - 1);
#pragma unroll
            for (int b = 0; b < 4; b++) {
                int o = tx * 4 + b;
                op[p][(((size_t)bidx * HH + h) * SS + s) * DH + o] =
                    acc[a][b] + bp[p][h * DH + o];
            }
        }
    }
}

// ---------------------------------------------------------------------------
// Kernel 2: causal flash attention. grid: (S/64 q-tiles, B*H). 256 threads.
// Dynamic smem (>48KB static limit): qs, ks, vs, ps (64x65 each) + row stats.
// ---------------------------------------------------------------------------
#define ATTN_SMEM_FLOATS (4 * 64 * 65 + 3 * 64)
#define ATTN_SMEM_BYTES  (ATTN_SMEM_FLOATS * sizeof(float))

__global__ __launch_bounds__(256) void attn_kernel()
{
    extern __shared__ float smem[];
    float (*qs)[65] = (float (*)[65])(smem);
    float (*ks)[65] = (float (*)[65])(smem + 64 * 65);
    float (*vs)[65] = (float (*)[65])(smem + 2 * 64 * 65);
    float (*ps)[65] = (float (*)[65])(smem + 3 * 64 * 65);
    float* m_s  = smem + 4 * 64 * 65;
    float* l_s  = m_s + 64;
    float* al_s = l_s + 64;

    // Reverse order: heaviest q-tiles (most key tiles) launch first.
    const int qt = gridDim.x - 1 - blockIdx.x;
    const int bh = blockIdx.y;
    const float* Qb = g_q + (size_t)bh * SS * DH;
    const float* Kb = g_k + (size_t)bh * SS * DH;
    const float* Vb = g_v + (size_t)bh * SS * DH;
    const int q0  = qt * 64;
    const int tid = threadIdx.x;
    const int ty = tid >> 4, tx = tid & 15;
    const int warp = tid >> 5, lane = tid & 31;

    for (int idx = tid; idx < 64 * 64; idx += 256) {
        int t = idx >> 6, d = idx & 63;
        qs[t][d] = Qb[(size_t)(q0 + t) * DH + d] * 0.125f;  // 1/sqrt(64)
    }
    if (tid < 64) { m_s[tid] = -1e30f; l_s[tid] = 0.0f; }

    float o_acc[4][4] = {};
    const int nkt = qt + 1;

    for (int kt = 0; kt < nkt; kt++) {
        __syncthreads();
        for (int idx = tid; idx < 64 * 64; idx += 256) {
            int t = idx >> 6, d = idx & 63;
            ks[t][d] = Kb[(size_t)(kt * 64 + t) * DH + d];
            vs[t][d] = Vb[(size_t)(kt * 64 + t) * DH + d];
        }
        __syncthreads();

        // S = Q K^T (scaled)
        float sacc[4][4] = {};
#pragma unroll 8
        for (int i = 0; i < 64; i++) {
            float qv[4], kv[4];
#pragma unroll
            for (int a = 0; a < 4; a++) qv[a] = qs[ty * 4 + a][i];
#pragma unroll
            for (int b = 0; b < 4; b++) kv[b] = ks[tx * 4 + b][i];
#pragma unroll
            for (int a = 0; a < 4; a++)
#pragma unroll
                for (int b = 0; b < 4; b++)
                    sacc[a][b] = fmaf(qv[a], kv[b], sacc[a][b]);
        }
        const bool diag = (kt == qt);
#pragma unroll
        for (int a = 0; a < 4; a++)
#pragma unroll
            for (int b = 0; b < 4; b++) {
                float v = sacc[a][b];
                if (diag && (tx * 4 + b) > (ty * 4 + a)) v = -1e30f;
                ps[ty * 4 + a][tx * 4 + b] = v;
            }
        __syncthreads();

        // Online softmax: each warp owns 8 rows.
#pragma unroll
        for (int r = 0; r < 8; r++) {
            int row = warp * 8 + r;
            float v0 = ps[row][lane], v1 = ps[row][lane + 32];
            float mx = fmaxf(v0, v1);
#pragma unroll
            for (int off = 16; off; off >>= 1)
                mx = fmaxf(mx, __shfl_xor_sync(0xffffffffu, mx, off));
            float mold = m_s[row];
            float mnew = fmaxf(mold, mx);
            float p0 = __expf(v0 - mnew), p1 = __expf(v1 - mnew);
            ps[row][lane] = p0;
            ps[row][lane + 32] = p1;
            float sum = p0 + p1;
#pragma unroll
            for (int off = 16; off; off >>= 1)
                sum += __shfl_xor_sync(0xffffffffu, sum, off);
            if (lane == 0) {
                float alpha = __expf(mold - mnew);
                m_s[row]  = mnew;
                l_s[row]  = l_s[row] * alpha + sum;
                al_s[row] = alpha;
            }
        }
        __syncthreads();

        // Rescale running O and accumulate P @ V
#pragma unroll
        for (int a = 0; a < 4; a++) {
            float al = al_s[ty * 4 + a];
#pragma unroll
            for (int b = 0; b < 4; b++) o_acc[a][b] *= al;
        }
#pragma unroll 8
        for (int j = 0; j < 64; j++) {
            float pv[4], vv[4];
#pragma unroll
            for (int a = 0; a < 4; a++) pv[a] = ps[ty * 4 + a][j];
#pragma unroll
            for (int b = 0; b < 4; b++) vv[b] = vs[j][tx * 4 + b];
#pragma unroll
            for (int a = 0; a < 4; a++)
#pragma unroll
                for (int b = 0; b < 4; b++)
                    o_acc[a][b] = fmaf(pv[a], vv[b], o_acc[a][b]);
        }
    }

    const int bidx = bh / HH, h = bh % HH;
#pragma unroll
    for (int a = 0; a < 4; a++) {
        float inv = 1.0f / l_s[ty * 4 + a];
        int s = q0 + ty * 4 + a;
#pragma unroll
        for (int b = 0; b < 4; b++) {
            g_attn[((size_t)bidx * SS + s) * DM + h * DH + tx * 4 + b] =
                o_acc[a][b] * inv;
        }
    }
}

// ---------------------------------------------------------------------------
// Kernel 3: output projection. C[4096,1024] = A @ Wo^T + bo.
// grid: (N/64, M/64). 256 threads, 64x64x16 tiles, 4x4 micro-tile.
// ---------------------------------------------------------------------------
__global__ __launch_bounds__(256) void proj_kernel(
    const float* __restrict__ Wo, const float* __restrict__ bo,
    float* __restrict__ out)
{
    __shared__ float As[64][17];
    __shared__ float Bs[64][17];
    const int n0 = blockIdx.x * 64;
    const int m0 = blockIdx.y * 64;
    const int tid = threadIdx.x;
    const int ty = tid >> 4, tx = tid & 15;

    float acc[4][4] = {};
    for (int k0 = 0; k0 < DM; k0 += 16) {
        __syncthreads();
        for (int idx = tid; idx < 64 * 16; idx += 256) {
            int r = idx >> 4, k = idx & 15;
            As[r][k] = g_attn[(size_t)(m0 + r) * DM + k0 + k];
            Bs[r][k] = Wo[(size_t)(n0 + r) * DM + k0 + k];
        }
        __syncthreads();
#pragma unroll
        for (int k = 0; k < 16; k++) {
            float av[4], wv[4];
#pragma unroll
            for (int a = 0; a < 4; a++) av[a] = As[ty * 4 + a][k];
#pragma unroll
            for (int b = 0; b < 4; b++) wv[b] = Bs[tx * 4 + b][k];
#pragma unroll
            for (int a = 0; a < 4; a++)
#pragma unroll
                for (int b = 0; b < 4; b++)
                    acc[a][b] = fmaf(av[a], wv[b], acc[a][b]);
        }
    }
#pragma unroll
    for (int a = 0; a < 4; a++)
#pragma unroll
        for (int b = 0; b < 4; b++)
            out[(size_t)(m0 + ty * 4 + a) * DM + n0 + tx * 4 + b] =
                acc[a][b] + bo[n0 + tx * 4 + b];
}

// ---------------------------------------------------------------------------
extern "C" void kernel_launch(void* const* d_in, const int* in_sizes, int n_in,
                              void* d_out, int out_size)
{
    const float* x  = (const float*)d_in[0];
    const float* Wq = (const float*)d_in[1];
    const float* bq = (const float*)d_in[2];
    const float* Wk = (const float*)d_in[3];
    const float* bk = (const float*)d_in[4];
    const float* Wv = (const float*)d_in[5];
    const float* bv = (const float*)d_in[6];
    const float* Wo = (const float*)d_in[7];
    const float* bo = (const float*)d_in[8];
    float* out = (float*)d_out;

    cudaFuncSetAttribute(attn_kernel,
                         cudaFuncAttributeMaxDynamicSharedMemorySize,
                         (int)ATTN_SMEM_BYTES);

    qkv_kernel<<<dim3(BB * SS / 64, HH), 256>>>(x, Wq, bq, Wk, bk, Wv, bv);
    attn_kernel<<<dim3(SS / 64, BB * HH), 256, ATTN_SMEM_BYTES>>>();
    proj_kernel<<<dim3(DM / 64, BB * SS / 64), 256>>>(Wo, bo, out);
}

// round 4
// speedup vs baseline: 1.2396x; 1.2396x over previous
#include <cuda_runtime.h>
#include <cstdint>

#define BB 2
#define SS 2048
#define DM 1024
#define HH 16
#define DH 64

// Scratch (allocation-free rule: __device__ globals)
__device__ float g_q[(size_t)BB * HH * SS * DH];     // [b,h,s,d]
__device__ float g_k[(size_t)BB * HH * SS * DH];     // [b,h,s,d]
__device__ float g_v[(size_t)BB * HH * SS * DH];     // [b,h,s,d]
__device__ float g_attn[(size_t)BB * SS * DM];       // [b,s,h*64+d]

// ---------------------------------------------------------------------------
// tf32 helpers (mma.sync path — works on base compute_103 target)
// ---------------------------------------------------------------------------
__device__ __forceinline__ void tf32_split(float x, float& hi, float& lo) {
    uint32_t h;
    asm("cvt.rna.tf32.f32 %0, %1;" : "=r"(h) : "f"(x));
    hi = __uint_as_float(h);
    float r = x - hi;
    uint32_t l;
    asm("cvt.rna.tf32.f32 %0, %1;" : "=r"(l) : "f"(r));
    lo = __uint_as_float(l);
}

__device__ __forceinline__ void mma_tf32(float c[4],
                                         uint32_t a0, uint32_t a1,
                                         uint32_t a2, uint32_t a3,
                                         uint32_t b0, uint32_t b1) {
    asm volatile(
        "mma.sync.aligned.m16n8k8.row.col.f32.tf32.tf32.f32 "
        "{%0,%1,%2,%3}, {%4,%5,%6,%7}, {%8,%9}, {%0,%1,%2,%3};"
        : "+f"(c[0]), "+f"(c[1]), "+f"(c[2]), "+f"(c[3])
        : "r"(a0), "r"(a1), "r"(a2), "r"(a3), "r"(b0), "r"(b1));
}

// ---------------------------------------------------------------------------
// Kernel 1: per-head QKV projections. (unchanged)
// ---------------------------------------------------------------------------
__global__ __launch_bounds__(256) void qkv_kernel(
    const float* __restrict__ x,
    const float* __restrict__ Wq, const float* __restrict__ bq,
    const float* __restrict__ Wk, const float* __restrict__ bk,
    const float* __restrict__ Wv, const float* __restrict__ bv)
{
    __shared__ float xs[64][65];
    __shared__ float ws[64][65];
    const int h    = blockIdx.y;
    const int tok0 = blockIdx.x * 64;
    const int tid  = threadIdx.x;
    const int ty = tid >> 4, tx = tid & 15;

    for (int idx = tid; idx < 64 * 64; idx += 256) {
        int t = idx >> 6, i = idx & 63;
        xs[t][i] = x[(size_t)(tok0 + t) * DM + h * DH + i];
    }

    const float* Wp[3] = {Wq, Wk, Wv};
    const float* bp[3] = {bq, bk, bv};
    float*       op[3] = {g_q, g_k, g_v};

    for (int p = 0; p < 3; p++) {
        __syncthreads();
        for (int idx = tid; idx < 64 * 64; idx += 256) {
            int o = idx >> 6, i = idx & 63;
            ws[o][i] = Wp[p][(size_t)(h * DH + o) * DH + i];
        }
        __syncthreads();

        float acc[4][4] = {};
#pragma unroll 8
        for (int i = 0; i < 64; i++) {
            float xv[4], wv[4];
#pragma unroll
            for (int a = 0; a < 4; a++) xv[a] = xs[ty * 4 + a][i];
#pragma unroll
            for (int b = 0; b < 4; b++) wv[b] = ws[tx * 4 + b][i];
#pragma unroll
            for (int a = 0; a < 4; a++)
#pragma unroll
                for (int b = 0; b < 4; b++)
                    acc[a][b] = fmaf(xv[a], wv[b], acc[a][b]);
        }

#pragma unroll
        for (int a = 0; a < 4; a++) {
            int g    = tok0 + ty * 4 + a;
            int bidx = g >> 11;
            int s    = g & (SS - 1);
#pragma unroll
            for (int b = 0; b < 4; b++) {
                int o = tx * 4 + b;
                op[p][(((size_t)bidx * HH + h) * SS + s) * DH + o] =
                    acc[a][b] + bp[p][h * DH + o];
            }
        }
    }
}

// ---------------------------------------------------------------------------
// Kernel 2: causal flash attention. (unchanged)
// ---------------------------------------------------------------------------
#define ATTN_SMEM_FLOATS (4 * 64 * 65 + 3 * 64)
#define ATTN_SMEM_BYTES  (ATTN_SMEM_FLOATS * sizeof(float))

__global__ __launch_bounds__(256) void attn_kernel()
{
    extern __shared__ float smem[];
    float (*qs)[65] = (float (*)[65])(smem);
    float (*ks)[65] = (float (*)[65])(smem + 64 * 65);
    float (*vs)[65] = (float (*)[65])(smem + 2 * 64 * 65);
    float (*ps)[65] = (float (*)[65])(smem + 3 * 64 * 65);
    float* m_s  = smem + 4 * 64 * 65;
    float* l_s  = m_s + 64;
    float* al_s = l_s + 64;

    const int qt = gridDim.x - 1 - blockIdx.x;
    const int bh = blockIdx.y;
    const float* Qb = g_q + (size_t)bh * SS * DH;
    const float* Kb = g_k + (size_t)bh * SS * DH;
    const float* Vb = g_v + (size_t)bh * SS * DH;
    const int q0  = qt * 64;
    const int tid = threadIdx.x;
    const int ty = tid >> 4, tx = tid & 15;
    const int warp = tid >> 5, lane = tid & 31;

    for (int idx = tid; idx < 64 * 64; idx += 256) {
        int t = idx >> 6, d = idx & 63;
        qs[t][d] = Qb[(size_t)(q0 + t) * DH + d] * 0.125f;
    }
    if (tid < 64) { m_s[tid] = -1e30f; l_s[tid] = 0.0f; }

    float o_acc[4][4] = {};
    const int nkt = qt + 1;

    for (int kt = 0; kt < nkt; kt++) {
        __syncthreads();
        for (int idx = tid; idx < 64 * 64; idx += 256) {
            int t = idx >> 6, d = idx & 63;
            ks[t][d] = Kb[(size_t)(kt * 64 + t) * DH + d];
            vs[t][d] = Vb[(size_t)(kt * 64 + t) * DH + d];
        }
        __syncthreads();

        float sacc[4][4] = {};
#pragma unroll 8
        for (int i = 0; i < 64; i++) {
            float qv[4], kv[4];
#pragma unroll
            for (int a = 0; a < 4; a++) qv[a] = qs[ty * 4 + a][i];
#pragma unroll
            for (int b = 0; b < 4; b++) kv[b] = ks[tx * 4 + b][i];
#pragma unroll
            for (int a = 0; a < 4; a++)
#pragma unroll
                for (int b = 0; b < 4; b++)
                    sacc[a][b] = fmaf(qv[a], kv[b], sacc[a][b]);
        }
        const bool diag = (kt == qt);
#pragma unroll
        for (int a = 0; a < 4; a++)
#pragma unroll
            for (int b = 0; b < 4; b++) {
                float v = sacc[a][b];
                if (diag && (tx * 4 + b) > (ty * 4 + a)) v = -1e30f;
                ps[ty * 4 + a][tx * 4 + b] = v;
            }
        __syncthreads();

#pragma unroll
        for (int r = 0; r < 8; r++) {
            int row = warp * 8 + r;
            float v0 = ps[row][lane], v1 = ps[row][lane + 32];
            float mx = fmaxf(v0, v1);
#pragma unroll
            for (int off = 16; off; off >>= 1)
                mx = fmaxf(mx, __shfl_xor_sync(0xffffffffu, mx, off));
            float mold = m_s[row];
            float mnew = fmaxf(mold, mx);
            float p0 = __expf(v0 - mnew), p1 = __expf(v1 - mnew);
            ps[row][lane] = p0;
            ps[row][lane + 32] = p1;
            float sum = p0 + p1;
#pragma unroll
            for (int off = 16; off; off >>= 1)
                sum += __shfl_xor_sync(0xffffffffu, sum, off);
            if (lane == 0) {
                float alpha = __expf(mold - mnew);
                m_s[row]  = mnew;
                l_s[row]  = l_s[row] * alpha + sum;
                al_s[row] = alpha;
            }
        }
        __syncthreads();

#pragma unroll
        for (int a = 0; a < 4; a++) {
            float al = al_s[ty * 4 + a];
#pragma unroll
            for (int b = 0; b < 4; b++) o_acc[a][b] *= al;
        }
#pragma unroll 8
        for (int j = 0; j < 64; j++) {
            float pv[4], vv[4];
#pragma unroll
            for (int a = 0; a < 4; a++) pv[a] = ps[ty * 4 + a][j];
#pragma unroll
            for (int b = 0; b < 4; b++) vv[b] = vs[j][tx * 4 + b];
#pragma unroll
            for (int a = 0; a < 4; a++)
#pragma unroll
                for (int b = 0; b < 4; b++)
                    o_acc[a][b] = fmaf(pv[a], vv[b], o_acc[a][b]);
        }
    }

    const int bidx = bh / HH, h = bh % HH;
#pragma unroll
    for (int a = 0; a < 4; a++) {
        float inv = 1.0f / l_s[ty * 4 + a];
        int s = q0 + ty * 4 + a;
#pragma unroll
        for (int b = 0; b < 4; b++) {
            g_attn[((size_t)bidx * SS + s) * DM + h * DH + tx * 4 + b] =
                o_acc[a][b] * inv;
        }
    }
}

// ---------------------------------------------------------------------------
// Kernel 3: output projection via mma.sync tf32 (2-way split).
// C[4096,1024] = A @ Wo^T + bo.
// CTA 128(M) x 128(N), 8 warps as 2(M) x 4(N), warp tile 64x32.
// K-chunk 32, hi/lo split done during smem staging.
// smem stride 36 floats: fragment loads are bank-conflict-free.
// ---------------------------------------------------------------------------
#define PROJ_SMEM_FLOATS (4 * 128 * 36)
#define PROJ_SMEM_BYTES  (PROJ_SMEM_FLOATS * sizeof(float))   // 73728

__global__ __launch_bounds__(256) void proj_mma_kernel(
    const float* __restrict__ Wo, const float* __restrict__ bo,
    float* __restrict__ out)
{
    extern __shared__ float pshm[];
    float (*As_hi)[36] = (float (*)[36])(pshm);
    float (*As_lo)[36] = (float (*)[36])(pshm + 128 * 36);
    float (*Bs_hi)[36] = (float (*)[36])(pshm + 2 * 128 * 36);
    float (*Bs_lo)[36] = (float (*)[36])(pshm + 3 * 128 * 36);

    const int n0 = blockIdx.x * 128;
    const int m0 = blockIdx.y * 128;
    const int tid  = threadIdx.x;
    const int lane = tid & 31, warp = tid >> 5;
    const int wm = (warp >> 2) * 64;     // 0 / 64
    const int wn = (warp & 3) * 32;      // 0,32,64,96
    const int gid = lane >> 2, tig = lane & 3;

    float c[4][4][4] = {};               // [mtile][ntile][frag]

    for (int k0 = 0; k0 < DM; k0 += 32) {
        __syncthreads();
        // stage + split: A rows (m) and B rows (n), 32 K-cols each
        for (int idx = tid; idx < 1024; idx += 256) {
            int r = idx >> 3, q = (idx & 7) << 2;
            float4 va = *(const float4*)&g_attn[(size_t)(m0 + r) * DM + k0 + q];
            float4 vb = *(const float4*)&Wo[(size_t)(n0 + r) * DM + k0 + q];
            float h0, l0, h1, l1, h2, l2, h3, l3;
            tf32_split(va.x, h0, l0); tf32_split(va.y, h1, l1);
            tf32_split(va.z, h2, l2); tf32_split(va.w, h3, l3);
            *(float4*)&As_hi[r][q] = make_float4(h0, h1, h2, h3);
            *(float4*)&As_lo[r][q] = make_float4(l0, l1, l2, l3);
            tf32_split(vb.x, h0, l0); tf32_split(vb.y, h1, l1);
            tf32_split(vb.z, h2, l2); tf32_split(vb.w, h3, l3);
            *(float4*)&Bs_hi[r][q] = make_float4(h0, h1, h2, h3);
            *(float4*)&Bs_lo[r][q] = make_float4(l0, l1, l2, l3);
        }
        __syncthreads();

#pragma unroll
        for (int ks = 0; ks < 4; ks++) {
            const int kc = ks * 8 + tig;
            uint32_t ah[4][4], al[4][4];
#pragma unroll
            for (int mt = 0; mt < 4; mt++) {
                int mr = wm + mt * 16 + gid;
                ah[mt][0] = __float_as_uint(As_hi[mr][kc]);
                ah[mt][1] = __float_as_uint(As_hi[mr + 8][kc]);
                ah[mt][2] = __float_as_uint(As_hi[mr][kc + 4]);
                ah[mt][3] = __float_as_uint(As_hi[mr + 8][kc + 4]);
                al[mt][0] = __float_as_uint(As_lo[mr][kc]);
                al[mt][1] = __float_as_uint(As_lo[mr + 8][kc]);
                al[mt][2] = __float_as_uint(As_lo[mr][kc + 4]);
                al[mt][3] = __float_as_uint(As_lo[mr + 8][kc + 4]);
            }
            uint32_t bh[4][2], bl[4][2];
#pragma unroll
            for (int nt = 0; nt < 4; nt++) {
                int nr = wn + nt * 8 + gid;
                bh[nt][0] = __float_as_uint(Bs_hi[nr][kc]);
                bh[nt][1] = __float_as_uint(Bs_hi[nr][kc + 4]);
                bl[nt][0] = __float_as_uint(Bs_lo[nr][kc]);
                bl[nt][1] = __float_as_uint(Bs_lo[nr][kc + 4]);
            }
#pragma unroll
            for (int mt = 0; mt < 4; mt++)
#pragma unroll
                for (int nt = 0; nt < 4; nt++) {
                    mma_tf32(c[mt][nt], ah[mt][0], ah[mt][1], ah[mt][2], ah[mt][3],
                             bh[nt][0], bh[nt][1]);
                    mma_tf32(c[mt][nt], ah[mt][0], ah[mt][1], ah[mt][2], ah[mt][3],
                             bl[nt][0], bl[nt][1]);
                    mma_tf32(c[mt][nt], al[mt][0], al[mt][1], al[mt][2], al[mt][3],
                             bh[nt][0], bh[nt][1]);
                }
        }
    }

    // Epilogue: c0/c1 -> (row=gid, col=2*tig, 2*tig+1); c2/c3 -> row=gid+8
#pragma unroll
    for (int mt = 0; mt < 4; mt++) {
#pragma unroll
        for (int nt = 0; nt < 4; nt++) {
            int m  = m0 + wm + mt * 16 + gid;
            int n  = n0 + wn + nt * 8 + tig * 2;
            float2 v0, v1;
            v0.x = c[mt][nt][0] + bo[n];
            v0.y = c[mt][nt][1] + bo[n + 1];
            v1.x = c[mt][nt][2] + bo[n];
            v1.y = c[mt][nt][3] + bo[n + 1];
            *(float2*)&out[(size_t)m * DM + n]       = v0;
            *(float2*)&out[(size_t)(m + 8) * DM + n] = v1;
        }
    }
}

// ---------------------------------------------------------------------------
extern "C" void kernel_launch(void* const* d_in, const int* in_sizes, int n_in,
                              void* d_out, int out_size)
{
    const float* x  = (const float*)d_in[0];
    const float* Wq = (const float*)d_in[1];
    const float* bq = (const float*)d_in[2];
    const float* Wk = (const float*)d_in[3];
    const float* bk = (const float*)d_in[4];
    const float* Wv = (const float*)d_in[5];
    const float* bv = (const float*)d_in[6];
    const float* Wo = (const float*)d_in[7];
    const float* bo = (const float*)d_in[8];
    float* out = (float*)d_out;

    cudaFuncSetAttribute(attn_kernel,
                         cudaFuncAttributeMaxDynamicSharedMemorySize,
                         (int)ATTN_SMEM_BYTES);
    cudaFuncSetAttribute(proj_mma_kernel,
                         cudaFuncAttributeMaxDynamicSharedMemorySize,
                         (int)PROJ_SMEM_BYTES);

    qkv_kernel<<<dim3(BB * SS / 64, HH), 256>>>(x, Wq, bq, Wk, bk, Wv, bv);
    attn_kernel<<<dim3(SS / 64, BB * HH), 256, ATTN_SMEM_BYTES>>>();
    proj_mma_kernel<<<dim3(DM / 128, BB * SS / 128), 256, PROJ_SMEM_BYTES>>>(Wo, bo, out);
}

// round 5
// speedup vs baseline: 1.8006x; 1.4526x over previous
#include <cuda_runtime.h>
#include <cstdint>

#define BB 2
#define SS 2048
#define DM 1024
#define HH 16
#define DH 64

// Scratch (allocation-free rule: __device__ globals)
__device__ float g_q[(size_t)BB * HH * SS * DH];     // [b,h,s,d]
__device__ float g_k[(size_t)BB * HH * SS * DH];     // [b,h,s,d]
__device__ float g_v[(size_t)BB * HH * SS * DH];     // [b,h,s,d]
__device__ float g_attn[(size_t)BB * SS * DM];       // [b,s,h*64+d]

// ---------------------------------------------------------------------------
// tf32 helpers (mma.sync path — works on base compute_103 target)
// ---------------------------------------------------------------------------
__device__ __forceinline__ void tf32_split(float x, float& hi, float& lo) {
    uint32_t h;
    asm("cvt.rna.tf32.f32 %0, %1;" : "=r"(h) : "f"(x));
    hi = __uint_as_float(h);
    float r = x - hi;
    uint32_t l;
    asm("cvt.rna.tf32.f32 %0, %1;" : "=r"(l) : "f"(r));
    lo = __uint_as_float(l);
}
__device__ __forceinline__ float tf32_round(float x) {
    uint32_t u;
    asm("cvt.rna.tf32.f32 %0, %1;" : "=r"(u) : "f"(x));
    return __uint_as_float(u);
}

__device__ __forceinline__ void mma_tf32(float c[4],
                                         uint32_t a0, uint32_t a1,
                                         uint32_t a2, uint32_t a3,
                                         uint32_t b0, uint32_t b1) {
    asm volatile(
        "mma.sync.aligned.m16n8k8.row.col.f32.tf32.tf32.f32 "
        "{%0,%1,%2,%3}, {%4,%5,%6,%7}, {%8,%9}, {%0,%1,%2,%3};"
        : "+f"(c[0]), "+f"(c[1]), "+f"(c[2]), "+f"(c[3])
        : "r"(a0), "r"(a1), "r"(a2), "r"(a3), "r"(b0), "r"(b1));
}

// ---------------------------------------------------------------------------
// Kernel 1: per-head QKV projections. (unchanged)
// ---------------------------------------------------------------------------
__global__ __launch_bounds__(256) void qkv_kernel(
    const float* __restrict__ x,
    const float* __restrict__ Wq, const float* __restrict__ bq,
    const float* __restrict__ Wk, const float* __restrict__ bk,
    const float* __restrict__ Wv, const float* __restrict__ bv)
{
    __shared__ float xs[64][65];
    __shared__ float ws[64][65];
    const int h    = blockIdx.y;
    const int tok0 = blockIdx.x * 64;
    const int tid  = threadIdx.x;
    const int ty = tid >> 4, tx = tid & 15;

    for (int idx = tid; idx < 64 * 64; idx += 256) {
        int t = idx >> 6, i = idx & 63;
        xs[t][i] = x[(size_t)(tok0 + t) * DM + h * DH + i];
    }

    const float* Wp[3] = {Wq, Wk, Wv};
    const float* bp[3] = {bq, bk, bv};
    float*       op[3] = {g_q, g_k, g_v};

    for (int p = 0; p < 3; p++) {
        __syncthreads();
        for (int idx = tid; idx < 64 * 64; idx += 256) {
            int o = idx >> 6, i = idx & 63;
            ws[o][i] = Wp[p][(size_t)(h * DH + o) * DH + i];
        }
        __syncthreads();

        float acc[4][4] = {};
#pragma unroll 8
        for (int i = 0; i < 64; i++) {
            float xv[4], wv[4];
#pragma unroll
            for (int a = 0; a < 4; a++) xv[a] = xs[ty * 4 + a][i];
#pragma unroll
            for (int b = 0; b < 4; b++) wv[b] = ws[tx * 4 + b][i];
#pragma unroll
            for (int a = 0; a < 4; a++)
#pragma unroll
                for (int b = 0; b < 4; b++)
                    acc[a][b] = fmaf(xv[a], wv[b], acc[a][b]);
        }

#pragma unroll
        for (int a = 0; a < 4; a++) {
            int g    = tok0 + ty * 4 + a;
            int bidx = g >> 11;
            int s    = g & (SS - 1);
#pragma unroll
            for (int b = 0; b < 4; b++) {
                int o = tx * 4 + b;
                op[p][(((size_t)bidx * HH + h) * SS + s) * DH + o] =
                    acc[a][b] + bp[p][h * DH + o];
            }
        }
    }
}

// ---------------------------------------------------------------------------
// Kernel 2: causal flash attention via mma.sync tf32.
// CTA: 128 q-rows x one (b,h). 8 warps, warp = 16 q-rows (full row per warp).
// Per 64-key tile: S = Q K^T (3-product tf32 split), online softmax in regs,
// P stored single-tf32, O += P V (V hi/lo split, 2 products). O in registers.
// Smem stride 68 (== 4 mod 32) -> conflict-free fragment LDS.
// ---------------------------------------------------------------------------
#define AQH 0
#define AQL 8704
#define AKH 17408
#define AKL 21760
#define AVH 26112
#define AVL 30464
#define APS 34816
#define ATTN2_SMEM_FLOATS 43520
#define ATTN2_SMEM_BYTES  (ATTN2_SMEM_FLOATS * 4)   // 174080

__global__ __launch_bounds__(256, 1) void attn_mma_kernel()
{
    extern __shared__ float sm[];
    float* Qh = sm + AQH;  float* Ql = sm + AQL;
    float* Kh = sm + AKH;  float* Kl = sm + AKL;
    float* Vh = sm + AVH;  float* Vl = sm + AVL;
    float* Ps = sm + APS;

    const int qt = gridDim.x - 1 - blockIdx.x;   // heavy tiles first
    const int bh = blockIdx.y;
    const int q0 = qt * 128;
    const float* Qg = g_q + (size_t)bh * SS * DH;
    const float* Kg = g_k + (size_t)bh * SS * DH;
    const float* Vg = g_v + (size_t)bh * SS * DH;

    const int tid  = threadIdx.x;
    const int warp = tid >> 5, lane = tid & 31;
    const int gid  = lane >> 2, tig = lane & 3;
    const int wr   = warp * 16;                  // warp's q-row base (local)

    // ---- load Q (once), scale + split ----
    for (int idx = tid; idx < 2048; idx += 256) {
        int r = idx >> 4, d = (idx & 15) << 2;
        float4 v = *(const float4*)&Qg[(size_t)(q0 + r) * DH + d];
        float h0, l0, h1, l1, h2, l2, h3, l3;
        tf32_split(v.x * 0.125f, h0, l0); tf32_split(v.y * 0.125f, h1, l1);
        tf32_split(v.z * 0.125f, h2, l2); tf32_split(v.w * 0.125f, h3, l3);
        *(float4*)&Qh[r * 68 + d] = make_float4(h0, h1, h2, h3);
        *(float4*)&Ql[r * 68 + d] = make_float4(l0, l1, l2, l3);
    }

    float o[8][4] = {};
    float m0 = -1e30f, m1 = -1e30f, l0s = 0.0f, l1s = 0.0f;
    const int nkt = 2 * qt + 2;

    for (int kt = 0; kt < nkt; kt++) {
        __syncthreads();                         // protect prior-tile K/V reads
        // ---- load K (split) and V (split + transpose) ----
        for (int idx = tid; idx < 1024; idx += 256) {
            int r = idx >> 4, d = (idx & 15) << 2;
            float4 kv = *(const float4*)&Kg[(size_t)(kt * 64 + r) * DH + d];
            float h0, l0, h1, l1, h2, l2, h3, l3;
            tf32_split(kv.x, h0, l0); tf32_split(kv.y, h1, l1);
            tf32_split(kv.z, h2, l2); tf32_split(kv.w, h3, l3);
            *(float4*)&Kh[r * 68 + d] = make_float4(h0, h1, h2, h3);
            *(float4*)&Kl[r * 68 + d] = make_float4(l0, l1, l2, l3);
            float4 vv = *(const float4*)&Vg[(size_t)(kt * 64 + r) * DH + d];
            tf32_split(vv.x, h0, l0); tf32_split(vv.y, h1, l1);
            tf32_split(vv.z, h2, l2); tf32_split(vv.w, h3, l3);
            Vh[(d + 0) * 68 + r] = h0; Vl[(d + 0) * 68 + r] = l0;
            Vh[(d + 1) * 68 + r] = h1; Vl[(d + 1) * 68 + r] = l1;
            Vh[(d + 2) * 68 + r] = h2; Vl[(d + 2) * 68 + r] = l2;
            Vh[(d + 3) * 68 + r] = h3; Vl[(d + 3) * 68 + r] = l3;
        }
        __syncthreads();

        // ---- S = Q K^T, 3-product split ----
        float c[8][4] = {};
#pragma unroll
        for (int ks = 0; ks < 8; ks++) {
            const int kc = ks * 8 + tig;
            uint32_t ah[4], al[4];
            ah[0] = __float_as_uint(Qh[(wr + gid) * 68 + kc]);
            ah[1] = __float_as_uint(Qh[(wr + gid + 8) * 68 + kc]);
            ah[2] = __float_as_uint(Qh[(wr + gid) * 68 + kc + 4]);
            ah[3] = __float_as_uint(Qh[(wr + gid + 8) * 68 + kc + 4]);
            al[0] = __float_as_uint(Ql[(wr + gid) * 68 + kc]);
            al[1] = __float_as_uint(Ql[(wr + gid + 8) * 68 + kc]);
            al[2] = __float_as_uint(Ql[(wr + gid) * 68 + kc + 4]);
            al[3] = __float_as_uint(Ql[(wr + gid + 8) * 68 + kc + 4]);
#pragma unroll
            for (int nt = 0; nt < 8; nt++) {
                int nr = nt * 8 + gid;
                uint32_t bh0 = __float_as_uint(Kh[nr * 68 + kc]);
                uint32_t bh1 = __float_as_uint(Kh[nr * 68 + kc + 4]);
                uint32_t bl0 = __float_as_uint(Kl[nr * 68 + kc]);
                uint32_t bl1 = __float_as_uint(Kl[nr * 68 + kc + 4]);
                mma_tf32(c[nt], ah[0], ah[1], ah[2], ah[3], bh0, bh1);
                mma_tf32(c[nt], ah[0], ah[1], ah[2], ah[3], bl0, bl1);
                mma_tf32(c[nt], al[0], al[1], al[2], al[3], bh0, bh1);
            }
        }

        // ---- causal mask (only diagonal-band tiles) ----
        const int row0 = q0 + wr + gid, row1 = row0 + 8;
        if (kt >= 2 * qt) {
#pragma unroll
            for (int nt = 0; nt < 8; nt++) {
                int col = kt * 64 + nt * 8 + 2 * tig;
                if (col > row0)     c[nt][0] = -1e30f;
                if (col + 1 > row0) c[nt][1] = -1e30f;
                if (col > row1)     c[nt][2] = -1e30f;
                if (col + 1 > row1) c[nt][3] = -1e30f;
            }
        }

        // ---- online softmax (rows in registers; quad shuffle reduce) ----
        float mx0 = -1e30f, mx1 = -1e30f;
#pragma unroll
        for (int nt = 0; nt < 8; nt++) {
            mx0 = fmaxf(mx0, fmaxf(c[nt][0], c[nt][1]));
            mx1 = fmaxf(mx1, fmaxf(c[nt][2], c[nt][3]));
        }
        mx0 = fmaxf(mx0, __shfl_xor_sync(0xffffffffu, mx0, 1));
        mx0 = fmaxf(mx0, __shfl_xor_sync(0xffffffffu, mx0, 2));
        mx1 = fmaxf(mx1, __shfl_xor_sync(0xffffffffu, mx1, 1));
        mx1 = fmaxf(mx1, __shfl_xor_sync(0xffffffffu, mx1, 2));
        float mn0 = fmaxf(m0, mx0), mn1 = fmaxf(m1, mx1);
        float a0 = __expf(m0 - mn0), a1 = __expf(m1 - mn1);
        m0 = mn0; m1 = mn1;

        float s0 = 0.0f, s1 = 0.0f;
#pragma unroll
        for (int nt = 0; nt < 8; nt++) {
            float p00 = tf32_round(__expf(c[nt][0] - mn0));
            float p01 = tf32_round(__expf(c[nt][1] - mn0));
            float p10 = tf32_round(__expf(c[nt][2] - mn1));
            float p11 = tf32_round(__expf(c[nt][3] - mn1));
            s0 += p00 + p01;
            s1 += p10 + p11;
            *(float2*)&Ps[(wr + gid) * 68 + nt * 8 + 2 * tig]     = make_float2(p00, p01);
            *(float2*)&Ps[(wr + gid + 8) * 68 + nt * 8 + 2 * tig] = make_float2(p10, p11);
        }
        s0 += __shfl_xor_sync(0xffffffffu, s0, 1);
        s0 += __shfl_xor_sync(0xffffffffu, s0, 2);
        s1 += __shfl_xor_sync(0xffffffffu, s1, 1);
        s1 += __shfl_xor_sync(0xffffffffu, s1, 2);
        l0s = l0s * a0 + s0;
        l1s = l1s * a1 + s1;

#pragma unroll
        for (int nt = 0; nt < 8; nt++) {
            o[nt][0] *= a0; o[nt][1] *= a0;
            o[nt][2] *= a1; o[nt][3] *= a1;
        }
        __syncwarp();   // P stores visible to whole warp

        // ---- O += P V (V split, 2 products) ----
#pragma unroll
        for (int ks = 0; ks < 8; ks++) {
            const int kc = ks * 8 + tig;
            uint32_t pa[4];
            pa[0] = __float_as_uint(Ps[(wr + gid) * 68 + kc]);
            pa[1] = __float_as_uint(Ps[(wr + gid + 8) * 68 + kc]);
            pa[2] = __float_as_uint(Ps[(wr + gid) * 68 + kc + 4]);
            pa[3] = __float_as_uint(Ps[(wr + gid + 8) * 68 + kc + 4]);
#pragma unroll
            for (int nt = 0; nt < 8; nt++) {
                int nr = nt * 8 + gid;
                uint32_t bh0 = __float_as_uint(Vh[nr * 68 + kc]);
                uint32_t bh1 = __float_as_uint(Vh[nr * 68 + kc + 4]);
                uint32_t bl0 = __float_as_uint(Vl[nr * 68 + kc]);
                uint32_t bl1 = __float_as_uint(Vl[nr * 68 + kc + 4]);
                mma_tf32(o[nt], pa[0], pa[1], pa[2], pa[3], bh0, bh1);
                mma_tf32(o[nt], pa[0], pa[1], pa[2], pa[3], bl0, bl1);
            }
        }
    }

    // ---- epilogue: normalize, write [b,s,h*64+d] ----
    const int bidx = bh / HH, h = bh % HH;
    const float i0 = 1.0f / l0s, i1 = 1.0f / l1s;
    const int r0 = q0 + wr + gid;
#pragma unroll
    for (int nt = 0; nt < 8; nt++) {
        int d = nt * 8 + 2 * tig;
        *(float2*)&g_attn[((size_t)bidx * SS + r0) * DM + h * DH + d] =
            make_float2(o[nt][0] * i0, o[nt][1] * i0);
        *(float2*)&g_attn[((size_t)bidx * SS + r0 + 8) * DM + h * DH + d] =
            make_float2(o[nt][2] * i1, o[nt][3] * i1);
    }
}

// ---------------------------------------------------------------------------
// Kernel 3: output projection via mma.sync tf32 (2-way split). (unchanged)
// ---------------------------------------------------------------------------
#define PROJ_SMEM_FLOATS (4 * 128 * 36)
#define PROJ_SMEM_BYTES  (PROJ_SMEM_FLOATS * sizeof(float))   // 73728

__global__ __launch_bounds__(256) void proj_mma_kernel(
    const float* __restrict__ Wo, const float* __restrict__ bo,
    float* __restrict__ out)
{
    extern __shared__ float pshm[];
    float (*As_hi)[36] = (float (*)[36])(pshm);
    float (*As_lo)[36] = (float (*)[36])(pshm + 128 * 36);
    float (*Bs_hi)[36] = (float (*)[36])(pshm + 2 * 128 * 36);
    float (*Bs_lo)[36] = (float (*)[36])(pshm + 3 * 128 * 36);

    const int n0 = blockIdx.x * 128;
    const int m0 = blockIdx.y * 128;
    const int tid  = threadIdx.x;
    const int lane = tid & 31, warp = tid >> 5;
    const int wm = (warp >> 2) * 64;
    const int wn = (warp & 3) * 32;
    const int gid = lane >> 2, tig = lane & 3;

    float c[4][4][4] = {};

    for (int k0 = 0; k0 < DM; k0 += 32) {
        __syncthreads();
        for (int idx = tid; idx < 1024; idx += 256) {
            int r = idx >> 3, q = (idx & 7) << 2;
            float4 va = *(const float4*)&g_attn[(size_t)(m0 + r) * DM + k0 + q];
            float4 vb = *(const float4*)&Wo[(size_t)(n0 + r) * DM + k0 + q];
            float h0, l0, h1, l1, h2, l2, h3, l3;
            tf32_split(va.x, h0, l0); tf32_split(va.y, h1, l1);
            tf32_split(va.z, h2, l2); tf32_split(va.w, h3, l3);
            *(float4*)&As_hi[r][q] = make_float4(h0, h1, h2, h3);
            *(float4*)&As_lo[r][q] = make_float4(l0, l1, l2, l3);
            tf32_split(vb.x, h0, l0); tf32_split(vb.y, h1, l1);
            tf32_split(vb.z, h2, l2); tf32_split(vb.w, h3, l3);
            *(float4*)&Bs_hi[r][q] = make_float4(h0, h1, h2, h3);
            *(float4*)&Bs_lo[r][q] = make_float4(l0, l1, l2, l3);
        }
        __syncthreads();

#pragma unroll
        for (int ks = 0; ks < 4; ks++) {
            const int kc = ks * 8 + tig;
            uint32_t ah[4][4], al[4][4];
#pragma unroll
            for (int mt = 0; mt < 4; mt++) {
                int mr = wm + mt * 16 + gid;
                ah[mt][0] = __float_as_uint(As_hi[mr][kc]);
                ah[mt][1] = __float_as_uint(As_hi[mr + 8][kc]);
                ah[mt][2] = __float_as_uint(As_hi[mr][kc + 4]);
                ah[mt][3] = __float_as_uint(As_hi[mr + 8][kc + 4]);
                al[mt][0] = __float_as_uint(As_lo[mr][kc]);
                al[mt][1] = __float_as_uint(As_lo[mr + 8][kc]);
                al[mt][2] = __float_as_uint(As_lo[mr][kc + 4]);
                al[mt][3] = __float_as_uint(As_lo[mr + 8][kc + 4]);
            }
            uint32_t bh[4][2], bl[4][2];
#pragma unroll
            for (int nt = 0; nt < 4; nt++) {
                int nr = wn + nt * 8 + gid;
                bh[nt][0] = __float_as_uint(Bs_hi[nr][kc]);
                bh[nt][1] = __float_as_uint(Bs_hi[nr][kc + 4]);
                bl[nt][0] = __float_as_uint(Bs_lo[nr][kc]);
                bl[nt][1] = __float_as_uint(Bs_lo[nr][kc + 4]);
            }
#pragma unroll
            for (int mt = 0; mt < 4; mt++)
#pragma unroll
                for (int nt = 0; nt < 4; nt++) {
                    mma_tf32(c[mt][nt], ah[mt][0], ah[mt][1], ah[mt][2], ah[mt][3],
                             bh[nt][0], bh[nt][1]);
                    mma_tf32(c[mt][nt], ah[mt][0], ah[mt][1], ah[mt][2], ah[mt][3],
                             bl[nt][0], bl[nt][1]);
                    mma_tf32(c[mt][nt], al[mt][0], al[mt][1], al[mt][2], al[mt][3],
                             bh[nt][0], bh[nt][1]);
                }
        }
    }

#pragma unroll
    for (int mt = 0; mt < 4; mt++) {
#pragma unroll
        for (int nt = 0; nt < 4; nt++) {
            int m  = m0 + wm + mt * 16 + gid;
            int n  = n0 + wn + nt * 8 + tig * 2;
            float2 v0, v1;
            v0.x = c[mt][nt][0] + bo[n];
            v0.y = c[mt][nt][1] + bo[n + 1];
            v1.x = c[mt][nt][2] + bo[n];
            v1.y = c[mt][nt][3] + bo[n + 1];
            *(float2*)&out[(size_t)m * DM + n]       = v0;
            *(float2*)&out[(size_t)(m + 8) * DM + n] = v1;
        }
    }
}

// ---------------------------------------------------------------------------
extern "C" void kernel_launch(void* const* d_in, const int* in_sizes, int n_in,
                              void* d_out, int out_size)
{
    const float* x  = (const float*)d_in[0];
    const float* Wq = (const float*)d_in[1];
    const float* bq = (const float*)d_in[2];
    const float* Wk = (const float*)d_in[3];
    const float* bk = (const float*)d_in[4];
    const float* Wv = (const float*)d_in[5];
    const float* bv = (const float*)d_in[6];
    const float* Wo = (const float*)d_in[7];
    const float* bo = (const float*)d_in[8];
    float* out = (float*)d_out;

    cudaFuncSetAttribute(attn_mma_kernel,
                         cudaFuncAttributeMaxDynamicSharedMemorySize,
                         (int)ATTN2_SMEM_BYTES);
    cudaFuncSetAttribute(proj_mma_kernel,
                         cudaFuncAttributeMaxDynamicSharedMemorySize,
                         (int)PROJ_SMEM_BYTES);

    qkv_kernel<<<dim3(BB * SS / 64, HH), 256>>>(x, Wq, bq, Wk, bk, Wv, bv);
    attn_mma_kernel<<<dim3(SS / 128, BB * HH), 256, ATTN2_SMEM_BYTES>>>();
    proj_mma_kernel<<<dim3(DM / 128, BB * SS / 128), 256, PROJ_SMEM_BYTES>>>(Wo, bo, out);
}

// round 6
// speedup vs baseline: 2.7319x; 1.5173x over previous
#include <cuda_runtime.h>
#include <cuda_fp16.h>
#include <cstdint>

#define BB 2
#define SS 2048
#define DM 1024
#define HH 16
#define DH 64

// Scratch (allocation-free rule: __device__ globals)
__device__ float g_q[(size_t)BB * HH * SS * DH];     // [b,h,s,d]
__device__ float g_k[(size_t)BB * HH * SS * DH];     // [b,h,s,d]
__device__ float g_v[(size_t)BB * HH * SS * DH];     // [b,h,s,d]
__device__ float g_attn[(size_t)BB * SS * DM];       // [b,s,h*64+d]

// ---------------------------------------------------------------------------
// fp16 helpers (mma.sync m16n8k16 — legacy HMMA, works on compute_103)
// ---------------------------------------------------------------------------
__device__ __forceinline__ void h_split(float x, float& hi, float& lo) {
    hi = __half2float(__float2half_rn(x));
    lo = x - hi;
}
__device__ __forceinline__ uint32_t f22h2(float a, float b) {
    __half2 h = __floats2half2_rn(a, b);
    return *(uint32_t*)&h;
}

__device__ __forceinline__ void mma_f16(float c[4],
                                        uint32_t a0, uint32_t a1,
                                        uint32_t a2, uint32_t a3,
                                        uint32_t b0, uint32_t b1) {
    asm volatile(
        "mma.sync.aligned.m16n8k16.row.col.f32.f16.f16.f32 "
        "{%0,%1,%2,%3}, {%4,%5,%6,%7}, {%8,%9}, {%0,%1,%2,%3};"
        : "+f"(c[0]), "+f"(c[1]), "+f"(c[2]), "+f"(c[3])
        : "r"(a0), "r"(a1), "r"(a2), "r"(a3), "r"(b0), "r"(b1));
}

#define U32(p) (*(const uint32_t*)&(p))

// ---------------------------------------------------------------------------
// Kernel 1: fused QKV projections via mma.sync fp16.
// CTA: 128 tokens x one head. 8 warps as 4(M)x2(N), warp tile 32x32.
// Stage x-slice hi/lo once; loop p over {Q,K,V} staging W.
// ---------------------------------------------------------------------------
#define QST 72   // smem stride in halves
#define QKV_SMEM_HALVES (2 * 128 * QST + 2 * 64 * QST)
#define QKV_SMEM_BYTES  (QKV_SMEM_HALVES * 2)     // 55296

__global__ __launch_bounds__(256) void qkv_mma_kernel(
    const float* __restrict__ x,
    const float* __restrict__ Wq, const float* __restrict__ bq,
    const float* __restrict__ Wk, const float* __restrict__ bk,
    const float* __restrict__ Wv, const float* __restrict__ bv)
{
    extern __shared__ __half qsm[];
    __half* Xh = qsm;
    __half* Xl = qsm + 128 * QST;
    __half* Wh = qsm + 2 * 128 * QST;
    __half* Wl = Wh + 64 * QST;

    const int h    = blockIdx.y;
    const int tok0 = blockIdx.x * 128;
    const int tid  = threadIdx.x;
    const int lane = tid & 31, warp = tid >> 5;
    const int gid  = lane >> 2, tig = lane & 3;
    const int wm   = (warp >> 1) * 32;
    const int wn   = (warp & 1) * 32;

    // stage x slice [128, 64] hi/lo
    for (int idx = tid; idx < 2048; idx += 256) {
        int r = idx >> 4, d = (idx & 15) << 2;
        float4 v = *(const float4*)&x[(size_t)(tok0 + r) * DM + h * DH + d];
        float h0, l0, h1, l1, h2, l2, h3, l3;
        h_split(v.x, h0, l0); h_split(v.y, h1, l1);
        h_split(v.z, h2, l2); h_split(v.w, h3, l3);
        *(uint2*)&Xh[r * QST + d] = make_uint2(f22h2(h0, h1), f22h2(h2, h3));
        *(uint2*)&Xl[r * QST + d] = make_uint2(f22h2(l0, l1), f22h2(l2, l3));
    }

    const float* Wp[3] = {Wq, Wk, Wv};
    const float* bp[3] = {bq, bk, bv};
    float*       op[3] = {g_q, g_k, g_v};

    for (int p = 0; p < 3; p++) {
        __syncthreads();
        for (int idx = tid; idx < 1024; idx += 256) {
            int r = idx >> 4, d = (idx & 15) << 2;
            float4 v = *(const float4*)&Wp[p][(size_t)(h * DH + r) * DH + d];
            float h0, l0, h1, l1, h2, l2, h3, l3;
            h_split(v.x, h0, l0); h_split(v.y, h1, l1);
            h_split(v.z, h2, l2); h_split(v.w, h3, l3);
            *(uint2*)&Wh[r * QST + d] = make_uint2(f22h2(h0, h1), f22h2(h2, h3));
            *(uint2*)&Wl[r * QST + d] = make_uint2(f22h2(l0, l1), f22h2(l2, l3));
        }
        __syncthreads();

        float c[2][4][4] = {};
#pragma unroll
        for (int ks = 0; ks < 4; ks++) {
            const int kc = ks * 16 + 2 * tig;
            uint32_t ah[2][4], al[2][4];
#pragma unroll
            for (int mt = 0; mt < 2; mt++) {
                int mr = wm + mt * 16 + gid;
                ah[mt][0] = U32(Xh[mr * QST + kc]);
                ah[mt][1] = U32(Xh[(mr + 8) * QST + kc]);
                ah[mt][2] = U32(Xh[mr * QST + kc + 8]);
                ah[mt][3] = U32(Xh[(mr + 8) * QST + kc + 8]);
                al[mt][0] = U32(Xl[mr * QST + kc]);
                al[mt][1] = U32(Xl[(mr + 8) * QST + kc]);
                al[mt][2] = U32(Xl[mr * QST + kc + 8]);
                al[mt][3] = U32(Xl[(mr + 8) * QST + kc + 8]);
            }
#pragma unroll
            for (int nt = 0; nt < 4; nt++) {
                int nr = wn + nt * 8 + gid;
                uint32_t bh0 = U32(Wh[nr * QST + kc]);
                uint32_t bh1 = U32(Wh[nr * QST + kc + 8]);
                uint32_t bl0 = U32(Wl[nr * QST + kc]);
                uint32_t bl1 = U32(Wl[nr * QST + kc + 8]);
#pragma unroll
                for (int mt = 0; mt < 2; mt++) {
                    mma_f16(c[mt][nt], ah[mt][0], ah[mt][1], ah[mt][2], ah[mt][3], bh0, bh1);
                    mma_f16(c[mt][nt], ah[mt][0], ah[mt][1], ah[mt][2], ah[mt][3], bl0, bl1);
                    mma_f16(c[mt][nt], al[mt][0], al[mt][1], al[mt][2], al[mt][3], bh0, bh1);
                }
            }
        }

#pragma unroll
        for (int mt = 0; mt < 2; mt++) {
#pragma unroll
            for (int nt = 0; nt < 4; nt++) {
                int gtok = tok0 + wm + mt * 16 + gid;
                int o    = wn + nt * 8 + 2 * tig;
                float b0 = bp[p][h * DH + o], b1 = bp[p][h * DH + o + 1];
                int bidx = gtok >> 11;
                int s    = gtok & (SS - 1);
                size_t base = (((size_t)bidx * HH + h) * SS + s) * DH + o;
                *(float2*)&op[p][base] =
                    make_float2(c[mt][nt][0] + b0, c[mt][nt][1] + b1);
                size_t base2 = base + 8 * DH;
                *(float2*)&op[p][base2] =
                    make_float2(c[mt][nt][2] + b0, c[mt][nt][3] + b1);
            }
        }
    }
}

// ---------------------------------------------------------------------------
// Kernel 2: causal flash attention via mma.sync fp16.
// CTA: 128 q-rows x one (b,h). 8 warps, warp = 16 q-rows.
// QK 3-product fp16 split; P single fp16; PV with V 2-product split.
// Stride 72 halves -> conflict-free fragment LDS.
// ---------------------------------------------------------------------------
#define AQH 0
#define AQL (128 * QST)
#define AKH (2 * 128 * QST)
#define AKL (AKH + 64 * QST)
#define AVH (AKL + 64 * QST)
#define AVL (AVH + 64 * QST)
#define APS (AVL + 64 * QST)
#define ATTN_SMEM_HALVES (APS + 128 * QST)
#define ATTN_SMEM_BYTES  (ATTN_SMEM_HALVES * 2)    // 92160

__global__ __launch_bounds__(256) void attn_mma_kernel()
{
    extern __shared__ __half asm_[];
    __half* Qh = asm_ + AQH;  __half* Ql = asm_ + AQL;
    __half* Kh = asm_ + AKH;  __half* Kl = asm_ + AKL;
    __half* Vh = asm_ + AVH;  __half* Vl = asm_ + AVL;
    __half* Ps = asm_ + APS;

    const int qt = gridDim.x - 1 - blockIdx.x;   // heavy tiles first
    const int bh = blockIdx.y;
    const int q0 = qt * 128;
    const float* Qg = g_q + (size_t)bh * SS * DH;
    const float* Kg = g_k + (size_t)bh * SS * DH;
    const float* Vg = g_v + (size_t)bh * SS * DH;

    const int tid  = threadIdx.x;
    const int warp = tid >> 5, lane = tid & 31;
    const int gid  = lane >> 2, tig = lane & 3;
    const int wr   = warp * 16;

    // load Q once, scale + split
    for (int idx = tid; idx < 2048; idx += 256) {
        int r = idx >> 4, d = (idx & 15) << 2;
        float4 v = *(const float4*)&Qg[(size_t)(q0 + r) * DH + d];
        float h0, l0, h1, l1, h2, l2, h3, l3;
        h_split(v.x * 0.125f, h0, l0); h_split(v.y * 0.125f, h1, l1);
        h_split(v.z * 0.125f, h2, l2); h_split(v.w * 0.125f, h3, l3);
        *(uint2*)&Qh[r * QST + d] = make_uint2(f22h2(h0, h1), f22h2(h2, h3));
        *(uint2*)&Ql[r * QST + d] = make_uint2(f22h2(l0, l1), f22h2(l2, l3));
    }

    float o[8][4] = {};
    float m0 = -1e30f, m1 = -1e30f, l0s = 0.0f, l1s = 0.0f;
    const int nkt = 2 * qt + 2;

    for (int kt = 0; kt < nkt; kt++) {
        __syncthreads();
        // stage K (split) and V (split + transpose)
        for (int idx = tid; idx < 1024; idx += 256) {
            int r = idx >> 4, d = (idx & 15) << 2;
            float4 kv = *(const float4*)&Kg[(size_t)(kt * 64 + r) * DH + d];
            float h0, l0, h1, l1, h2, l2, h3, l3;
            h_split(kv.x, h0, l0); h_split(kv.y, h1, l1);
            h_split(kv.z, h2, l2); h_split(kv.w, h3, l3);
            *(uint2*)&Kh[r * QST + d] = make_uint2(f22h2(h0, h1), f22h2(h2, h3));
            *(uint2*)&Kl[r * QST + d] = make_uint2(f22h2(l0, l1), f22h2(l2, l3));
            float4 vv = *(const float4*)&Vg[(size_t)(kt * 64 + r) * DH + d];
            h_split(vv.x, h0, l0); h_split(vv.y, h1, l1);
            h_split(vv.z, h2, l2); h_split(vv.w, h3, l3);
            Vh[(d + 0) * QST + r] = __float2half_rn(h0);
            Vh[(d + 1) * QST + r] = __float2half_rn(h1);
            Vh[(d + 2) * QST + r] = __float2half_rn(h2);
            Vh[(d + 3) * QST + r] = __float2half_rn(h3);
            Vl[(d + 0) * QST + r] = __float2half_rn(l0);
            Vl[(d + 1) * QST + r] = __float2half_rn(l1);
            Vl[(d + 2) * QST + r] = __float2half_rn(l2);
            Vl[(d + 3) * QST + r] = __float2half_rn(l3);
        }
        __syncthreads();

        // S = Q K^T, 3-product split
        float c[8][4] = {};
#pragma unroll
        for (int ks = 0; ks < 4; ks++) {
            const int kc = ks * 16 + 2 * tig;
            uint32_t ah[4], al[4];
            ah[0] = U32(Qh[(wr + gid) * QST + kc]);
            ah[1] = U32(Qh[(wr + gid + 8) * QST + kc]);
            ah[2] = U32(Qh[(wr + gid) * QST + kc + 8]);
            ah[3] = U32(Qh[(wr + gid + 8) * QST + kc + 8]);
            al[0] = U32(Ql[(wr + gid) * QST + kc]);
            al[1] = U32(Ql[(wr + gid + 8) * QST + kc]);
            al[2] = U32(Ql[(wr + gid) * QST + kc + 8]);
            al[3] = U32(Ql[(wr + gid + 8) * QST + kc + 8]);
#pragma unroll
            for (int nt = 0; nt < 8; nt++) {
                int nr = nt * 8 + gid;
                uint32_t bh0 = U32(Kh[nr * QST + kc]);
                uint32_t bh1 = U32(Kh[nr * QST + kc + 8]);
                uint32_t bl0 = U32(Kl[nr * QST + kc]);
                uint32_t bl1 = U32(Kl[nr * QST + kc + 8]);
                mma_f16(c[nt], ah[0], ah[1], ah[2], ah[3], bh0, bh1);
                mma_f16(c[nt], ah[0], ah[1], ah[2], ah[3], bl0, bl1);
                mma_f16(c[nt], al[0], al[1], al[2], al[3], bh0, bh1);
            }
        }

        // causal mask (diagonal band only)
        const int row0 = q0 + wr + gid, row1 = row0 + 8;
        if (kt >= 2 * qt) {
#pragma unroll
            for (int nt = 0; nt < 8; nt++) {
                int col = kt * 64 + nt * 8 + 2 * tig;
                if (col > row0)     c[nt][0] = -1e30f;
                if (col + 1 > row0) c[nt][1] = -1e30f;
                if (col > row1)     c[nt][2] = -1e30f;
                if (col + 1 > row1) c[nt][3] = -1e30f;
            }
        }

        // online softmax (registers, quad shuffle)
        float mx0 = -1e30f, mx1 = -1e30f;
#pragma unroll
        for (int nt = 0; nt < 8; nt++) {
            mx0 = fmaxf(mx0, fmaxf(c[nt][0], c[nt][1]));
            mx1 = fmaxf(mx1, fmaxf(c[nt][2], c[nt][3]));
        }
        mx0 = fmaxf(mx0, __shfl_xor_sync(0xffffffffu, mx0, 1));
        mx0 = fmaxf(mx0, __shfl_xor_sync(0xffffffffu, mx0, 2));
        mx1 = fmaxf(mx1, __shfl_xor_sync(0xffffffffu, mx1, 1));
        mx1 = fmaxf(mx1, __shfl_xor_sync(0xffffffffu, mx1, 2));
        float mn0 = fmaxf(m0, mx0), mn1 = fmaxf(m1, mx1);
        float a0 = __expf(m0 - mn0), a1 = __expf(m1 - mn1);
        m0 = mn0; m1 = mn1;

        float s0 = 0.0f, s1 = 0.0f;
#pragma unroll
        for (int nt = 0; nt < 8; nt++) {
            __half2 p0 = __floats2half2_rn(__expf(c[nt][0] - mn0),
                                           __expf(c[nt][1] - mn0));
            __half2 p1 = __floats2half2_rn(__expf(c[nt][2] - mn1),
                                           __expf(c[nt][3] - mn1));
            float2 pf0 = __half22float2(p0), pf1 = __half22float2(p1);
            s0 += pf0.x + pf0.y;
            s1 += pf1.x + pf1.y;
            *(uint32_t*)&Ps[(wr + gid) * QST + nt * 8 + 2 * tig]     = *(uint32_t*)&p0;
            *(uint32_t*)&Ps[(wr + gid + 8) * QST + nt * 8 + 2 * tig] = *(uint32_t*)&p1;
        }
        s0 += __shfl_xor_sync(0xffffffffu, s0, 1);
        s0 += __shfl_xor_sync(0xffffffffu, s0, 2);
        s1 += __shfl_xor_sync(0xffffffffu, s1, 1);
        s1 += __shfl_xor_sync(0xffffffffu, s1, 2);
        l0s = l0s * a0 + s0;
        l1s = l1s * a1 + s1;

#pragma unroll
        for (int nt = 0; nt < 8; nt++) {
            o[nt][0] *= a0; o[nt][1] *= a0;
            o[nt][2] *= a1; o[nt][3] *= a1;
        }
        __syncwarp();   // P stores visible within warp

        // O += P V
#pragma unroll
        for (int ks = 0; ks < 4; ks++) {
            const int kc = ks * 16 + 2 * tig;
            uint32_t pa[4];
            pa[0] = U32(Ps[(wr + gid) * QST + kc]);
            pa[1] = U32(Ps[(wr + gid + 8) * QST + kc]);
            pa[2] = U32(Ps[(wr + gid) * QST + kc + 8]);
            pa[3] = U32(Ps[(wr + gid + 8) * QST + kc + 8]);
#pragma unroll
            for (int nt = 0; nt < 8; nt++) {
                int nr = nt * 8 + gid;
                uint32_t bh0 = U32(Vh[nr * QST + kc]);
                uint32_t bh1 = U32(Vh[nr * QST + kc + 8]);
                uint32_t bl0 = U32(Vl[nr * QST + kc]);
                uint32_t bl1 = U32(Vl[nr * QST + kc + 8]);
                mma_f16(o[nt], pa[0], pa[1], pa[2], pa[3], bh0, bh1);
                mma_f16(o[nt], pa[0], pa[1], pa[2], pa[3], bl0, bl1);
            }
        }
    }

    // epilogue: normalize, write [b,s,h*64+d]
    const int bidx = bh / HH, h = bh % HH;
    const float i0 = 1.0f / l0s, i1 = 1.0f / l1s;
    const int r0 = q0 + wr + gid;
#pragma unroll
    for (int nt = 0; nt < 8; nt++) {
        int d = nt * 8 + 2 * tig;
        *(float2*)&g_attn[((size_t)bidx * SS + r0) * DM + h * DH + d] =
            make_float2(o[nt][0] * i0, o[nt][1] * i0);
        *(float2*)&g_attn[((size_t)bidx * SS + r0 + 8) * DM + h * DH + d] =
            make_float2(o[nt][2] * i1, o[nt][3] * i1);
    }
}

// ---------------------------------------------------------------------------
// Kernel 3: output projection via mma.sync fp16 (3-product split).
// C[4096,1024] = A @ Wo^T + bo. CTA 128x128, warps 2(M)x4(N), K-chunk 64.
// ---------------------------------------------------------------------------
#define PROJ_SMEM_HALVES (4 * 128 * QST)
#define PROJ_SMEM_BYTES  (PROJ_SMEM_HALVES * 2)   // 73728

__global__ __launch_bounds__(256) void proj_mma_kernel(
    const float* __restrict__ Wo, const float* __restrict__ bo,
    float* __restrict__ out)
{
    extern __shared__ __half psm[];
    __half* Ah = psm;
    __half* Al = psm + 128 * QST;
    __half* Bh = psm + 2 * 128 * QST;
    __half* Bl = psm + 3 * 128 * QST;

    const int n0 = blockIdx.x * 128;
    const int m0 = blockIdx.y * 128;
    const int tid  = threadIdx.x;
    const int lane = tid & 31, warp = tid >> 5;
    const int wm = (warp >> 2) * 64;
    const int wn = (warp & 3) * 32;
    const int gid = lane >> 2, tig = lane & 3;

    float c[4][4][4] = {};

    for (int k0 = 0; k0 < DM; k0 += 64) {
        __syncthreads();
        for (int idx = tid; idx < 2048; idx += 256) {
            int r = idx >> 4, q = (idx & 15) << 2;
            float4 va = *(const float4*)&g_attn[(size_t)(m0 + r) * DM + k0 + q];
            float4 vb = *(const float4*)&Wo[(size_t)(n0 + r) * DM + k0 + q];
            float h0, l0, h1, l1, h2, l2, h3, l3;
            h_split(va.x, h0, l0); h_split(va.y, h1, l1);
            h_split(va.z, h2, l2); h_split(va.w, h3, l3);
            *(uint2*)&Ah[r * QST + q] = make_uint2(f22h2(h0, h1), f22h2(h2, h3));
            *(uint2*)&Al[r * QST + q] = make_uint2(f22h2(l0, l1), f22h2(l2, l3));
            h_split(vb.x, h0, l0); h_split(vb.y, h1, l1);
            h_split(vb.z, h2, l2); h_split(vb.w, h3, l3);
            *(uint2*)&Bh[r * QST + q] = make_uint2(f22h2(h0, h1), f22h2(h2, h3));
            *(uint2*)&Bl[r * QST + q] = make_uint2(f22h2(l0, l1), f22h2(l2, l3));
        }
        __syncthreads();

#pragma unroll
        for (int ks = 0; ks < 4; ks++) {
            const int kc = ks * 16 + 2 * tig;
            uint32_t ah[4][4], al[4][4];
#pragma unroll
            for (int mt = 0; mt < 4; mt++) {
                int mr = wm + mt * 16 + gid;
                ah[mt][0] = U32(Ah[mr * QST + kc]);
                ah[mt][1] = U32(Ah[(mr + 8) * QST + kc]);
                ah[mt][2] = U32(Ah[mr * QST + kc + 8]);
                ah[mt][3] = U32(Ah[(mr + 8) * QST + kc + 8]);
                al[mt][0] = U32(Al[mr * QST + kc]);
                al[mt][1] = U32(Al[(mr + 8) * QST + kc]);
                al[mt][2] = U32(Al[mr * QST + kc + 8]);
                al[mt][3] = U32(Al[(mr + 8) * QST + kc + 8]);
            }
#pragma unroll
            for (int nt = 0; nt < 4; nt++) {
                int nr = wn + nt * 8 + gid;
                uint32_t bh0 = U32(Bh[nr * QST + kc]);
                uint32_t bh1 = U32(Bh[nr * QST + kc + 8]);
                uint32_t bl0 = U32(Bl[nr * QST + kc]);
                uint32_t bl1 = U32(Bl[nr * QST + kc + 8]);
#pragma unroll
                for (int mt = 0; mt < 4; mt++) {
                    mma_f16(c[mt][nt], ah[mt][0], ah[mt][1], ah[mt][2], ah[mt][3], bh0, bh1);
                    mma_f16(c[mt][nt], ah[mt][0], ah[mt][1], ah[mt][2], ah[mt][3], bl0, bl1);
                    mma_f16(c[mt][nt], al[mt][0], al[mt][1], al[mt][2], al[mt][3], bh0, bh1);
                }
            }
        }
    }

#pragma unroll
    for (int mt = 0; mt < 4; mt++) {
#pragma unroll
        for (int nt = 0; nt < 4; nt++) {
            int m  = m0 + wm + mt * 16 + gid;
            int n  = n0 + wn + nt * 8 + tig * 2;
            float2 v0, v1;
            v0.x = c[mt][nt][0] + bo[n];
            v0.y = c[mt][nt][1] + bo[n + 1];
            v1.x = c[mt][nt][2] + bo[n];
            v1.y = c[mt][nt][3] + bo[n + 1];
            *(float2*)&out[(size_t)m * DM + n]       = v0;
            *(float2*)&out[(size_t)(m + 8) * DM + n] = v1;
        }
    }
}

// ---------------------------------------------------------------------------
extern "C" void kernel_launch(void* const* d_in, const int* in_sizes, int n_in,
                              void* d_out, int out_size)
{
    const float* x  = (const float*)d_in[0];
    const float* Wq = (const float*)d_in[1];
    const float* bq = (const float*)d_in[2];
    const float* Wk = (const float*)d_in[3];
    const float* bk = (const float*)d_in[4];
    const float* Wv = (const float*)d_in[5];
    const float* bv = (const float*)d_in[6];
    const float* Wo = (const float*)d_in[7];
    const float* bo = (const float*)d_in[8];
    float* out = (float*)d_out;

    cudaFuncSetAttribute(qkv_mma_kernel,
                         cudaFuncAttributeMaxDynamicSharedMemorySize,
                         (int)QKV_SMEM_BYTES);
    cudaFuncSetAttribute(attn_mma_kernel,
                         cudaFuncAttributeMaxDynamicSharedMemorySize,
                         (int)ATTN_SMEM_BYTES);
    cudaFuncSetAttribute(proj_mma_kernel,
                         cudaFuncAttributeMaxDynamicSharedMemorySize,
                         (int)PROJ_SMEM_BYTES);

    qkv_mma_kernel<<<dim3(BB * SS / 128, HH), 256, QKV_SMEM_BYTES>>>(
        x, Wq, bq, Wk, bk, Wv, bv);
    attn_mma_kernel<<<dim3(SS / 128, BB * HH), 256, ATTN_SMEM_BYTES>>>();
    proj_mma_kernel<<<dim3(DM / 128, BB * SS / 128), 256, PROJ_SMEM_BYTES>>>(Wo, bo, out);
}

// round 7
// speedup vs baseline: 3.1093x; 1.1381x over previous
#include <cuda_runtime.h>
#include <cuda_fp16.h>
#include <cstdint>

#define BB 2
#define SS 2048
#define DM 1024
#define HH 16
#define DH 64

// Scratch (allocation-free rule: __device__ globals)
__device__ float g_q[(size_t)BB * HH * SS * DH];     // [b,h,s,d]
__device__ float g_k[(size_t)BB * HH * SS * DH];     // [b,h,s,d]
__device__ float g_v[(size_t)BB * HH * SS * DH];     // [b,h,s,d]
__device__ float g_attn[(size_t)BB * SS * DM];       // [b,s,h*64+d]

// ---------------------------------------------------------------------------
// fp16 helpers (mma.sync m16n8k16 — legacy HMMA, works on compute_103)
// ---------------------------------------------------------------------------
__device__ __forceinline__ void h_split(float x, float& hi, float& lo) {
    hi = __half2float(__float2half_rn(x));
    lo = x - hi;
}
__device__ __forceinline__ uint32_t f22h2(float a, float b) {
    __half2 h = __floats2half2_rn(a, b);
    return *(uint32_t*)&h;
}

__device__ __forceinline__ void mma_f16(float c[4],
                                        uint32_t a0, uint32_t a1,
                                        uint32_t a2, uint32_t a3,
                                        uint32_t b0, uint32_t b1) {
    asm volatile(
        "mma.sync.aligned.m16n8k16.row.col.f32.f16.f16.f32 "
        "{%0,%1,%2,%3}, {%4,%5,%6,%7}, {%8,%9}, {%0,%1,%2,%3};"
        : "+f"(c[0]), "+f"(c[1]), "+f"(c[2]), "+f"(c[3])
        : "r"(a0), "r"(a1), "r"(a2), "r"(a3), "r"(b0), "r"(b1));
}

#define U32(p) (*(const uint32_t*)&(p))

// ---------------------------------------------------------------------------
// Kernel 1: fused QKV projections via mma.sync fp16. (occupancy 2)
// ---------------------------------------------------------------------------
#define QST 72   // smem stride in halves
#define QKV_SMEM_HALVES (2 * 128 * QST + 2 * 64 * QST)
#define QKV_SMEM_BYTES  (QKV_SMEM_HALVES * 2)     // 55296

__global__ __launch_bounds__(256, 2) void qkv_mma_kernel(
    const float* __restrict__ x,
    const float* __restrict__ Wq, const float* __restrict__ bq,
    const float* __restrict__ Wk, const float* __restrict__ bk,
    const float* __restrict__ Wv, const float* __restrict__ bv)
{
    extern __shared__ __half qsm[];
    __half* Xh = qsm;
    __half* Xl = qsm + 128 * QST;
    __half* Wh = qsm + 2 * 128 * QST;
    __half* Wl = Wh + 64 * QST;

    const int h    = blockIdx.y;
    const int tok0 = blockIdx.x * 128;
    const int tid  = threadIdx.x;
    const int lane = tid & 31, warp = tid >> 5;
    const int gid  = lane >> 2, tig = lane & 3;
    const int wm   = (warp >> 1) * 32;
    const int wn   = (warp & 1) * 32;

    for (int idx = tid; idx < 2048; idx += 256) {
        int r = idx >> 4, d = (idx & 15) << 2;
        float4 v = *(const float4*)&x[(size_t)(tok0 + r) * DM + h * DH + d];
        float h0, l0, h1, l1, h2, l2, h3, l3;
        h_split(v.x, h0, l0); h_split(v.y, h1, l1);
        h_split(v.z, h2, l2); h_split(v.w, h3, l3);
        *(uint2*)&Xh[r * QST + d] = make_uint2(f22h2(h0, h1), f22h2(h2, h3));
        *(uint2*)&Xl[r * QST + d] = make_uint2(f22h2(l0, l1), f22h2(l2, l3));
    }

    const float* Wp[3] = {Wq, Wk, Wv};
    const float* bp[3] = {bq, bk, bv};
    float*       op[3] = {g_q, g_k, g_v};

    for (int p = 0; p < 3; p++) {
        __syncthreads();
        for (int idx = tid; idx < 1024; idx += 256) {
            int r = idx >> 4, d = (idx & 15) << 2;
            float4 v = *(const float4*)&Wp[p][(size_t)(h * DH + r) * DH + d];
            float h0, l0, h1, l1, h2, l2, h3, l3;
            h_split(v.x, h0, l0); h_split(v.y, h1, l1);
            h_split(v.z, h2, l2); h_split(v.w, h3, l3);
            *(uint2*)&Wh[r * QST + d] = make_uint2(f22h2(h0, h1), f22h2(h2, h3));
            *(uint2*)&Wl[r * QST + d] = make_uint2(f22h2(l0, l1), f22h2(l2, l3));
        }
        __syncthreads();

        float c[2][4][4] = {};
#pragma unroll
        for (int ks = 0; ks < 4; ks++) {
            const int kc = ks * 16 + 2 * tig;
            uint32_t ah[2][4], al[2][4];
#pragma unroll
            for (int mt = 0; mt < 2; mt++) {
                int mr = wm + mt * 16 + gid;
                ah[mt][0] = U32(Xh[mr * QST + kc]);
                ah[mt][1] = U32(Xh[(mr + 8) * QST + kc]);
                ah[mt][2] = U32(Xh[mr * QST + kc + 8]);
                ah[mt][3] = U32(Xh[(mr + 8) * QST + kc + 8]);
                al[mt][0] = U32(Xl[mr * QST + kc]);
                al[mt][1] = U32(Xl[(mr + 8) * QST + kc]);
                al[mt][2] = U32(Xl[mr * QST + kc + 8]);
                al[mt][3] = U32(Xl[(mr + 8) * QST + kc + 8]);
            }
#pragma unroll
            for (int nt = 0; nt < 4; nt++) {
                int nr = wn + nt * 8 + gid;
                uint32_t bh0 = U32(Wh[nr * QST + kc]);
                uint32_t bh1 = U32(Wh[nr * QST + kc + 8]);
                uint32_t bl0 = U32(Wl[nr * QST + kc]);
                uint32_t bl1 = U32(Wl[nr * QST + kc + 8]);
#pragma unroll
                for (int mt = 0; mt < 2; mt++) {
                    mma_f16(c[mt][nt], ah[mt][0], ah[mt][1], ah[mt][2], ah[mt][3], bh0, bh1);
                    mma_f16(c[mt][nt], ah[mt][0], ah[mt][1], ah[mt][2], ah[mt][3], bl0, bl1);
                    mma_f16(c[mt][nt], al[mt][0], al[mt][1], al[mt][2], al[mt][3], bh0, bh1);
                }
            }
        }

#pragma unroll
        for (int mt = 0; mt < 2; mt++) {
#pragma unroll
            for (int nt = 0; nt < 4; nt++) {
                int gtok = tok0 + wm + mt * 16 + gid;
                int o    = wn + nt * 8 + 2 * tig;
                float b0 = bp[p][h * DH + o], b1 = bp[p][h * DH + o + 1];
                int bidx = gtok >> 11;
                int s    = gtok & (SS - 1);
                size_t base = (((size_t)bidx * HH + h) * SS + s) * DH + o;
                *(float2*)&op[p][base] =
                    make_float2(c[mt][nt][0] + b0, c[mt][nt][1] + b1);
                size_t base2 = base + 8 * DH;
                *(float2*)&op[p][base2] =
                    make_float2(c[mt][nt][2] + b0, c[mt][nt][3] + b1);
            }
        }
    }
}

// ---------------------------------------------------------------------------
// Kernel 2: causal flash attention via mma.sync fp16. (occupancy 2)
// ---------------------------------------------------------------------------
#define AQH 0
#define AQL (128 * QST)
#define AKH (2 * 128 * QST)
#define AKL (AKH + 64 * QST)
#define AVH (AKL + 64 * QST)
#define AVL (AVH + 64 * QST)
#define APS (AVL + 64 * QST)
#define ATTN_SMEM_HALVES (APS + 128 * QST)
#define ATTN_SMEM_BYTES  (ATTN_SMEM_HALVES * 2)    // 92160

__global__ __launch_bounds__(256, 2) void attn_mma_kernel()
{
    extern __shared__ __half asm_[];
    __half* Qh = asm_ + AQH;  __half* Ql = asm_ + AQL;
    __half* Kh = asm_ + AKH;  __half* Kl = asm_ + AKL;
    __half* Vh = asm_ + AVH;  __half* Vl = asm_ + AVL;
    __half* Ps = asm_ + APS;

    const int qt = gridDim.x - 1 - blockIdx.x;   // heavy tiles first
    const int bh = blockIdx.y;
    const int q0 = qt * 128;
    const float* Qg = g_q + (size_t)bh * SS * DH;
    const float* Kg = g_k + (size_t)bh * SS * DH;
    const float* Vg = g_v + (size_t)bh * SS * DH;

    const int tid  = threadIdx.x;
    const int warp = tid >> 5, lane = tid & 31;
    const int gid  = lane >> 2, tig = lane & 3;
    const int wr   = warp * 16;

    // load Q once, scale + split
    for (int idx = tid; idx < 2048; idx += 256) {
        int r = idx >> 4, d = (idx & 15) << 2;
        float4 v = *(const float4*)&Qg[(size_t)(q0 + r) * DH + d];
        float h0, l0, h1, l1, h2, l2, h3, l3;
        h_split(v.x * 0.125f, h0, l0); h_split(v.y * 0.125f, h1, l1);
        h_split(v.z * 0.125f, h2, l2); h_split(v.w * 0.125f, h3, l3);
        *(uint2*)&Qh[r * QST + d] = make_uint2(f22h2(h0, h1), f22h2(h2, h3));
        *(uint2*)&Ql[r * QST + d] = make_uint2(f22h2(l0, l1), f22h2(l2, l3));
    }

    float o[8][4] = {};
    float m0 = -1e30f, m1 = -1e30f, l0s = 0.0f, l1s = 0.0f;
    const int nkt = 2 * qt + 2;

    for (int kt = 0; kt < nkt; kt++) {
        __syncthreads();
        // stage K (split) and V (split + transpose)
        for (int idx = tid; idx < 1024; idx += 256) {
            int r = idx >> 4, d = (idx & 15) << 2;
            float4 kv = *(const float4*)&Kg[(size_t)(kt * 64 + r) * DH + d];
            float h0, l0, h1, l1, h2, l2, h3, l3;
            h_split(kv.x, h0, l0); h_split(kv.y, h1, l1);
            h_split(kv.z, h2, l2); h_split(kv.w, h3, l3);
            *(uint2*)&Kh[r * QST + d] = make_uint2(f22h2(h0, h1), f22h2(h2, h3));
            *(uint2*)&Kl[r * QST + d] = make_uint2(f22h2(l0, l1), f22h2(l2, l3));
            float4 vv = *(const float4*)&Vg[(size_t)(kt * 64 + r) * DH + d];
            h_split(vv.x, h0, l0); h_split(vv.y, h1, l1);
            h_split(vv.z, h2, l2); h_split(vv.w, h3, l3);
            Vh[(d + 0) * QST + r] = __float2half_rn(h0);
            Vh[(d + 1) * QST + r] = __float2half_rn(h1);
            Vh[(d + 2) * QST + r] = __float2half_rn(h2);
            Vh[(d + 3) * QST + r] = __float2half_rn(h3);
            Vl[(d + 0) * QST + r] = __float2half_rn(l0);
            Vl[(d + 1) * QST + r] = __float2half_rn(l1);
            Vl[(d + 2) * QST + r] = __float2half_rn(l2);
            Vl[(d + 3) * QST + r] = __float2half_rn(l3);
        }
        __syncthreads();

        // S = Q K^T, 3-product split
        float c[8][4] = {};
#pragma unroll
        for (int ks = 0; ks < 4; ks++) {
            const int kc = ks * 16 + 2 * tig;
            uint32_t ah[4], al[4];
            ah[0] = U32(Qh[(wr + gid) * QST + kc]);
            ah[1] = U32(Qh[(wr + gid + 8) * QST + kc]);
            ah[2] = U32(Qh[(wr + gid) * QST + kc + 8]);
            ah[3] = U32(Qh[(wr + gid + 8) * QST + kc + 8]);
            al[0] = U32(Ql[(wr + gid) * QST + kc]);
            al[1] = U32(Ql[(wr + gid + 8) * QST + kc]);
            al[2] = U32(Ql[(wr + gid) * QST + kc + 8]);
            al[3] = U32(Ql[(wr + gid + 8) * QST + kc + 8]);
#pragma unroll
            for (int nt = 0; nt < 8; nt++) {
                int nr = nt * 8 + gid;
                uint32_t bh0 = U32(Kh[nr * QST + kc]);
                uint32_t bh1 = U32(Kh[nr * QST + kc + 8]);
                uint32_t bl0 = U32(Kl[nr * QST + kc]);
                uint32_t bl1 = U32(Kl[nr * QST + kc + 8]);
                mma_f16(c[nt], ah[0], ah[1], ah[2], ah[3], bh0, bh1);
                mma_f16(c[nt], ah[0], ah[1], ah[2], ah[3], bl0, bl1);
                mma_f16(c[nt], al[0], al[1], al[2], al[3], bh0, bh1);
            }
        }

        // causal mask (diagonal band only)
        const int row0 = q0 + wr + gid, row1 = row0 + 8;
        if (kt >= 2 * qt) {
#pragma unroll
            for (int nt = 0; nt < 8; nt++) {
                int col = kt * 64 + nt * 8 + 2 * tig;
                if (col > row0)     c[nt][0] = -1e30f;
                if (col + 1 > row0) c[nt][1] = -1e30f;
                if (col > row1)     c[nt][2] = -1e30f;
                if (col + 1 > row1) c[nt][3] = -1e30f;
            }
        }

        // online softmax (registers, quad shuffle)
        float mx0 = -1e30f, mx1 = -1e30f;
#pragma unroll
        for (int nt = 0; nt < 8; nt++) {
            mx0 = fmaxf(mx0, fmaxf(c[nt][0], c[nt][1]));
            mx1 = fmaxf(mx1, fmaxf(c[nt][2], c[nt][3]));
        }
        mx0 = fmaxf(mx0, __shfl_xor_sync(0xffffffffu, mx0, 1));
        mx0 = fmaxf(mx0, __shfl_xor_sync(0xffffffffu, mx0, 2));
        mx1 = fmaxf(mx1, __shfl_xor_sync(0xffffffffu, mx1, 1));
        mx1 = fmaxf(mx1, __shfl_xor_sync(0xffffffffu, mx1, 2));
        float mn0 = fmaxf(m0, mx0), mn1 = fmaxf(m1, mx1);
        float a0 = __expf(m0 - mn0), a1 = __expf(m1 - mn1);
        m0 = mn0; m1 = mn1;

        float s0 = 0.0f, s1 = 0.0f;
#pragma unroll
        for (int nt = 0; nt < 8; nt++) {
            __half2 p0 = __floats2half2_rn(__expf(c[nt][0] - mn0),
                                           __expf(c[nt][1] - mn0));
            __half2 p1 = __floats2half2_rn(__expf(c[nt][2] - mn1),
                                           __expf(c[nt][3] - mn1));
            float2 pf0 = __half22float2(p0), pf1 = __half22float2(p1);
            s0 += pf0.x + pf0.y;
            s1 += pf1.x + pf1.y;
            *(uint32_t*)&Ps[(wr + gid) * QST + nt * 8 + 2 * tig]     = *(uint32_t*)&p0;
            *(uint32_t*)&Ps[(wr + gid + 8) * QST + nt * 8 + 2 * tig] = *(uint32_t*)&p1;
        }
        s0 += __shfl_xor_sync(0xffffffffu, s0, 1);
        s0 += __shfl_xor_sync(0xffffffffu, s0, 2);
        s1 += __shfl_xor_sync(0xffffffffu, s1, 1);
        s1 += __shfl_xor_sync(0xffffffffu, s1, 2);
        l0s = l0s * a0 + s0;
        l1s = l1s * a1 + s1;

#pragma unroll
        for (int nt = 0; nt < 8; nt++) {
            o[nt][0] *= a0; o[nt][1] *= a0;
            o[nt][2] *= a1; o[nt][3] *= a1;
        }
        __syncwarp();   // P stores visible within warp

        // O += P V
#pragma unroll
        for (int ks = 0; ks < 4; ks++) {
            const int kc = ks * 16 + 2 * tig;
            uint32_t pa[4];
            pa[0] = U32(Ps[(wr + gid) * QST + kc]);
            pa[1] = U32(Ps[(wr + gid + 8) * QST + kc]);
            pa[2] = U32(Ps[(wr + gid) * QST + kc + 8]);
            pa[3] = U32(Ps[(wr + gid + 8) * QST + kc + 8]);
#pragma unroll
            for (int nt = 0; nt < 8; nt++) {
                int nr = nt * 8 + gid;
                uint32_t bh0 = U32(Vh[nr * QST + kc]);
                uint32_t bh1 = U32(Vh[nr * QST + kc + 8]);
                uint32_t bl0 = U32(Vl[nr * QST + kc]);
                uint32_t bl1 = U32(Vl[nr * QST + kc + 8]);
                mma_f16(o[nt], pa[0], pa[1], pa[2], pa[3], bh0, bh1);
                mma_f16(o[nt], pa[0], pa[1], pa[2], pa[3], bl0, bl1);
            }
        }
    }

    // epilogue: normalize, write [b,s,h*64+d]
    const int bidx = bh / HH, h = bh % HH;
    const float i0 = 1.0f / l0s, i1 = 1.0f / l1s;
    const int r0 = q0 + wr + gid;
#pragma unroll
    for (int nt = 0; nt < 8; nt++) {
        int d = nt * 8 + 2 * tig;
        *(float2*)&g_attn[((size_t)bidx * SS + r0) * DM + h * DH + d] =
            make_float2(o[nt][0] * i0, o[nt][1] * i0);
        *(float2*)&g_attn[((size_t)bidx * SS + r0 + 8) * DM + h * DH + d] =
            make_float2(o[nt][2] * i1, o[nt][3] * i1);
    }
}

// ---------------------------------------------------------------------------
// Kernel 3: output projection via mma.sync fp16 (3-product split). (occ 2)
// ---------------------------------------------------------------------------
#define PROJ_SMEM_HALVES (4 * 128 * QST)
#define PROJ_SMEM_BYTES  (PROJ_SMEM_HALVES * 2)   // 73728

__global__ __launch_bounds__(256, 2) void proj_mma_kernel(
    const float* __restrict__ Wo, const float* __restrict__ bo,
    float* __restrict__ out)
{
    extern __shared__ __half psm[];
    __half* Ah = psm;
    __half* Al = psm + 128 * QST;
    __half* Bh = psm + 2 * 128 * QST;
    __half* Bl = psm + 3 * 128 * QST;

    const int n0 = blockIdx.x * 128;
    const int m0 = blockIdx.y * 128;
    const int tid  = threadIdx.x;
    const int lane = tid & 31, warp = tid >> 5;
    const int wm = (warp >> 2) * 64;
    const int wn = (warp & 3) * 32;
    const int gid = lane >> 2, tig = lane & 3;

    float c[4][4][4] = {};

    for (int k0 = 0; k0 < DM; k0 += 64) {
        __syncthreads();
        for (int idx = tid; idx < 2048; idx += 256) {
            int r = idx >> 4, q = (idx & 15) << 2;
            float4 va = *(const float4*)&g_attn[(size_t)(m0 + r) * DM + k0 + q];
            float4 vb = *(const float4*)&Wo[(size_t)(n0 + r) * DM + k0 + q];
            float h0, l0, h1, l1, h2, l2, h3, l3;
            h_split(va.x, h0, l0); h_split(va.y, h1, l1);
            h_split(va.z, h2, l2); h_split(va.w, h3, l3);
            *(uint2*)&Ah[r * QST + q] = make_uint2(f22h2(h0, h1), f22h2(h2, h3));
            *(uint2*)&Al[r * QST + q] = make_uint2(f22h2(l0, l1), f22h2(l2, l3));
            h_split(vb.x, h0, l0); h_split(vb.y, h1, l1);
            h_split(vb.z, h2, l2); h_split(vb.w, h3, l3);
            *(uint2*)&Bh[r * QST + q] = make_uint2(f22h2(h0, h1), f22h2(h2, h3));
            *(uint2*)&Bl[r * QST + q] = make_uint2(f22h2(l0, l1), f22h2(l2, l3));
        }
        __syncthreads();

#pragma unroll
        for (int ks = 0; ks < 4; ks++) {
            const int kc = ks * 16 + 2 * tig;
            uint32_t ah[4][4], al[4][4];
#pragma unroll
            for (int mt = 0; mt < 4; mt++) {
                int mr = wm + mt * 16 + gid;
                ah[mt][0] = U32(Ah[mr * QST + kc]);
                ah[mt][1] = U32(Ah[(mr + 8) * QST + kc]);
                ah[mt][2] = U32(Ah[mr * QST + kc + 8]);
                ah[mt][3] = U32(Ah[(mr + 8) * QST + kc + 8]);
                al[mt][0] = U32(Al[mr * QST + kc]);
                al[mt][1] = U32(Al[(mr + 8) * QST + kc]);
                al[mt][2] = U32(Al[mr * QST + kc + 8]);
                al[mt][3] = U32(Al[(mr + 8) * QST + kc + 8]);
            }
#pragma unroll
            for (int nt = 0; nt < 4; nt++) {
                int nr = wn + nt * 8 + gid;
                uint32_t bh0 = U32(Bh[nr * QST + kc]);
                uint32_t bh1 = U32(Bh[nr * QST + kc + 8]);
                uint32_t bl0 = U32(Bl[nr * QST + kc]);
                uint32_t bl1 = U32(Bl[nr * QST + kc + 8]);
#pragma unroll
                for (int mt = 0; mt < 4; mt++) {
                    mma_f16(c[mt][nt], ah[mt][0], ah[mt][1], ah[mt][2], ah[mt][3], bh0, bh1);
                    mma_f16(c[mt][nt], ah[mt][0], ah[mt][1], ah[mt][2], ah[mt][3], bl0, bl1);
                    mma_f16(c[mt][nt], al[mt][0], al[mt][1], al[mt][2], al[mt][3], bh0, bh1);
                }
            }
        }
    }

#pragma unroll
    for (int mt = 0; mt < 4; mt++) {
#pragma unroll
        for (int nt = 0; nt < 4; nt++) {
            int m  = m0 + wm + mt * 16 + gid;
            int n  = n0 + wn + nt * 8 + tig * 2;
            float2 v0, v1;
            v0.x = c[mt][nt][0] + bo[n];
            v0.y = c[mt][nt][1] + bo[n + 1];
            v1.x = c[mt][nt][2] + bo[n];
            v1.y = c[mt][nt][3] + bo[n + 1];
            *(float2*)&out[(size_t)m * DM + n]       = v0;
            *(float2*)&out[(size_t)(m + 8) * DM + n] = v1;
        }
    }
}

// ---------------------------------------------------------------------------
extern "C" void kernel_launch(void* const* d_in, const int* in_sizes, int n_in,
                              void* d_out, int out_size)
{
    const float* x  = (const float*)d_in[0];
    const float* Wq = (const float*)d_in[1];
    const float* bq = (const float*)d_in[2];
    const float* Wk = (const float*)d_in[3];
    const float* bk = (const float*)d_in[4];
    const float* Wv = (const float*)d_in[5];
    const float* bv = (const float*)d_in[6];
    const float* Wo = (const float*)d_in[7];
    const float* bo = (const float*)d_in[8];
    float* out = (float*)d_out;

    cudaFuncSetAttribute(qkv_mma_kernel,
                         cudaFuncAttributeMaxDynamicSharedMemorySize,
                         (int)QKV_SMEM_BYTES);
    cudaFuncSetAttribute(attn_mma_kernel,
                         cudaFuncAttributeMaxDynamicSharedMemorySize,
                         (int)ATTN_SMEM_BYTES);
    cudaFuncSetAttribute(proj_mma_kernel,
                         cudaFuncAttributeMaxDynamicSharedMemorySize,
                         (int)PROJ_SMEM_BYTES);

    qkv_mma_kernel<<<dim3(BB * SS / 128, HH), 256, QKV_SMEM_BYTES>>>(
        x, Wq, bq, Wk, bk, Wv, bv);
    attn_mma_kernel<<<dim3(SS / 128, BB * HH), 256, ATTN_SMEM_BYTES>>>();
    proj_mma_kernel<<<dim3(DM / 128, BB * SS / 128), 256, PROJ_SMEM_BYTES>>>(Wo, bo, out);
}

// round 8
// speedup vs baseline: 3.6854x; 1.1853x over previous
#include <cuda_runtime.h>
#include <cuda_fp16.h>
#include <cstdint>

#define BB 2
#define SS 2048
#define DM 1024
#define HH 16
#define DH 64
#define NE ((size_t)BB * HH * SS * DH)   // 4M elements per tensor

// Pre-split fp16 hi/lo scratch (allocation-free rule: __device__ globals)
__device__ __half g_qh[NE], g_ql[NE];            // Q*0.125: [bh][s][d]
__device__ __half g_kh[NE], g_kl[NE];            // K:       [bh][s][d]
__device__ __half g_vth[NE], g_vtl[NE];          // V^T:     [bh][d][s]
__device__ __half g_oh[NE], g_ol[NE];            // attnout: [b][s][h*64+d]
__device__ __half g_woh[(size_t)DM * DM], g_wol[(size_t)DM * DM];

// ---------------------------------------------------------------------------
// fp16 helpers (mma.sync m16n8k16 — legacy HMMA, works on compute_103)
// ---------------------------------------------------------------------------
__device__ __forceinline__ void h_split(float x, float& hi, float& lo) {
    hi = __half2float(__float2half_rn(x));
    lo = x - hi;
}
__device__ __forceinline__ uint32_t f22h2(float a, float b) {
    __half2 h = __floats2half2_rn(a, b);
    return *(uint32_t*)&h;
}

__device__ __forceinline__ void mma_f16(float c[4],
                                        uint32_t a0, uint32_t a1,
                                        uint32_t a2, uint32_t a3,
                                        uint32_t b0, uint32_t b1) {
    asm volatile(
        "mma.sync.aligned.m16n8k16.row.col.f32.f16.f16.f32 "
        "{%0,%1,%2,%3}, {%4,%5,%6,%7}, {%8,%9}, {%0,%1,%2,%3};"
        : "+f"(c[0]), "+f"(c[1]), "+f"(c[2]), "+f"(c[3])
        : "r"(a0), "r"(a1), "r"(a2), "r"(a3), "r"(b0), "r"(b1));
}

#define U32(p) (*(const uint32_t*)&(p))

// ---------------------------------------------------------------------------
// Kernel 0: one-shot Wo hi/lo split.
// ---------------------------------------------------------------------------
__global__ __launch_bounds__(256) void wsplit_kernel(const float* __restrict__ w)
{
    int i = (blockIdx.x * 256 + threadIdx.x) * 4;
    float4 v = *(const float4*)&w[i];
    float h0, l0, h1, l1, h2, l2, h3, l3;
    h_split(v.x, h0, l0); h_split(v.y, h1, l1);
    h_split(v.z, h2, l2); h_split(v.w, h3, l3);
    *(uint2*)&g_woh[i] = make_uint2(f22h2(h0, h1), f22h2(h2, h3));
    *(uint2*)&g_wol[i] = make_uint2(f22h2(l0, l1), f22h2(l2, l3));
}

// ---------------------------------------------------------------------------
// Kernel 1: fused QKV projections; epilogue writes pre-split fp16 hi/lo
// (Q scaled by 1/8; V transposed to [bh][d][s]).
// ---------------------------------------------------------------------------
#define QST 72   // smem stride in halves
#define QKV_SMEM_HALVES (2 * 128 * QST + 2 * 64 * QST)
#define QKV_SMEM_BYTES  (QKV_SMEM_HALVES * 2)     // 55296

__global__ __launch_bounds__(256, 2) void qkv_mma_kernel(
    const float* __restrict__ x,
    const float* __restrict__ Wq, const float* __restrict__ bq,
    const float* __restrict__ Wk, const float* __restrict__ bk,
    const float* __restrict__ Wv, const float* __restrict__ bv)
{
    extern __shared__ __half qsm[];
    __half* Xh = qsm;
    __half* Xl = qsm + 128 * QST;
    __half* Wh = qsm + 2 * 128 * QST;
    __half* Wl = Wh + 64 * QST;

    const int h    = blockIdx.y;
    const int tok0 = blockIdx.x * 128;
    const int tid  = threadIdx.x;
    const int lane = tid & 31, warp = tid >> 5;
    const int gid  = lane >> 2, tig = lane & 3;
    const int wm   = (warp >> 1) * 32;
    const int wn   = (warp & 1) * 32;

    for (int idx = tid; idx < 2048; idx += 256) {
        int r = idx >> 4, d = (idx & 15) << 2;
        float4 v = *(const float4*)&x[(size_t)(tok0 + r) * DM + h * DH + d];
        float h0, l0, h1, l1, h2, l2, h3, l3;
        h_split(v.x, h0, l0); h_split(v.y, h1, l1);
        h_split(v.z, h2, l2); h_split(v.w, h3, l3);
        *(uint2*)&Xh[r * QST + d] = make_uint2(f22h2(h0, h1), f22h2(h2, h3));
        *(uint2*)&Xl[r * QST + d] = make_uint2(f22h2(l0, l1), f22h2(l2, l3));
    }

    const float* Wp[3] = {Wq, Wk, Wv};
    const float* bp[3] = {bq, bk, bv};

    for (int p = 0; p < 3; p++) {
        __syncthreads();
        for (int idx = tid; idx < 1024; idx += 256) {
            int r = idx >> 4, d = (idx & 15) << 2;
            float4 v = *(const float4*)&Wp[p][(size_t)(h * DH + r) * DH + d];
            float h0, l0, h1, l1, h2, l2, h3, l3;
            h_split(v.x, h0, l0); h_split(v.y, h1, l1);
            h_split(v.z, h2, l2); h_split(v.w, h3, l3);
            *(uint2*)&Wh[r * QST + d] = make_uint2(f22h2(h0, h1), f22h2(h2, h3));
            *(uint2*)&Wl[r * QST + d] = make_uint2(f22h2(l0, l1), f22h2(l2, l3));
        }
        __syncthreads();

        float c[2][4][4] = {};
#pragma unroll
        for (int ks = 0; ks < 4; ks++) {
            const int kc = ks * 16 + 2 * tig;
            uint32_t ah[2][4], al[2][4];
#pragma unroll
            for (int mt = 0; mt < 2; mt++) {
                int mr = wm + mt * 16 + gid;
                ah[mt][0] = U32(Xh[mr * QST + kc]);
                ah[mt][1] = U32(Xh[(mr + 8) * QST + kc]);
                ah[mt][2] = U32(Xh[mr * QST + kc + 8]);
                ah[mt][3] = U32(Xh[(mr + 8) * QST + kc + 8]);
                al[mt][0] = U32(Xl[mr * QST + kc]);
                al[mt][1] = U32(Xl[(mr + 8) * QST + kc]);
                al[mt][2] = U32(Xl[mr * QST + kc + 8]);
                al[mt][3] = U32(Xl[(mr + 8) * QST + kc + 8]);
            }
#pragma unroll
            for (int nt = 0; nt < 4; nt++) {
                int nr = wn + nt * 8 + gid;
                uint32_t bh0 = U32(Wh[nr * QST + kc]);
                uint32_t bh1 = U32(Wh[nr * QST + kc + 8]);
                uint32_t bl0 = U32(Wl[nr * QST + kc]);
                uint32_t bl1 = U32(Wl[nr * QST + kc + 8]);
#pragma unroll
                for (int mt = 0; mt < 2; mt++) {
                    mma_f16(c[mt][nt], ah[mt][0], ah[mt][1], ah[mt][2], ah[mt][3], bh0, bh1);
                    mma_f16(c[mt][nt], ah[mt][0], ah[mt][1], ah[mt][2], ah[mt][3], bl0, bl1);
                    mma_f16(c[mt][nt], al[mt][0], al[mt][1], al[mt][2], al[mt][3], bh0, bh1);
                }
            }
        }

        // epilogue: +bias, (Q: *0.125), split to fp16 hi/lo, store
#pragma unroll
        for (int mt = 0; mt < 2; mt++) {
#pragma unroll
            for (int nt = 0; nt < 4; nt++) {
                int gtok = tok0 + wm + mt * 16 + gid;
                int o    = wn + nt * 8 + 2 * tig;
                float b0 = bp[p][h * DH + o], b1 = bp[p][h * DH + o + 1];
                int bidx = gtok >> 11;
                int s    = gtok & (SS - 1);
                size_t bh_ = (size_t)bidx * HH + h;
                float r0c0 = c[mt][nt][0] + b0, r0c1 = c[mt][nt][1] + b1;
                float r1c0 = c[mt][nt][2] + b0, r1c1 = c[mt][nt][3] + b1;
                if (p == 0) {
                    r0c0 *= 0.125f; r0c1 *= 0.125f;
                    r1c0 *= 0.125f; r1c1 *= 0.125f;
                }
                float h0, l0, h1, l1, h2, l2, h3, l3;
                h_split(r0c0, h0, l0); h_split(r0c1, h1, l1);
                h_split(r1c0, h2, l2); h_split(r1c1, h3, l3);
                if (p < 2) {
                    __half* H = (p == 0) ? g_qh : g_kh;
                    __half* L = (p == 0) ? g_ql : g_kl;
                    size_t a0 = (bh_ * SS + s) * DH + o;
                    *(uint32_t*)&H[a0] = f22h2(h0, h1);
                    *(uint32_t*)&L[a0] = f22h2(l0, l1);
                    size_t a1 = a0 + 8 * DH;
                    *(uint32_t*)&H[a1] = f22h2(h2, h3);
                    *(uint32_t*)&L[a1] = f22h2(l2, l3);
                } else {
                    // V transposed: [bh][d][s]
                    size_t vb0 = (bh_ * DH + o) * SS;
                    size_t vb1 = vb0 + SS;
                    g_vth[vb0 + s]     = __float2half_rn(h0);
                    g_vtl[vb0 + s]     = __float2half_rn(l0);
                    g_vth[vb1 + s]     = __float2half_rn(h1);
                    g_vtl[vb1 + s]     = __float2half_rn(l1);
                    g_vth[vb0 + s + 8] = __float2half_rn(h2);
                    g_vtl[vb0 + s + 8] = __float2half_rn(l2);
                    g_vth[vb1 + s + 8] = __float2half_rn(h3);
                    g_vtl[vb1 + s + 8] = __float2half_rn(l3);
                }
            }
        }
    }
}

// ---------------------------------------------------------------------------
// Kernel 2: causal flash attention; staging = pure uint4 copies of
// pre-split fp16 (K hi/lo [s][d], V hi/lo pre-transposed [d][s]).
// ---------------------------------------------------------------------------
#define AQH 0
#define AQL (128 * QST)
#define AKH (2 * 128 * QST)
#define AKL (AKH + 64 * QST)
#define AVH (AKL + 64 * QST)
#define AVL (AVH + 64 * QST)
#define APS (AVL + 64 * QST)
#define ATTN_SMEM_HALVES (APS + 128 * QST)
#define ATTN_SMEM_BYTES  (ATTN_SMEM_HALVES * 2)    // 92160

__global__ __launch_bounds__(256, 2) void attn_mma_kernel()
{
    extern __shared__ __half asm_[];
    __half* Qh = asm_ + AQH;  __half* Ql = asm_ + AQL;
    __half* Kh = asm_ + AKH;  __half* Kl = asm_ + AKL;
    __half* Vh = asm_ + AVH;  __half* Vl = asm_ + AVL;
    __half* Ps = asm_ + APS;

    const int qt = gridDim.x - 1 - blockIdx.x;   // heavy tiles first
    const int bh = blockIdx.y;
    const int q0 = qt * 128;
    const __half* Qhg = g_qh + (size_t)bh * SS * DH;
    const __half* Qlg = g_ql + (size_t)bh * SS * DH;
    const __half* Khg = g_kh + (size_t)bh * SS * DH;
    const __half* Klg = g_kl + (size_t)bh * SS * DH;
    const __half* Vhg = g_vth + (size_t)bh * DH * SS;
    const __half* Vlg = g_vtl + (size_t)bh * DH * SS;

    const int tid  = threadIdx.x;
    const int warp = tid >> 5, lane = tid & 31;
    const int gid  = lane >> 2, tig = lane & 3;
    const int wr   = warp * 16;

    // stage Q once (pure copy; already scaled + split)
    for (int idx = tid; idx < 1024; idx += 256) {
        int r = idx >> 3, d8 = (idx & 7) << 3;
        *(uint4*)&Qh[r * QST + d8] = *(const uint4*)&Qhg[(size_t)(q0 + r) * DH + d8];
        *(uint4*)&Ql[r * QST + d8] = *(const uint4*)&Qlg[(size_t)(q0 + r) * DH + d8];
    }

    float o[8][4] = {};
    float m0 = -1e30f, m1 = -1e30f, l0s = 0.0f, l1s = 0.0f;
    const int nkt = 2 * qt + 2;

    for (int kt = 0; kt < nkt; kt++) {
        __syncthreads();
        // stage K [s][d] and V^T [d][s] — pure copies
        for (int idx = tid; idx < 512; idx += 256) {
            int r = idx >> 3, d8 = (idx & 7) << 3;
            size_t ka = (size_t)(kt * 64 + r) * DH + d8;
            *(uint4*)&Kh[r * QST + d8] = *(const uint4*)&Khg[ka];
            *(uint4*)&Kl[r * QST + d8] = *(const uint4*)&Klg[ka];
            size_t va = (size_t)r * SS + kt * 64 + d8;   // r = d, d8 = s-local
            *(uint4*)&Vh[r * QST + d8] = *(const uint4*)&Vhg[va];
            *(uint4*)&Vl[r * QST + d8] = *(const uint4*)&Vlg[va];
        }
        __syncthreads();

        // S = Q K^T, 3-product split
        float c[8][4] = {};
#pragma unroll
        for (int ks = 0; ks < 4; ks++) {
            const int kc = ks * 16 + 2 * tig;
            uint32_t ah[4], al[4];
            ah[0] = U32(Qh[(wr + gid) * QST + kc]);
            ah[1] = U32(Qh[(wr + gid + 8) * QST + kc]);
            ah[2] = U32(Qh[(wr + gid) * QST + kc + 8]);
            ah[3] = U32(Qh[(wr + gid + 8) * QST + kc + 8]);
            al[0] = U32(Ql[(wr + gid) * QST + kc]);
            al[1] = U32(Ql[(wr + gid + 8) * QST + kc]);
            al[2] = U32(Ql[(wr + gid) * QST + kc + 8]);
            al[3] = U32(Ql[(wr + gid + 8) * QST + kc + 8]);
#pragma unroll
            for (int nt = 0; nt < 8; nt++) {
                int nr = nt * 8 + gid;
                uint32_t bh0 = U32(Kh[nr * QST + kc]);
                uint32_t bh1 = U32(Kh[nr * QST + kc + 8]);
                uint32_t bl0 = U32(Kl[nr * QST + kc]);
                uint32_t bl1 = U32(Kl[nr * QST + kc + 8]);
                mma_f16(c[nt], ah[0], ah[1], ah[2], ah[3], bh0, bh1);
                mma_f16(c[nt], ah[0], ah[1], ah[2], ah[3], bl0, bl1);
                mma_f16(c[nt], al[0], al[1], al[2], al[3], bh0, bh1);
            }
        }

        // causal mask (diagonal band only)
        const int row0 = q0 + wr + gid, row1 = row0 + 8;
        if (kt >= 2 * qt) {
#pragma unroll
            for (int nt = 0; nt < 8; nt++) {
                int col = kt * 64 + nt * 8 + 2 * tig;
                if (col > row0)     c[nt][0] = -1e30f;
                if (col + 1 > row0) c[nt][1] = -1e30f;
                if (col > row1)     c[nt][2] = -1e30f;
                if (col + 1 > row1) c[nt][3] = -1e30f;
            }
        }

        // online softmax (registers, quad shuffle)
        float mx0 = -1e30f, mx1 = -1e30f;
#pragma unroll
        for (int nt = 0; nt < 8; nt++) {
            mx0 = fmaxf(mx0, fmaxf(c[nt][0], c[nt][1]));
            mx1 = fmaxf(mx1, fmaxf(c[nt][2], c[nt][3]));
        }
        mx0 = fmaxf(mx0, __shfl_xor_sync(0xffffffffu, mx0, 1));
        mx0 = fmaxf(mx0, __shfl_xor_sync(0xffffffffu, mx0, 2));
        mx1 = fmaxf(mx1, __shfl_xor_sync(0xffffffffu, mx1, 1));
        mx1 = fmaxf(mx1, __shfl_xor_sync(0xffffffffu, mx1, 2));
        float mn0 = fmaxf(m0, mx0), mn1 = fmaxf(m1, mx1);
        float a0 = __expf(m0 - mn0), a1 = __expf(m1 - mn1);
        m0 = mn0; m1 = mn1;

        float s0 = 0.0f, s1 = 0.0f;
#pragma unroll
        for (int nt = 0; nt < 8; nt++) {
            __half2 p0 = __floats2half2_rn(__expf(c[nt][0] - mn0),
                                           __expf(c[nt][1] - mn0));
            __half2 p1 = __floats2half2_rn(__expf(c[nt][2] - mn1),
                                           __expf(c[nt][3] - mn1));
            float2 pf0 = __half22float2(p0), pf1 = __half22float2(p1);
            s0 += pf0.x + pf0.y;
            s1 += pf1.x + pf1.y;
            *(uint32_t*)&Ps[(wr + gid) * QST + nt * 8 + 2 * tig]     = *(uint32_t*)&p0;
            *(uint32_t*)&Ps[(wr + gid + 8) * QST + nt * 8 + 2 * tig] = *(uint32_t*)&p1;
        }
        s0 += __shfl_xor_sync(0xffffffffu, s0, 1);
        s0 += __shfl_xor_sync(0xffffffffu, s0, 2);
        s1 += __shfl_xor_sync(0xffffffffu, s1, 1);
        s1 += __shfl_xor_sync(0xffffffffu, s1, 2);
        l0s = l0s * a0 + s0;
        l1s = l1s * a1 + s1;

#pragma unroll
        for (int nt = 0; nt < 8; nt++) {
            o[nt][0] *= a0; o[nt][1] *= a0;
            o[nt][2] *= a1; o[nt][3] *= a1;
        }
        __syncwarp();   // P stores visible within warp

        // O += P V
#pragma unroll
        for (int ks = 0; ks < 4; ks++) {
            const int kc = ks * 16 + 2 * tig;
            uint32_t pa[4];
            pa[0] = U32(Ps[(wr + gid) * QST + kc]);
            pa[1] = U32(Ps[(wr + gid + 8) * QST + kc]);
            pa[2] = U32(Ps[(wr + gid) * QST + kc + 8]);
            pa[3] = U32(Ps[(wr + gid + 8) * QST + kc + 8]);
#pragma unroll
            for (int nt = 0; nt < 8; nt++) {
                int nr = nt * 8 + gid;
                uint32_t bh0 = U32(Vh[nr * QST + kc]);
                uint32_t bh1 = U32(Vh[nr * QST + kc + 8]);
                uint32_t bl0 = U32(Vl[nr * QST + kc]);
                uint32_t bl1 = U32(Vl[nr * QST + kc + 8]);
                mma_f16(o[nt], pa[0], pa[1], pa[2], pa[3], bh0, bh1);
                mma_f16(o[nt], pa[0], pa[1], pa[2], pa[3], bl0, bl1);
            }
        }
    }

    // epilogue: normalize, split, write pre-split O halves [b][s][h*64+d]
    const int bidx = bh / HH, h = bh % HH;
    const float i0 = 1.0f / l0s, i1 = 1.0f / l1s;
    const int r0 = q0 + wr + gid;
#pragma unroll
    for (int nt = 0; nt < 8; nt++) {
        int d = nt * 8 + 2 * tig;
        float v0 = o[nt][0] * i0, v1 = o[nt][1] * i0;
        float v2 = o[nt][2] * i1, v3 = o[nt][3] * i1;
        float h0, l0, h1, l1, h2, l2, h3, l3;
        h_split(v0, h0, l0); h_split(v1, h1, l1);
        h_split(v2, h2, l2); h_split(v3, h3, l3);
        size_t a0 = ((size_t)bidx * SS + r0) * DM + h * DH + d;
        *(uint32_t*)&g_oh[a0] = f22h2(h0, h1);
        *(uint32_t*)&g_ol[a0] = f22h2(l0, l1);
        size_t a1 = a0 + 8 * DM;
        *(uint32_t*)&g_oh[a1] = f22h2(h2, h3);
        *(uint32_t*)&g_ol[a1] = f22h2(l2, l3);
    }
}

// ---------------------------------------------------------------------------
// Kernel 3: output projection; staging = pure uint4 copies of pre-split A/Wo.
// ---------------------------------------------------------------------------
#define PROJ_SMEM_HALVES (4 * 128 * QST)
#define PROJ_SMEM_BYTES  (PROJ_SMEM_HALVES * 2)   // 73728

__global__ __launch_bounds__(256, 2) void proj_mma_kernel(
    const float* __restrict__ bo, float* __restrict__ out)
{
    extern __shared__ __half psm[];
    __half* Ah = psm;
    __half* Al = psm + 128 * QST;
    __half* Bh = psm + 2 * 128 * QST;
    __half* Bl = psm + 3 * 128 * QST;

    const int n0 = blockIdx.x * 128;
    const int m0 = blockIdx.y * 128;
    const int tid  = threadIdx.x;
    const int lane = tid & 31, warp = tid >> 5;
    const int wm = (warp >> 2) * 64;
    const int wn = (warp & 3) * 32;
    const int gid = lane >> 2, tig = lane & 3;

    float c[4][4][4] = {};

    for (int k0 = 0; k0 < DM; k0 += 64) {
        __syncthreads();
        for (int idx = tid; idx < 1024; idx += 256) {
            int r = idx >> 3, q8 = (idx & 7) << 3;
            size_t aa = (size_t)(m0 + r) * DM + k0 + q8;
            *(uint4*)&Ah[r * QST + q8] = *(const uint4*)&g_oh[aa];
            *(uint4*)&Al[r * QST + q8] = *(const uint4*)&g_ol[aa];
            size_t ba = (size_t)(n0 + r) * DM + k0 + q8;
            *(uint4*)&Bh[r * QST + q8] = *(const uint4*)&g_woh[ba];
            *(uint4*)&Bl[r * QST + q8] = *(const uint4*)&g_wol[ba];
        }
        __syncthreads();

#pragma unroll
        for (int ks = 0; ks < 4; ks++) {
            const int kc = ks * 16 + 2 * tig;
            uint32_t ah[4][4], al[4][4];
#pragma unroll
            for (int mt = 0; mt < 4; mt++) {
                int mr = wm + mt * 16 + gid;
                ah[mt][0] = U32(Ah[mr * QST + kc]);
                ah[mt][1] = U32(Ah[(mr + 8) * QST + kc]);
                ah[mt][2] = U32(Ah[mr * QST + kc + 8]);
                ah[mt][3] = U32(Ah[(mr + 8) * QST + kc + 8]);
                al[mt][0] = U32(Al[mr * QST + kc]);
                al[mt][1] = U32(Al[(mr + 8) * QST + kc]);
                al[mt][2] = U32(Al[mr * QST + kc + 8]);
                al[mt][3] = U32(Al[(mr + 8) * QST + kc + 8]);
            }
#pragma unroll
            for (int nt = 0; nt < 4; nt++) {
                int nr = wn + nt * 8 + gid;
                uint32_t bh0 = U32(Bh[nr * QST + kc]);
                uint32_t bh1 = U32(Bh[nr * QST + kc + 8]);
                uint32_t bl0 = U32(Bl[nr * QST + kc]);
                uint32_t bl1 = U32(Bl[nr * QST + kc + 8]);
#pragma unroll
                for (int mt = 0; mt < 4; mt++) {
                    mma_f16(c[mt][nt], ah[mt][0], ah[mt][1], ah[mt][2], ah[mt][3], bh0, bh1);
                    mma_f16(c[mt][nt], ah[mt][0], ah[mt][1], ah[mt][2], ah[mt][3], bl0, bl1);
                    mma_f16(c[mt][nt], al[mt][0], al[mt][1], al[mt][2], al[mt][3], bh0, bh1);
                }
            }
        }
    }

#pragma unroll
    for (int mt = 0; mt < 4; mt++) {
#pragma unroll
        for (int nt = 0; nt < 4; nt++) {
            int m  = m0 + wm + mt * 16 + gid;
            int n  = n0 + wn + nt * 8 + tig * 2;
            float2 v0, v1;
            v0.x = c[mt][nt][0] + bo[n];
            v0.y = c[mt][nt][1] + bo[n + 1];
            v1.x = c[mt][nt][2] + bo[n];
            v1.y = c[mt][nt][3] + bo[n + 1];
            *(float2*)&out[(size_t)m * DM + n]       = v0;
            *(float2*)&out[(size_t)(m + 8) * DM + n] = v1;
        }
    }
}

// ---------------------------------------------------------------------------
extern "C" void kernel_launch(void* const* d_in, const int* in_sizes, int n_in,
                              void* d_out, int out_size)
{
    const float* x  = (const float*)d_in[0];
    const float* Wq = (const float*)d_in[1];
    const float* bq = (const float*)d_in[2];
    const float* Wk = (const float*)d_in[3];
    const float* bk = (const float*)d_in[4];
    const float* Wv = (const float*)d_in[5];
    const float* bv = (const float*)d_in[6];
    const float* Wo = (const float*)d_in[7];
    const float* bo = (const float*)d_in[8];
    float* out = (float*)d_out;

    cudaFuncSetAttribute(qkv_mma_kernel,
                         cudaFuncAttributeMaxDynamicSharedMemorySize,
                         (int)QKV_SMEM_BYTES);
    cudaFuncSetAttribute(attn_mma_kernel,
                         cudaFuncAttributeMaxDynamicSharedMemorySize,
                         (int)ATTN_SMEM_BYTES);
    cudaFuncSetAttribute(proj_mma_kernel,
                         cudaFuncAttributeMaxDynamicSharedMemorySize,
                         (int)PROJ_SMEM_BYTES);

    wsplit_kernel<<<DM * DM / 1024, 256>>>(Wo);
    qkv_mma_kernel<<<dim3(BB * SS / 128, HH), 256, QKV_SMEM_BYTES>>>(
        x, Wq, bq, Wk, bk, Wv, bv);
    attn_mma_kernel<<<dim3(SS / 128, BB * HH), 256, ATTN_SMEM_BYTES>>>();
    proj_mma_kernel<<<dim3(DM / 128, BB * SS / 128), 256, PROJ_SMEM_BYTES>>>(bo, out);
}

// round 9
// speedup vs baseline: 4.0856x; 1.1086x over previous
#include <cuda_runtime.h>
#include <cuda_fp16.h>
#include <cstdint>

#define BB 2
#define SS 2048
#define DM 1024
#define HH 16
#define DH 64
#define NE ((size_t)BB * HH * SS * DH)   // 4M elements per tensor

// Pre-split fp16 hi/lo scratch (allocation-free rule: __device__ globals)
__device__ __half g_qh[NE], g_ql[NE];            // Q*0.125: [bh][s][d]
__device__ __half g_kh[NE], g_kl[NE];            // K:       [bh][s][d]
__device__ __half g_vth[NE], g_vtl[NE];          // V^T:     [bh][d][s]
__device__ __half g_oh[NE], g_ol[NE];            // attnout: [b][s][h*64+d]
__device__ __half g_woh[(size_t)DM * DM], g_wol[(size_t)DM * DM];

// ---------------------------------------------------------------------------
// fp16 helpers (mma.sync m16n8k16 + ldmatrix — legacy path, compute_103-safe)
// ---------------------------------------------------------------------------
__device__ __forceinline__ void h_split(float x, float& hi, float& lo) {
    hi = __half2float(__float2half_rn(x));
    lo = x - hi;
}
__device__ __forceinline__ uint32_t f22h2(float a, float b) {
    __half2 h = __floats2half2_rn(a, b);
    return *(uint32_t*)&h;
}
__device__ __forceinline__ uint32_t sptr(const void* p) {
    return (uint32_t)__cvta_generic_to_shared(p);
}
__device__ __forceinline__ void ldmx4(uint32_t r[4], uint32_t addr) {
    asm volatile("ldmatrix.sync.aligned.m8n8.x4.shared.b16 {%0,%1,%2,%3}, [%4];"
                 : "=r"(r[0]), "=r"(r[1]), "=r"(r[2]), "=r"(r[3]) : "r"(addr));
}
__device__ __forceinline__ void mma_f16(float c[4],
                                        uint32_t a0, uint32_t a1,
                                        uint32_t a2, uint32_t a3,
                                        uint32_t b0, uint32_t b1) {
    asm volatile(
        "mma.sync.aligned.m16n8k16.row.col.f32.f16.f16.f32 "
        "{%0,%1,%2,%3}, {%4,%5,%6,%7}, {%8,%9}, {%0,%1,%2,%3};"
        : "+f"(c[0]), "+f"(c[1]), "+f"(c[2]), "+f"(c[3])
        : "r"(a0), "r"(a1), "r"(a2), "r"(a3), "r"(b0), "r"(b1));
}

#define U32(p) (*(const uint32_t*)&(p))

// ---------------------------------------------------------------------------
// Kernel 0: one-shot Wo hi/lo split.
// ---------------------------------------------------------------------------
__global__ __launch_bounds__(256) void wsplit_kernel(const float* __restrict__ w)
{
    int i = (blockIdx.x * 256 + threadIdx.x) * 4;
    float4 v = *(const float4*)&w[i];
    float h0, l0, h1, l1, h2, l2, h3, l3;
    h_split(v.x, h0, l0); h_split(v.y, h1, l1);
    h_split(v.z, h2, l2); h_split(v.w, h3, l3);
    *(uint2*)&g_woh[i] = make_uint2(f22h2(h0, h1), f22h2(h2, h3));
    *(uint2*)&g_wol[i] = make_uint2(f22h2(l0, l1), f22h2(l2, l3));
}

// ---------------------------------------------------------------------------
// Kernel 1: fused QKV projections (unchanged from R8).
// ---------------------------------------------------------------------------
#define QST 72   // smem stride in halves (144 B: ldmatrix rows conflict-free)
#define QKV_SMEM_HALVES (2 * 128 * QST + 2 * 64 * QST)
#define QKV_SMEM_BYTES  (QKV_SMEM_HALVES * 2)     // 55296

__global__ __launch_bounds__(256, 2) void qkv_mma_kernel(
    const float* __restrict__ x,
    const float* __restrict__ Wq, const float* __restrict__ bq,
    const float* __restrict__ Wk, const float* __restrict__ bk,
    const float* __restrict__ Wv, const float* __restrict__ bv)
{
    extern __shared__ __half qsm[];
    __half* Xh = qsm;
    __half* Xl = qsm + 128 * QST;
    __half* Wh = qsm + 2 * 128 * QST;
    __half* Wl = Wh + 64 * QST;

    const int h    = blockIdx.y;
    const int tok0 = blockIdx.x * 128;
    const int tid  = threadIdx.x;
    const int lane = tid & 31, warp = tid >> 5;
    const int gid  = lane >> 2, tig = lane & 3;
    const int wm   = (warp >> 1) * 32;
    const int wn   = (warp & 1) * 32;

    for (int idx = tid; idx < 2048; idx += 256) {
        int r = idx >> 4, d = (idx & 15) << 2;
        float4 v = *(const float4*)&x[(size_t)(tok0 + r) * DM + h * DH + d];
        float h0, l0, h1, l1, h2, l2, h3, l3;
        h_split(v.x, h0, l0); h_split(v.y, h1, l1);
        h_split(v.z, h2, l2); h_split(v.w, h3, l3);
        *(uint2*)&Xh[r * QST + d] = make_uint2(f22h2(h0, h1), f22h2(h2, h3));
        *(uint2*)&Xl[r * QST + d] = make_uint2(f22h2(l0, l1), f22h2(l2, l3));
    }

    const float* Wp[3] = {Wq, Wk, Wv};
    const float* bp[3] = {bq, bk, bv};

    for (int p = 0; p < 3; p++) {
        __syncthreads();
        for (int idx = tid; idx < 1024; idx += 256) {
            int r = idx >> 4, d = (idx & 15) << 2;
            float4 v = *(const float4*)&Wp[p][(size_t)(h * DH + r) * DH + d];
            float h0, l0, h1, l1, h2, l2, h3, l3;
            h_split(v.x, h0, l0); h_split(v.y, h1, l1);
            h_split(v.z, h2, l2); h_split(v.w, h3, l3);
            *(uint2*)&Wh[r * QST + d] = make_uint2(f22h2(h0, h1), f22h2(h2, h3));
            *(uint2*)&Wl[r * QST + d] = make_uint2(f22h2(l0, l1), f22h2(l2, l3));
        }
        __syncthreads();

        float c[2][4][4] = {};
#pragma unroll
        for (int ks = 0; ks < 4; ks++) {
            const int kc = ks * 16 + 2 * tig;
            uint32_t ah[2][4], al[2][4];
#pragma unroll
            for (int mt = 0; mt < 2; mt++) {
                int mr = wm + mt * 16 + gid;
                ah[mt][0] = U32(Xh[mr * QST + kc]);
                ah[mt][1] = U32(Xh[(mr + 8) * QST + kc]);
                ah[mt][2] = U32(Xh[mr * QST + kc + 8]);
                ah[mt][3] = U32(Xh[(mr + 8) * QST + kc + 8]);
                al[mt][0] = U32(Xl[mr * QST + kc]);
                al[mt][1] = U32(Xl[(mr + 8) * QST + kc]);
                al[mt][2] = U32(Xl[mr * QST + kc + 8]);
                al[mt][3] = U32(Xl[(mr + 8) * QST + kc + 8]);
            }
#pragma unroll
            for (int nt = 0; nt < 4; nt++) {
                int nr = wn + nt * 8 + gid;
                uint32_t bh0 = U32(Wh[nr * QST + kc]);
                uint32_t bh1 = U32(Wh[nr * QST + kc + 8]);
                uint32_t bl0 = U32(Wl[nr * QST + kc]);
                uint32_t bl1 = U32(Wl[nr * QST + kc + 8]);
#pragma unroll
                for (int mt = 0; mt < 2; mt++) {
                    mma_f16(c[mt][nt], ah[mt][0], ah[mt][1], ah[mt][2], ah[mt][3], bh0, bh1);
                    mma_f16(c[mt][nt], ah[mt][0], ah[mt][1], ah[mt][2], ah[mt][3], bl0, bl1);
                    mma_f16(c[mt][nt], al[mt][0], al[mt][1], al[mt][2], al[mt][3], bh0, bh1);
                }
            }
        }

        // epilogue: +bias, (Q: *0.125), split to fp16 hi/lo, store
#pragma unroll
        for (int mt = 0; mt < 2; mt++) {
#pragma unroll
            for (int nt = 0; nt < 4; nt++) {
                int gtok = tok0 + wm + mt * 16 + gid;
                int o    = wn + nt * 8 + 2 * tig;
                float b0 = bp[p][h * DH + o], b1 = bp[p][h * DH + o + 1];
                int bidx = gtok >> 11;
                int s    = gtok & (SS - 1);
                size_t bh_ = (size_t)bidx * HH + h;
                float r0c0 = c[mt][nt][0] + b0, r0c1 = c[mt][nt][1] + b1;
                float r1c0 = c[mt][nt][2] + b0, r1c1 = c[mt][nt][3] + b1;
                if (p == 0) {
                    r0c0 *= 0.125f; r0c1 *= 0.125f;
                    r1c0 *= 0.125f; r1c1 *= 0.125f;
                }
                float h0, l0, h1, l1, h2, l2, h3, l3;
                h_split(r0c0, h0, l0); h_split(r0c1, h1, l1);
                h_split(r1c0, h2, l2); h_split(r1c1, h3, l3);
                if (p < 2) {
                    __half* H = (p == 0) ? g_qh : g_kh;
                    __half* L = (p == 0) ? g_ql : g_kl;
                    size_t a0 = (bh_ * SS + s) * DH + o;
                    *(uint32_t*)&H[a0] = f22h2(h0, h1);
                    *(uint32_t*)&L[a0] = f22h2(l0, l1);
                    size_t a1 = a0 + 8 * DH;
                    *(uint32_t*)&H[a1] = f22h2(h2, h3);
                    *(uint32_t*)&L[a1] = f22h2(l2, l3);
                } else {
                    size_t vb0 = (bh_ * DH + o) * SS;
                    size_t vb1 = vb0 + SS;
                    g_vth[vb0 + s]     = __float2half_rn(h0);
                    g_vtl[vb0 + s]     = __float2half_rn(l0);
                    g_vth[vb1 + s]     = __float2half_rn(h1);
                    g_vtl[vb1 + s]     = __float2half_rn(l1);
                    g_vth[vb0 + s + 8] = __float2half_rn(h2);
                    g_vtl[vb0 + s + 8] = __float2half_rn(l2);
                    g_vth[vb1 + s + 8] = __float2half_rn(h3);
                    g_vtl[vb1 + s + 8] = __float2half_rn(l3);
                }
            }
        }
    }
}

// ---------------------------------------------------------------------------
// Kernel 2: causal flash attention. ldmatrix fragment loads; P kept entirely
// in registers (QK^T accumulator layout == PV A-operand layout).
// ---------------------------------------------------------------------------
#define AQH 0
#define AQL (128 * QST)
#define AKH (2 * 128 * QST)
#define AKL (AKH + 64 * QST)
#define AVH (AKL + 64 * QST)
#define AVL (AVH + 64 * QST)
#define ATTN_SMEM_HALVES (AVL + 64 * QST)
#define ATTN_SMEM_BYTES  (ATTN_SMEM_HALVES * 2)    // 73728

__global__ __launch_bounds__(256, 2) void attn_mma_kernel()
{
    extern __shared__ __half asm_[];
    __half* Qh = asm_ + AQH;  __half* Ql = asm_ + AQL;
    __half* Kh = asm_ + AKH;  __half* Kl = asm_ + AKL;
    __half* Vh = asm_ + AVH;  __half* Vl = asm_ + AVL;

    const int qt = gridDim.x - 1 - blockIdx.x;   // heavy tiles first
    const int bh = blockIdx.y;
    const int q0 = qt * 128;
    const __half* Qhg = g_qh + (size_t)bh * SS * DH;
    const __half* Qlg = g_ql + (size_t)bh * SS * DH;
    const __half* Khg = g_kh + (size_t)bh * SS * DH;
    const __half* Klg = g_kl + (size_t)bh * SS * DH;
    const __half* Vhg = g_vth + (size_t)bh * DH * SS;
    const __half* Vlg = g_vtl + (size_t)bh * DH * SS;

    const int tid  = threadIdx.x;
    const int warp = tid >> 5, lane = tid & 31;
    const int gid  = lane >> 2, tig = lane & 3;
    const int wr   = warp * 16;

    // ldmatrix lane addressing
    const int arow = (lane & 15), acol = (lane >> 4) << 3;          // A operand
    const int brow = (lane & 7) + ((lane >> 4) << 3);               // B operand
    const int bcol = ((lane >> 3) & 1) << 3;

    const uint32_t qa_h = sptr(&Qh[(wr + arow) * QST + acol]);
    const uint32_t qa_l = sptr(&Ql[(wr + arow) * QST + acol]);
    uint32_t ka_h[4], ka_l[4], va_h[4], va_l[4];
#pragma unroll
    for (int np = 0; np < 4; np++) {
        ka_h[np] = sptr(&Kh[(np * 16 + brow) * QST + bcol]);
        ka_l[np] = sptr(&Kl[(np * 16 + brow) * QST + bcol]);
        va_h[np] = sptr(&Vh[(np * 16 + brow) * QST + bcol]);
        va_l[np] = sptr(&Vl[(np * 16 + brow) * QST + bcol]);
    }

    // stage Q once (pure copy; already scaled + split)
    for (int idx = tid; idx < 1024; idx += 256) {
        int r = idx >> 3, d8 = (idx & 7) << 3;
        *(uint4*)&Qh[r * QST + d8] = *(const uint4*)&Qhg[(size_t)(q0 + r) * DH + d8];
        *(uint4*)&Ql[r * QST + d8] = *(const uint4*)&Qlg[(size_t)(q0 + r) * DH + d8];
    }

    float o[8][4] = {};
    float m0 = -1e30f, m1 = -1e30f, l0s = 0.0f, l1s = 0.0f;
    const int nkt = 2 * qt + 2;

    for (int kt = 0; kt < nkt; kt++) {
        __syncthreads();
        // stage K [s][d] and V^T [d][s] — pure copies
        for (int idx = tid; idx < 512; idx += 256) {
            int r = idx >> 3, d8 = (idx & 7) << 3;
            size_t ka = (size_t)(kt * 64 + r) * DH + d8;
            *(uint4*)&Kh[r * QST + d8] = *(const uint4*)&Khg[ka];
            *(uint4*)&Kl[r * QST + d8] = *(const uint4*)&Klg[ka];
            size_t va = (size_t)r * SS + kt * 64 + d8;   // r = d, d8 = s-local
            *(uint4*)&Vh[r * QST + d8] = *(const uint4*)&Vhg[va];
            *(uint4*)&Vl[r * QST + d8] = *(const uint4*)&Vlg[va];
        }
        __syncthreads();

        // S = Q K^T, 3-product split, ldmatrix fragments
        float c[8][4] = {};
#pragma unroll
        for (int ks = 0; ks < 4; ks++) {
            uint32_t ah[4], al[4];
            ldmx4(ah, qa_h + ks * 32);
            ldmx4(al, qa_l + ks * 32);
#pragma unroll
            for (int np = 0; np < 4; np++) {
                uint32_t bh4[4], bl4[4];
                ldmx4(bh4, ka_h[np] + ks * 32);
                ldmx4(bl4, ka_l[np] + ks * 32);
                mma_f16(c[2 * np],     ah[0], ah[1], ah[2], ah[3], bh4[0], bh4[1]);
                mma_f16(c[2 * np],     ah[0], ah[1], ah[2], ah[3], bl4[0], bl4[1]);
                mma_f16(c[2 * np],     al[0], al[1], al[2], al[3], bh4[0], bh4[1]);
                mma_f16(c[2 * np + 1], ah[0], ah[1], ah[2], ah[3], bh4[2], bh4[3]);
                mma_f16(c[2 * np + 1], ah[0], ah[1], ah[2], ah[3], bl4[2], bl4[3]);
                mma_f16(c[2 * np + 1], al[0], al[1], al[2], al[3], bh4[2], bh4[3]);
            }
        }

        // causal mask (diagonal band only)
        const int row0 = q0 + wr + gid, row1 = row0 + 8;
        if (kt >= 2 * qt) {
#pragma unroll
            for (int nt = 0; nt < 8; nt++) {
                int col = kt * 64 + nt * 8 + 2 * tig;
                if (col > row0)     c[nt][0] = -1e30f;
                if (col + 1 > row0) c[nt][1] = -1e30f;
                if (col > row1)     c[nt][2] = -1e30f;
                if (col + 1 > row1) c[nt][3] = -1e30f;
            }
        }

        // online softmax (registers, quad shuffle)
        float mx0 = -1e30f, mx1 = -1e30f;
#pragma unroll
        for (int nt = 0; nt < 8; nt++) {
            mx0 = fmaxf(mx0, fmaxf(c[nt][0], c[nt][1]));
            mx1 = fmaxf(mx1, fmaxf(c[nt][2], c[nt][3]));
        }
        mx0 = fmaxf(mx0, __shfl_xor_sync(0xffffffffu, mx0, 1));
        mx0 = fmaxf(mx0, __shfl_xor_sync(0xffffffffu, mx0, 2));
        mx1 = fmaxf(mx1, __shfl_xor_sync(0xffffffffu, mx1, 1));
        mx1 = fmaxf(mx1, __shfl_xor_sync(0xffffffffu, mx1, 2));
        float mn0 = fmaxf(m0, mx0), mn1 = fmaxf(m1, mx1);
        float a0 = __expf(m0 - mn0), a1 = __expf(m1 - mn1);
        m0 = mn0; m1 = mn1;

        // exp + pack P directly into PV A-fragments (no smem round-trip)
        uint32_t pa[4][4];
        float s0 = 0.0f, s1 = 0.0f;
#pragma unroll
        for (int nt = 0; nt < 8; nt++) {
            __half2 p0 = __floats2half2_rn(__expf(c[nt][0] - mn0),
                                           __expf(c[nt][1] - mn0));
            __half2 p1 = __floats2half2_rn(__expf(c[nt][2] - mn1),
                                           __expf(c[nt][3] - mn1));
            float2 pf0 = __half22float2(p0), pf1 = __half22float2(p1);
            s0 += pf0.x + pf0.y;
            s1 += pf1.x + pf1.y;
            int ks = nt >> 1;
            if ((nt & 1) == 0) { pa[ks][0] = U32(p0); pa[ks][1] = U32(p1); }
            else               { pa[ks][2] = U32(p0); pa[ks][3] = U32(p1); }
        }
        s0 += __shfl_xor_sync(0xffffffffu, s0, 1);
        s0 += __shfl_xor_sync(0xffffffffu, s0, 2);
        s1 += __shfl_xor_sync(0xffffffffu, s1, 1);
        s1 += __shfl_xor_sync(0xffffffffu, s1, 2);
        l0s = l0s * a0 + s0;
        l1s = l1s * a1 + s1;

#pragma unroll
        for (int nt = 0; nt < 8; nt++) {
            o[nt][0] *= a0; o[nt][1] *= a0;
            o[nt][2] *= a1; o[nt][3] *= a1;
        }

        // O += P V (V split, ldmatrix B fragments)
#pragma unroll
        for (int ks = 0; ks < 4; ks++) {
#pragma unroll
            for (int np = 0; np < 4; np++) {
                uint32_t bh4[4], bl4[4];
                ldmx4(bh4, va_h[np] + ks * 32);
                ldmx4(bl4, va_l[np] + ks * 32);
                mma_f16(o[2 * np],     pa[ks][0], pa[ks][1], pa[ks][2], pa[ks][3], bh4[0], bh4[1]);
                mma_f16(o[2 * np],     pa[ks][0], pa[ks][1], pa[ks][2], pa[ks][3], bl4[0], bl4[1]);
                mma_f16(o[2 * np + 1], pa[ks][0], pa[ks][1], pa[ks][2], pa[ks][3], bh4[2], bh4[3]);
                mma_f16(o[2 * np + 1], pa[ks][0], pa[ks][1], pa[ks][2], pa[ks][3], bl4[2], bl4[3]);
            }
        }
    }

    // epilogue: normalize, split, write pre-split O halves [b][s][h*64+d]
    const int bidx = bh / HH, h = bh % HH;
    const float i0 = 1.0f / l0s, i1 = 1.0f / l1s;
    const int r0 = q0 + wr + gid;
#pragma unroll
    for (int nt = 0; nt < 8; nt++) {
        int d = nt * 8 + 2 * tig;
        float v0 = o[nt][0] * i0, v1 = o[nt][1] * i0;
        float v2 = o[nt][2] * i1, v3 = o[nt][3] * i1;
        float h0, l0, h1, l1, h2, l2, h3, l3;
        h_split(v0, h0, l0); h_split(v1, h1, l1);
        h_split(v2, h2, l2); h_split(v3, h3, l3);
        size_t a0 = ((size_t)bidx * SS + r0) * DM + h * DH + d;
        *(uint32_t*)&g_oh[a0] = f22h2(h0, h1);
        *(uint32_t*)&g_ol[a0] = f22h2(l0, l1);
        size_t a1 = a0 + 8 * DM;
        *(uint32_t*)&g_oh[a1] = f22h2(h2, h3);
        *(uint32_t*)&g_ol[a1] = f22h2(l2, l3);
    }
}

// ---------------------------------------------------------------------------
// Kernel 3: output projection; ldmatrix fragment loads.
// ---------------------------------------------------------------------------
#define PROJ_SMEM_HALVES (4 * 128 * QST)
#define PROJ_SMEM_BYTES  (PROJ_SMEM_HALVES * 2)   // 73728

__global__ __launch_bounds__(256, 2) void proj_mma_kernel(
    const float* __restrict__ bo, float* __restrict__ out)
{
    extern __shared__ __half psm[];
    __half* Ah = psm;
    __half* Al = psm + 128 * QST;
    __half* Bh = psm + 2 * 128 * QST;
    __half* Bl = psm + 3 * 128 * QST;

    const int n0 = blockIdx.x * 128;
    const int m0 = blockIdx.y * 128;
    const int tid  = threadIdx.x;
    const int lane = tid & 31, warp = tid >> 5;
    const int wm = (warp >> 2) * 64;
    const int wn = (warp & 3) * 32;
    const int gid = lane >> 2, tig = lane & 3;

    const int arow = (lane & 15), acol = (lane >> 4) << 3;
    const int brow = (lane & 7) + ((lane >> 4) << 3);
    const int bcol = ((lane >> 3) & 1) << 3;

    uint32_t aa_h[4], aa_l[4], ba_h[2], ba_l[2];
#pragma unroll
    for (int mt = 0; mt < 4; mt++) {
        aa_h[mt] = sptr(&Ah[(wm + mt * 16 + arow) * QST + acol]);
        aa_l[mt] = sptr(&Al[(wm + mt * 16 + arow) * QST + acol]);
    }
#pragma unroll
    for (int np = 0; np < 2; np++) {
        ba_h[np] = sptr(&Bh[(wn + np * 16 + brow) * QST + bcol]);
        ba_l[np] = sptr(&Bl[(wn + np * 16 + brow) * QST + bcol]);
    }

    float c[4][4][4] = {};

    for (int k0 = 0; k0 < DM; k0 += 64) {
        __syncthreads();
        for (int idx = tid; idx < 1024; idx += 256) {
            int r = idx >> 3, q8 = (idx & 7) << 3;
            size_t aa = (size_t)(m0 + r) * DM + k0 + q8;
            *(uint4*)&Ah[r * QST + q8] = *(const uint4*)&g_oh[aa];
            *(uint4*)&Al[r * QST + q8] = *(const uint4*)&g_ol[aa];
            size_t ba = (size_t)(n0 + r) * DM + k0 + q8;
            *(uint4*)&Bh[r * QST + q8] = *(const uint4*)&g_woh[ba];
            *(uint4*)&Bl[r * QST + q8] = *(const uint4*)&g_wol[ba];
        }
        __syncthreads();

#pragma unroll
        for (int ks = 0; ks < 4; ks++) {
            uint32_t ah[4][4], al[4][4];
#pragma unroll
            for (int mt = 0; mt < 4; mt++) {
                ldmx4(ah[mt], aa_h[mt] + ks * 32);
                ldmx4(al[mt], aa_l[mt] + ks * 32);
            }
#pragma unroll
            for (int np = 0; np < 2; np++) {
                uint32_t bh4[4], bl4[4];
                ldmx4(bh4, ba_h[np] + ks * 32);
                ldmx4(bl4, ba_l[np] + ks * 32);
#pragma unroll
                for (int mt = 0; mt < 4; mt++) {
                    mma_f16(c[mt][2 * np], ah[mt][0], ah[mt][1], ah[mt][2], ah[mt][3], bh4[0], bh4[1]);
                    mma_f16(c[mt][2 * np], ah[mt][0], ah[mt][1], ah[mt][2], ah[mt][3], bl4[0], bl4[1]);
                    mma_f16(c[mt][2 * np], al[mt][0], al[mt][1], al[mt][2], al[mt][3], bh4[0], bh4[1]);
                    mma_f16(c[mt][2 * np + 1], ah[mt][0], ah[mt][1], ah[mt][2], ah[mt][3], bh4[2], bh4[3]);
                    mma_f16(c[mt][2 * np + 1], ah[mt][0], ah[mt][1], ah[mt][2], ah[mt][3], bl4[2], bl4[3]);
                    mma_f16(c[mt][2 * np + 1], al[mt][0], al[mt][1], al[mt][2], al[mt][3], bh4[2], bh4[3]);
                }
            }
        }
    }

#pragma unroll
    for (int mt = 0; mt < 4; mt++) {
#pragma unroll
        for (int nt = 0; nt < 4; nt++) {
            int m  = m0 + wm + mt * 16 + gid;
            int n  = n0 + wn + nt * 8 + tig * 2;
            float2 v0, v1;
            v0.x = c[mt][nt][0] + bo[n];
            v0.y = c[mt][nt][1] + bo[n + 1];
            v1.x = c[mt][nt][2] + bo[n];
            v1.y = c[mt][nt][3] + bo[n + 1];
            *(float2*)&out[(size_t)m * DM + n]       = v0;
            *(float2*)&out[(size_t)(m + 8) * DM + n] = v1;
        }
    }
}

// ---------------------------------------------------------------------------
extern "C" void kernel_launch(void* const* d_in, const int* in_sizes, int n_in,
                              void* d_out, int out_size)
{
    const float* x  = (const float*)d_in[0];
    const float* Wq = (const float*)d_in[1];
    const float* bq = (const float*)d_in[2];
    const float* Wk = (const float*)d_in[3];
    const float* bk = (const float*)d_in[4];
    const float* Wv = (const float*)d_in[5];
    const float* bv = (const float*)d_in[6];
    const float* Wo = (const float*)d_in[7];
    const float* bo = (const float*)d_in[8];
    float* out = (float*)d_out;

    cudaFuncSetAttribute(qkv_mma_kernel,
                         cudaFuncAttributeMaxDynamicSharedMemorySize,
                         (int)QKV_SMEM_BYTES);
    cudaFuncSetAttribute(attn_mma_kernel,
                         cudaFuncAttributeMaxDynamicSharedMemorySize,
                         (int)ATTN_SMEM_BYTES);
    cudaFuncSetAttribute(proj_mma_kernel,
                         cudaFuncAttributeMaxDynamicSharedMemorySize,
                         (int)PROJ_SMEM_BYTES);

    wsplit_kernel<<<DM * DM / 1024, 256>>>(Wo);
    qkv_mma_kernel<<<dim3(BB * SS / 128, HH), 256, QKV_SMEM_BYTES>>>(
        x, Wq, bq, Wk, bk, Wv, bv);
    attn_mma_kernel<<<dim3(SS / 128, BB * HH), 256, ATTN_SMEM_BYTES>>>();
    proj_mma_kernel<<<dim3(DM / 128, BB * SS / 128), 256, PROJ_SMEM_BYTES>>>(bo, out);
}

// round 12
// speedup vs baseline: 5.1649x; 1.2642x over previous
#include <cuda_runtime.h>
#include <cuda_fp16.h>
#include <cstdint>

#define BB 2
#define SS 2048
#define DM 1024
#define HH 16
#define DH 64
#define NE ((size_t)BB * HH * SS * DH)   // 4M elements per tensor

// Pre-split fp16 scratch (allocation-free rule: __device__ globals)
__device__ __half g_qh[NE];                      // Q*0.125 (single fp16): [bh][s][d]
__device__ __half g_kh[NE], g_kl[NE];            // K hi/lo: [bh][s][d]
__device__ __half g_vth[NE], g_vtl[NE];          // V^T hi/lo: [bh][d][s]
__device__ __half g_oh[NE];                      // attnout (single fp16): [b][s][h*64+d]
__device__ __half g_woh[(size_t)DM * DM], g_wol[(size_t)DM * DM];

// ---------------------------------------------------------------------------
// fp16 helpers (mma.sync m16n8k16 + ldmatrix + cp.async — compute_103-safe)
// ---------------------------------------------------------------------------
__device__ __forceinline__ void h_split(float x, float& hi, float& lo) {
    hi = __half2float(__float2half_rn(x));
    lo = x - hi;
}
__device__ __forceinline__ uint32_t f22h2(float a, float b) {
    __half2 h = __floats2half2_rn(a, b);
    return *(uint32_t*)&h;
}
__device__ __forceinline__ uint32_t sptr(const void* p) {
    return (uint32_t)__cvta_generic_to_shared(p);
}
__device__ __forceinline__ void ldmx4(uint32_t r[4], uint32_t addr) {
    asm volatile("ldmatrix.sync.aligned.m8n8.x4.shared.b16 {%0,%1,%2,%3}, [%4];"
                 : "=r"(r[0]), "=r"(r[1]), "=r"(r[2]), "=r"(r[3]) : "r"(addr));
}
__device__ __forceinline__ void cpa16(uint32_t dst, const void* src) {
    asm volatile("cp.async.cg.shared.global [%0], [%1], 16;"
                 :: "r"(dst), "l"(src) : "memory");
}
#define CP_COMMIT() asm volatile("cp.async.commit_group;" ::: "memory")
#define CP_WAIT0()  asm volatile("cp.async.wait_group 0;" ::: "memory")
__device__ __forceinline__ void mma_f16(float c[4],
                                        uint32_t a0, uint32_t a1,
                                        uint32_t a2, uint32_t a3,
                                        uint32_t b0, uint32_t b1) {
    asm volatile(
        "mma.sync.aligned.m16n8k16.row.col.f32.f16.f16.f32 "
        "{%0,%1,%2,%3}, {%4,%5,%6,%7}, {%8,%9}, {%0,%1,%2,%3};"
        : "+f"(c[0]), "+f"(c[1]), "+f"(c[2]), "+f"(c[3])
        : "r"(a0), "r"(a1), "r"(a2), "r"(a3), "r"(b0), "r"(b1));
}

#define U32(p) (*(const uint32_t*)&(p))

// ---------------------------------------------------------------------------
// Kernel 0: one-shot Wo hi/lo split.
// ---------------------------------------------------------------------------
__global__ __launch_bounds__(256) void wsplit_kernel(const float* __restrict__ w)
{
    int i = (blockIdx.x * 256 + threadIdx.x) * 4;
    float4 v = *(const float4*)&w[i];
    float h0, l0, h1, l1, h2, l2, h3, l3;
    h_split(v.x, h0, l0); h_split(v.y, h1, l1);
    h_split(v.z, h2, l2); h_split(v.w, h3, l3);
    *(uint2*)&g_woh[i] = make_uint2(f22h2(h0, h1), f22h2(h2, h3));
    *(uint2*)&g_wol[i] = make_uint2(f22h2(l0, l1), f22h2(l2, l3));
}

// ---------------------------------------------------------------------------
// Kernel 1: fused QKV projections (full 3-product accuracy; epilogue writes
// Q single fp16, K hi/lo, V^T hi/lo).
// ---------------------------------------------------------------------------
#define QST 72   // smem stride in halves (144 B: ldmatrix rows conflict-free)
#define QKV_SMEM_HALVES (2 * 128 * QST + 2 * 64 * QST)
#define QKV_SMEM_BYTES  (QKV_SMEM_HALVES * 2)     // 55296

__global__ __launch_bounds__(256, 2) void qkv_mma_kernel(
    const float* __restrict__ x,
    const float* __restrict__ Wq, const float* __restrict__ bq,
    const float* __restrict__ Wk, const float* __restrict__ bk,
    const float* __restrict__ Wv, const float* __restrict__ bv)
{
    extern __shared__ __half qsm[];
    __half* Xh = qsm;
    __half* Xl = qsm + 128 * QST;
    __half* Wh = qsm + 2 * 128 * QST;
    __half* Wl = Wh + 64 * QST;

    const int h    = blockIdx.y;
    const int tok0 = blockIdx.x * 128;
    const int tid  = threadIdx.x;
    const int lane = tid & 31, warp = tid >> 5;
    const int gid  = lane >> 2, tig = lane & 3;
    const int wm   = (warp >> 1) * 32;
    const int wn   = (warp & 1) * 32;

    for (int idx = tid; idx < 2048; idx += 256) {
        int r = idx >> 4, d = (idx & 15) << 2;
        float4 v = *(const float4*)&x[(size_t)(tok0 + r) * DM + h * DH + d];
        float h0, l0, h1, l1, h2, l2, h3, l3;
        h_split(v.x, h0, l0); h_split(v.y, h1, l1);
        h_split(v.z, h2, l2); h_split(v.w, h3, l3);
        *(uint2*)&Xh[r * QST + d] = make_uint2(f22h2(h0, h1), f22h2(h2, h3));
        *(uint2*)&Xl[r * QST + d] = make_uint2(f22h2(l0, l1), f22h2(l2, l3));
    }

    const float* Wp[3] = {Wq, Wk, Wv};
    const float* bp[3] = {bq, bk, bv};

    for (int p = 0; p < 3; p++) {
        __syncthreads();
        for (int idx = tid; idx < 1024; idx += 256) {
            int r = idx >> 4, d = (idx & 15) << 2;
            float4 v = *(const float4*)&Wp[p][(size_t)(h * DH + r) * DH + d];
            float h0, l0, h1, l1, h2, l2, h3, l3;
            h_split(v.x, h0, l0); h_split(v.y, h1, l1);
            h_split(v.z, h2, l2); h_split(v.w, h3, l3);
            *(uint2*)&Wh[r * QST + d] = make_uint2(f22h2(h0, h1), f22h2(h2, h3));
            *(uint2*)&Wl[r * QST + d] = make_uint2(f22h2(l0, l1), f22h2(l2, l3));
        }
        __syncthreads();

        float c[2][4][4] = {};
#pragma unroll
        for (int ks = 0; ks < 4; ks++) {
            const int kc = ks * 16 + 2 * tig;
            uint32_t ah[2][4], al[2][4];
#pragma unroll
            for (int mt = 0; mt < 2; mt++) {
                int mr = wm + mt * 16 + gid;
                ah[mt][0] = U32(Xh[mr * QST + kc]);
                ah[mt][1] = U32(Xh[(mr + 8) * QST + kc]);
                ah[mt][2] = U32(Xh[mr * QST + kc + 8]);
                ah[mt][3] = U32(Xh[(mr + 8) * QST + kc + 8]);
                al[mt][0] = U32(Xl[mr * QST + kc]);
                al[mt][1] = U32(Xl[(mr + 8) * QST + kc]);
                al[mt][2] = U32(Xl[mr * QST + kc + 8]);
                al[mt][3] = U32(Xl[(mr + 8) * QST + kc + 8]);
            }
#pragma unroll
            for (int nt = 0; nt < 4; nt++) {
                int nr = wn + nt * 8 + gid;
                uint32_t bh0 = U32(Wh[nr * QST + kc]);
                uint32_t bh1 = U32(Wh[nr * QST + kc + 8]);
                uint32_t bl0 = U32(Wl[nr * QST + kc]);
                uint32_t bl1 = U32(Wl[nr * QST + kc + 8]);
#pragma unroll
                for (int mt = 0; mt < 2; mt++) {
                    mma_f16(c[mt][nt], ah[mt][0], ah[mt][1], ah[mt][2], ah[mt][3], bh0, bh1);
                    mma_f16(c[mt][nt], ah[mt][0], ah[mt][1], ah[mt][2], ah[mt][3], bl0, bl1);
                    mma_f16(c[mt][nt], al[mt][0], al[mt][1], al[mt][2], al[mt][3], bh0, bh1);
                }
            }
        }

        // epilogue: +bias, (Q: *0.125), fp16 encode, store
#pragma unroll
        for (int mt = 0; mt < 2; mt++) {
#pragma unroll
            for (int nt = 0; nt < 4; nt++) {
                int gtok = tok0 + wm + mt * 16 + gid;
                int o    = wn + nt * 8 + 2 * tig;
                float b0 = bp[p][h * DH + o], b1 = bp[p][h * DH + o + 1];
                int bidx = gtok >> 11;
                int s    = gtok & (SS - 1);
                size_t bh_ = (size_t)bidx * HH + h;
                float r0c0 = c[mt][nt][0] + b0, r0c1 = c[mt][nt][1] + b1;
                float r1c0 = c[mt][nt][2] + b0, r1c1 = c[mt][nt][3] + b1;
                if (p == 0) {
                    r0c0 *= 0.125f; r0c1 *= 0.125f;
                    r1c0 *= 0.125f; r1c1 *= 0.125f;
                }
                float h0, l0, h1, l1, h2, l2, h3, l3;
                h_split(r0c0, h0, l0); h_split(r0c1, h1, l1);
                h_split(r1c0, h2, l2); h_split(r1c1, h3, l3);
                if (p == 0) {
                    size_t a0 = (bh_ * SS + s) * DH + o;
                    *(uint32_t*)&g_qh[a0] = f22h2(h0, h1);
                    *(uint32_t*)&g_qh[a0 + 8 * DH] = f22h2(h2, h3);
                } else if (p == 1) {
                    size_t a0 = (bh_ * SS + s) * DH + o;
                    *(uint32_t*)&g_kh[a0] = f22h2(h0, h1);
                    *(uint32_t*)&g_kl[a0] = f22h2(l0, l1);
                    size_t a1 = a0 + 8 * DH;
                    *(uint32_t*)&g_kh[a1] = f22h2(h2, h3);
                    *(uint32_t*)&g_kl[a1] = f22h2(l2, l3);
                } else {
                    size_t vb0 = (bh_ * DH + o) * SS;
                    size_t vb1 = vb0 + SS;
                    g_vth[vb0 + s]     = __float2half_rn(h0);
                    g_vtl[vb0 + s]     = __float2half_rn(l0);
                    g_vth[vb1 + s]     = __float2half_rn(h1);
                    g_vtl[vb1 + s]     = __float2half_rn(l1);
                    g_vth[vb0 + s + 8] = __float2half_rn(h2);
                    g_vtl[vb0 + s + 8] = __float2half_rn(l2);
                    g_vth[vb1 + s + 8] = __float2half_rn(h3);
                    g_vtl[vb1 + s + 8] = __float2half_rn(l3);
                }
            }
        }
    }
}

// ---------------------------------------------------------------------------
// Kernel 2: causal flash attention. Q single fp16 (2-product QK), P in regs,
// cp.async double-buffered K/V staging, ldmatrix fragments.
// ---------------------------------------------------------------------------
#define AQB_H   (128 * QST)                 // Q region, halves
#define KVB_H   (4 * 64 * QST)              // one K/V buffer, halves (Kh,Kl,Vh,Vl)
#define KVB_B   (KVB_H * 2)                 // 36864 bytes
#define AKL_OFF (64 * QST * 2)              // byte offsets within buffer
#define AVH_OFF (2 * 64 * QST * 2)
#define AVL_OFF (3 * 64 * QST * 2)
#define ATTN_SMEM_BYTES ((AQB_H + 2 * KVB_H) * 2)   // 92160

__global__ __launch_bounds__(256, 2) void attn_mma_kernel()
{
    extern __shared__ __half asm_[];
    __half* Qh = asm_;
    const uint32_t sb    = sptr(asm_);
    const uint32_t kvb0  = sb + AQB_H * 2;

    const int qt = gridDim.x - 1 - blockIdx.x;   // heavy tiles first
    const int bh = blockIdx.y;
    const int q0 = qt * 128;
    const __half* Qhg = g_qh + (size_t)bh * SS * DH;
    const __half* Khg = g_kh + (size_t)bh * SS * DH;
    const __half* Klg = g_kl + (size_t)bh * SS * DH;
    const __half* Vhg = g_vth + (size_t)bh * DH * SS;
    const __half* Vlg = g_vtl + (size_t)bh * DH * SS;

    const int tid  = threadIdx.x;
    const int warp = tid >> 5, lane = tid & 31;
    const int gid  = lane >> 2, tig = lane & 3;
    const int wr   = warp * 16;

    // ldmatrix lane addressing
    const int arow = (lane & 15), acol = (lane >> 4) << 3;          // A operand
    const int brow = (lane & 7) + ((lane >> 4) << 3);               // B operand
    const int bcol = ((lane >> 3) & 1) << 3;

    const uint32_t qa = sb + ((wr + arow) * QST + acol) * 2;
    uint32_t kofs[4], vofs[4];
#pragma unroll
    for (int np = 0; np < 4; np++) {
        kofs[np] = ((np * 16 + brow) * QST + bcol) * 2;
        vofs[np] = kofs[np];
    }

    // stage Q once (pure copy)
    for (int idx = tid; idx < 1024; idx += 256) {
        int r = idx >> 3, d8 = (idx & 7) << 3;
        *(uint4*)&Qh[r * QST + d8] = *(const uint4*)&Qhg[(size_t)(q0 + r) * DH + d8];
    }

    const int nkt = 2 * qt + 2;

    // async stage of K/V tile kt into buffer b
    auto stage_kv = [&](int b, int kt) {
        uint32_t base = kvb0 + b * KVB_B;
        for (int idx = tid; idx < 512; idx += 256) {
            int r = idx >> 3, d8 = (idx & 7) << 3;
            uint32_t so = (r * QST + d8) * 2;
            size_t ka = (size_t)(kt * 64 + r) * DH + d8;
            cpa16(base + so, &Khg[ka]);
            cpa16(base + AKL_OFF + so, &Klg[ka]);
            size_t va = (size_t)r * SS + kt * 64 + d8;   // r = d, d8 = s-local
            cpa16(base + AVH_OFF + so, &Vhg[va]);
            cpa16(base + AVL_OFF + so, &Vlg[va]);
        }
        CP_COMMIT();
    };

    stage_kv(0, 0);

    float o[8][4] = {};
    float m0 = -1e30f, m1 = -1e30f, l0s = 0.0f, l1s = 0.0f;

    for (int kt = 0; kt < nkt; kt++) {
        CP_WAIT0();
        __syncthreads();                       // tile kt visible; prior compute done
        if (kt + 1 < nkt) stage_kv((kt + 1) & 1, kt + 1);   // overlap with compute

        const uint32_t kb = kvb0 + (kt & 1) * KVB_B;

        // S = Q K^T (Q single, K split: 2 products)
        float c[8][4] = {};
#pragma unroll
        for (int ks = 0; ks < 4; ks++) {
            uint32_t ah[4];
            ldmx4(ah, qa + ks * 32);
#pragma unroll
            for (int np = 0; np < 4; np++) {
                uint32_t bh4[4], bl4[4];
                ldmx4(bh4, kb + kofs[np] + ks * 32);
                ldmx4(bl4, kb + AKL_OFF + kofs[np] + ks * 32);
                mma_f16(c[2 * np],     ah[0], ah[1], ah[2], ah[3], bh4[0], bh4[1]);
                mma_f16(c[2 * np],     ah[0], ah[1], ah[2], ah[3], bl4[0], bl4[1]);
                mma_f16(c[2 * np + 1], ah[0], ah[1], ah[2], ah[3], bh4[2], bh4[3]);
                mma_f16(c[2 * np + 1], ah[0], ah[1], ah[2], ah[3], bl4[2], bl4[3]);
            }
        }

        // causal mask (diagonal band only)
        const int row0 = q0 + wr + gid, row1 = row0 + 8;
        if (kt >= 2 * qt) {
#pragma unroll
            for (int nt = 0; nt < 8; nt++) {
                int col = kt * 64 + nt * 8 + 2 * tig;
                if (col > row0)     c[nt][0] = -1e30f;
                if (col + 1 > row0) c[nt][1] = -1e30f;
                if (col > row1)     c[nt][2] = -1e30f;
                if (col + 1 > row1) c[nt][3] = -1e30f;
            }
        }

        // online softmax (registers, quad shuffle)
        float mx0 = -1e30f, mx1 = -1e30f;
#pragma unroll
        for (int nt = 0; nt < 8; nt++) {
            mx0 = fmaxf(mx0, fmaxf(c[nt][0], c[nt][1]));
            mx1 = fmaxf(mx1, fmaxf(c[nt][2], c[nt][3]));
        }
        mx0 = fmaxf(mx0, __shfl_xor_sync(0xffffffffu, mx0, 1));
        mx0 = fmaxf(mx0, __shfl_xor_sync(0xffffffffu, mx0, 2));
        mx1 = fmaxf(mx1, __shfl_xor_sync(0xffffffffu, mx1, 1));
        mx1 = fmaxf(mx1, __shfl_xor_sync(0xffffffffu, mx1, 2));
        float mn0 = fmaxf(m0, mx0), mn1 = fmaxf(m1, mx1);
        float a0 = __expf(m0 - mn0), a1 = __expf(m1 - mn1);
        m0 = mn0; m1 = mn1;

        // exp + pack P directly into PV A-fragments
        uint32_t pa[4][4];
        float s0 = 0.0f, s1 = 0.0f;
#pragma unroll
        for (int nt = 0; nt < 8; nt++) {
            __half2 p0 = __floats2half2_rn(__expf(c[nt][0] - mn0),
                                           __expf(c[nt][1] - mn0));
            __half2 p1 = __floats2half2_rn(__expf(c[nt][2] - mn1),
                                           __expf(c[nt][3] - mn1));
            float2 pf0 = __half22float2(p0), pf1 = __half22float2(p1);
            s0 += pf0.x + pf0.y;
            s1 += pf1.x + pf1.y;
            int ks = nt >> 1;
            if ((nt & 1) == 0) { pa[ks][0] = U32(p0); pa[ks][1] = U32(p1); }
            else               { pa[ks][2] = U32(p0); pa[ks][3] = U32(p1); }
        }
        s0 += __shfl_xor_sync(0xffffffffu, s0, 1);
        s0 += __shfl_xor_sync(0xffffffffu, s0, 2);
        s1 += __shfl_xor_sync(0xffffffffu, s1, 1);
        s1 += __shfl_xor_sync(0xffffffffu, s1, 2);
        l0s = l0s * a0 + s0;
        l1s = l1s * a1 + s1;

#pragma unroll
        for (int nt = 0; nt < 8; nt++) {
            o[nt][0] *= a0; o[nt][1] *= a0;
            o[nt][2] *= a1; o[nt][3] *= a1;
        }

        // O += P V (V split, ldmatrix B fragments)
#pragma unroll
        for (int ks = 0; ks < 4; ks++) {
#pragma unroll
            for (int np = 0; np < 4; np++) {
                uint32_t bh4[4], bl4[4];
                ldmx4(bh4, kb + AVH_OFF + vofs[np] + ks * 32);
                ldmx4(bl4, kb + AVL_OFF + vofs[np] + ks * 32);
                mma_f16(o[2 * np],     pa[ks][0], pa[ks][1], pa[ks][2], pa[ks][3], bh4[0], bh4[1]);
                mma_f16(o[2 * np],     pa[ks][0], pa[ks][1], pa[ks][2], pa[ks][3], bl4[0], bl4[1]);
                mma_f16(o[2 * np + 1], pa[ks][0], pa[ks][1], pa[ks][2], pa[ks][3], bh4[2], bh4[3]);
                mma_f16(o[2 * np + 1], pa[ks][0], pa[ks][1], pa[ks][2], pa[ks][3], bl4[2], bl4[3]);
            }
        }
    }

    // epilogue: normalize, write single-fp16 O [b][s][h*64+d]
    const int bidx = bh / HH, h = bh % HH;
    const float i0 = 1.0f / l0s, i1 = 1.0f / l1s;
    const int r0 = q0 + wr + gid;
#pragma unroll
    for (int nt = 0; nt < 8; nt++) {
        int d = nt * 8 + 2 * tig;
        size_t a0 = ((size_t)bidx * SS + r0) * DM + h * DH + d;
        *(uint32_t*)&g_oh[a0] = f22h2(o[nt][0] * i0, o[nt][1] * i0);
        *(uint32_t*)&g_oh[a0 + 8 * DM] = f22h2(o[nt][2] * i1, o[nt][3] * i1);
    }
}

// ---------------------------------------------------------------------------
// Kernel 3: output projection. A single fp16 (2 products), cp.async
// double-buffered staging, ldmatrix fragments.
// ---------------------------------------------------------------------------
#define PAB   (128 * QST * 2)               // one region (A or Bh or Bl), bytes
#define PBUF_B (3 * PAB)                    // 55296 per buffer
#define PROJ_SMEM_BYTES (2 * PBUF_B)        // 110592

__global__ __launch_bounds__(256, 2) void proj_mma_kernel(
    const float* __restrict__ bo, float* __restrict__ out)
{
    extern __shared__ __half psm[];
    const uint32_t sb = sptr(psm);

    const int n0 = blockIdx.x * 128;
    const int m0 = blockIdx.y * 128;
    const int tid  = threadIdx.x;
    const int lane = tid & 31, warp = tid >> 5;
    const int wm = (warp >> 2) * 64;
    const int wn = (warp & 3) * 32;
    const int gid = lane >> 2, tig = lane & 3;

    const int arow = (lane & 15), acol = (lane >> 4) << 3;
    const int brow = (lane & 7) + ((lane >> 4) << 3);
    const int bcol = ((lane >> 3) & 1) << 3;

    uint32_t aofs[4], bofs[2];
#pragma unroll
    for (int mt = 0; mt < 4; mt++)
        aofs[mt] = ((wm + mt * 16 + arow) * QST + acol) * 2;
#pragma unroll
    for (int np = 0; np < 2; np++)
        bofs[np] = ((wn + np * 16 + brow) * QST + bcol) * 2;

    auto stage = [&](int b, int k0) {
        uint32_t base = sb + b * PBUF_B;
        for (int idx = tid; idx < 1024; idx += 256) {
            int r = idx >> 3, q8 = (idx & 7) << 3;
            uint32_t so = (r * QST + q8) * 2;
            cpa16(base + so, &g_oh[(size_t)(m0 + r) * DM + k0 + q8]);
            size_t ba = (size_t)(n0 + r) * DM + k0 + q8;
            cpa16(base + PAB + so, &g_woh[ba]);
            cpa16(base + 2 * PAB + so, &g_wol[ba]);
        }
        CP_COMMIT();
    };

    stage(0, 0);

    float c[4][4][4] = {};

    for (int kc = 0; kc < 16; kc++) {
        CP_WAIT0();
        __syncthreads();
        if (kc + 1 < 16) stage((kc + 1) & 1, (kc + 1) * 64);

        const uint32_t base = sb + (kc & 1) * PBUF_B;
#pragma unroll
        for (int ks = 0; ks < 4; ks++) {
            uint32_t ah[4][4];
#pragma unroll
            for (int mt = 0; mt < 4; mt++)
                ldmx4(ah[mt], base + aofs[mt] + ks * 32);
#pragma unroll
            for (int np = 0; np < 2; np++) {
                uint32_t bh4[4], bl4[4];
                ldmx4(bh4, base + PAB + bofs[np] + ks * 32);
                ldmx4(bl4, base + 2 * PAB + bofs[np] + ks * 32);
#pragma unroll
                for (int mt = 0; mt < 4; mt++) {
                    mma_f16(c[mt][2 * np],     ah[mt][0], ah[mt][1], ah[mt][2], ah[mt][3], bh4[0], bh4[1]);
                    mma_f16(c[mt][2 * np],     ah[mt][0], ah[mt][1], ah[mt][2], ah[mt][3], bl4[0], bl4[1]);
                    mma_f16(c[mt][2 * np + 1], ah[mt][0], ah[mt][1], ah[mt][2], ah[mt][3], bh4[2], bh4[3]);
                    mma_f16(c[mt][2 * np + 1], ah[mt][0], ah[mt][1], ah[mt][2], ah[mt][3], bl4[2], bl4[3]);
                }
            }
        }
    }

#pragma unroll
    for (int mt = 0; mt < 4; mt++) {
#pragma unroll
        for (int nt = 0; nt < 4; nt++) {
            int m  = m0 + wm + mt * 16 + gid;
            int n  = n0 + wn + nt * 8 + tig * 2;
            float2 v0, v1;
            v0.x = c[mt][nt][0] + bo[n];
            v0.y = c[mt][nt][1] + bo[n + 1];
            v1.x = c[mt][nt][2] + bo[n];
            v1.y = c[mt][nt][3] + bo[n + 1];
            *(float2*)&out[(size_t)m * DM + n]       = v0;
            *(float2*)&out[(size_t)(m + 8) * DM + n] = v1;
        }
    }
}

// ---------------------------------------------------------------------------
extern "C" void kernel_launch(void* const* d_in, const int* in_sizes, int n_in,
                              void* d_out, int out_size)
{
    const float* x  = (const float*)d_in[0];
    const float* Wq = (const float*)d_in[1];
    const float* bq = (const float*)d_in[2];
    const float* Wk = (const float*)d_in[3];
    const float* bk = (const float*)d_in[4];
    const float* Wv = (const float*)d_in[5];
    const float* bv = (const float*)d_in[6];
    const float* Wo = (const float*)d_in[7];
    const float* bo = (const float*)d_in[8];
    float* out = (float*)d_out;

    cudaFuncSetAttribute(qkv_mma_kernel,
                         cudaFuncAttributeMaxDynamicSharedMemorySize,
                         (int)QKV_SMEM_BYTES);
    cudaFuncSetAttribute(attn_mma_kernel,
                         cudaFuncAttributeMaxDynamicSharedMemorySize,
                         (int)ATTN_SMEM_BYTES);
    cudaFuncSetAttribute(proj_mma_kernel,
                         cudaFuncAttributeMaxDynamicSharedMemorySize,
                         (int)PROJ_SMEM_BYTES);

    wsplit_kernel<<<DM * DM / 1024, 256>>>(Wo);
    qkv_mma_kernel<<<dim3(BB * SS / 128, HH), 256, QKV_SMEM_BYTES>>>(
        x, Wq, bq, Wk, bk, Wv, bv);
    attn_mma_kernel<<<dim3(SS / 128, BB * HH), 256, ATTN_SMEM_BYTES>>>();
    proj_mma_kernel<<<dim3(DM / 128, BB * SS / 128), 256, PROJ_SMEM_BYTES>>>(bo, out);
}

// round 13
// speedup vs baseline: 7.7519x; 1.5009x over previous
#include <cuda_runtime.h>
#include <cuda_fp16.h>
#include <cstdint>

#define BB 2
#define SS 2048
#define DM 1024
#define HH 16
#define DH 64
#define NE ((size_t)BB * HH * SS * DH)   // 4M elements per tensor

// Pre-rounded fp16 scratch (allocation-free rule: __device__ globals)
__device__ __half g_qh[NE];                      // Q*0.125: [bh][s][d]
__device__ __half g_kh[NE];                      // K:       [bh][s][d]
__device__ __half g_vth[NE];                     // V^T:     [bh][d][s]
__device__ __half g_oh[NE];                      // attnout: [b][s][h*64+d]
__device__ __half g_woh[(size_t)DM * DM];        // Wo

// ---------------------------------------------------------------------------
// fp16 helpers (mma.sync m16n8k16 + ldmatrix + cp.async — compute_103-safe)
// ---------------------------------------------------------------------------
__device__ __forceinline__ void h_split(float x, float& hi, float& lo) {
    hi = __half2float(__float2half_rn(x));
    lo = x - hi;
}
__device__ __forceinline__ uint32_t f22h2(float a, float b) {
    __half2 h = __floats2half2_rn(a, b);
    return *(uint32_t*)&h;
}
__device__ __forceinline__ uint32_t sptr(const void* p) {
    return (uint32_t)__cvta_generic_to_shared(p);
}
__device__ __forceinline__ void ldmx4(uint32_t r[4], uint32_t addr) {
    asm volatile("ldmatrix.sync.aligned.m8n8.x4.shared.b16 {%0,%1,%2,%3}, [%4];"
                 : "=r"(r[0]), "=r"(r[1]), "=r"(r[2]), "=r"(r[3]) : "r"(addr));
}
__device__ __forceinline__ void cpa16(uint32_t dst, const void* src) {
    asm volatile("cp.async.cg.shared.global [%0], [%1], 16;"
                 :: "r"(dst), "l"(src) : "memory");
}
#define CP_COMMIT() asm volatile("cp.async.commit_group;" ::: "memory")
#define CP_WAIT0()  asm volatile("cp.async.wait_group 0;" ::: "memory")
__device__ __forceinline__ void mma_f16(float c[4],
                                        uint32_t a0, uint32_t a1,
                                        uint32_t a2, uint32_t a3,
                                        uint32_t b0, uint32_t b1) {
    asm volatile(
        "mma.sync.aligned.m16n8k16.row.col.f32.f16.f16.f32 "
        "{%0,%1,%2,%3}, {%4,%5,%6,%7}, {%8,%9}, {%0,%1,%2,%3};"
        : "+f"(c[0]), "+f"(c[1]), "+f"(c[2]), "+f"(c[3])
        : "r"(a0), "r"(a1), "r"(a2), "r"(a3), "r"(b0), "r"(b1));
}

#define U32(p) (*(const uint32_t*)&(p))

// ---------------------------------------------------------------------------
// Kernel 0: one-shot Wo fp16 round (hi only).
// ---------------------------------------------------------------------------
__global__ __launch_bounds__(256) void wsplit_kernel(const float* __restrict__ w)
{
    int i = (blockIdx.x * 256 + threadIdx.x) * 4;
    float4 v = *(const float4*)&w[i];
    *(uint2*)&g_woh[i] = make_uint2(f22h2(v.x, v.y), f22h2(v.z, v.w));
}

// ---------------------------------------------------------------------------
// Kernel 1: fused QKV projections (full 3-product accuracy; epilogue writes
// Q/K single fp16, V^T single fp16).
// ---------------------------------------------------------------------------
#define QST 72   // smem stride in halves (144 B: ldmatrix rows conflict-free)
#define QKV_SMEM_HALVES (2 * 128 * QST + 2 * 64 * QST)
#define QKV_SMEM_BYTES  (QKV_SMEM_HALVES * 2)     // 55296

__global__ __launch_bounds__(256, 2) void qkv_mma_kernel(
    const float* __restrict__ x,
    const float* __restrict__ Wq, const float* __restrict__ bq,
    const float* __restrict__ Wk, const float* __restrict__ bk,
    const float* __restrict__ Wv, const float* __restrict__ bv)
{
    extern __shared__ __half qsm[];
    __half* Xh = qsm;
    __half* Xl = qsm + 128 * QST;
    __half* Wh = qsm + 2 * 128 * QST;
    __half* Wl = Wh + 64 * QST;

    const int h    = blockIdx.y;
    const int tok0 = blockIdx.x * 128;
    const int tid  = threadIdx.x;
    const int lane = tid & 31, warp = tid >> 5;
    const int gid  = lane >> 2, tig = lane & 3;
    const int wm   = (warp >> 1) * 32;
    const int wn   = (warp & 1) * 32;

    for (int idx = tid; idx < 2048; idx += 256) {
        int r = idx >> 4, d = (idx & 15) << 2;
        float4 v = *(const float4*)&x[(size_t)(tok0 + r) * DM + h * DH + d];
        float h0, l0, h1, l1, h2, l2, h3, l3;
        h_split(v.x, h0, l0); h_split(v.y, h1, l1);
        h_split(v.z, h2, l2); h_split(v.w, h3, l3);
        *(uint2*)&Xh[r * QST + d] = make_uint2(f22h2(h0, h1), f22h2(h2, h3));
        *(uint2*)&Xl[r * QST + d] = make_uint2(f22h2(l0, l1), f22h2(l2, l3));
    }

    const float* Wp[3] = {Wq, Wk, Wv};
    const float* bp[3] = {bq, bk, bv};

    for (int p = 0; p < 3; p++) {
        __syncthreads();
        for (int idx = tid; idx < 1024; idx += 256) {
            int r = idx >> 4, d = (idx & 15) << 2;
            float4 v = *(const float4*)&Wp[p][(size_t)(h * DH + r) * DH + d];
            float h0, l0, h1, l1, h2, l2, h3, l3;
            h_split(v.x, h0, l0); h_split(v.y, h1, l1);
            h_split(v.z, h2, l2); h_split(v.w, h3, l3);
            *(uint2*)&Wh[r * QST + d] = make_uint2(f22h2(h0, h1), f22h2(h2, h3));
            *(uint2*)&Wl[r * QST + d] = make_uint2(f22h2(l0, l1), f22h2(l2, l3));
        }
        __syncthreads();

        float c[2][4][4] = {};
#pragma unroll
        for (int ks = 0; ks < 4; ks++) {
            const int kc = ks * 16 + 2 * tig;
            uint32_t ah[2][4], al[2][4];
#pragma unroll
            for (int mt = 0; mt < 2; mt++) {
                int mr = wm + mt * 16 + gid;
                ah[mt][0] = U32(Xh[mr * QST + kc]);
                ah[mt][1] = U32(Xh[(mr + 8) * QST + kc]);
                ah[mt][2] = U32(Xh[mr * QST + kc + 8]);
                ah[mt][3] = U32(Xh[(mr + 8) * QST + kc + 8]);
                al[mt][0] = U32(Xl[mr * QST + kc]);
                al[mt][1] = U32(Xl[(mr + 8) * QST + kc]);
                al[mt][2] = U32(Xl[mr * QST + kc + 8]);
                al[mt][3] = U32(Xl[(mr + 8) * QST + kc + 8]);
            }
#pragma unroll
            for (int nt = 0; nt < 4; nt++) {
                int nr = wn + nt * 8 + gid;
                uint32_t bh0 = U32(Wh[nr * QST + kc]);
                uint32_t bh1 = U32(Wh[nr * QST + kc + 8]);
                uint32_t bl0 = U32(Wl[nr * QST + kc]);
                uint32_t bl1 = U32(Wl[nr * QST + kc + 8]);
#pragma unroll
                for (int mt = 0; mt < 2; mt++) {
                    mma_f16(c[mt][nt], ah[mt][0], ah[mt][1], ah[mt][2], ah[mt][3], bh0, bh1);
                    mma_f16(c[mt][nt], ah[mt][0], ah[mt][1], ah[mt][2], ah[mt][3], bl0, bl1);
                    mma_f16(c[mt][nt], al[mt][0], al[mt][1], al[mt][2], al[mt][3], bh0, bh1);
                }
            }
        }

        // epilogue: +bias, (Q: *0.125), round to fp16, store
#pragma unroll
        for (int mt = 0; mt < 2; mt++) {
#pragma unroll
            for (int nt = 0; nt < 4; nt++) {
                int gtok = tok0 + wm + mt * 16 + gid;
                int o    = wn + nt * 8 + 2 * tig;
                float b0 = bp[p][h * DH + o], b1 = bp[p][h * DH + o + 1];
                int bidx = gtok >> 11;
                int s    = gtok & (SS - 1);
                size_t bh_ = (size_t)bidx * HH + h;
                float r0c0 = c[mt][nt][0] + b0, r0c1 = c[mt][nt][1] + b1;
                float r1c0 = c[mt][nt][2] + b0, r1c1 = c[mt][nt][3] + b1;
                if (p == 0) {
                    r0c0 *= 0.125f; r0c1 *= 0.125f;
                    r1c0 *= 0.125f; r1c1 *= 0.125f;
                }
                if (p < 2) {
                    __half* H = (p == 0) ? g_qh : g_kh;
                    size_t a0 = (bh_ * SS + s) * DH + o;
                    *(uint32_t*)&H[a0] = f22h2(r0c0, r0c1);
                    *(uint32_t*)&H[a0 + 8 * DH] = f22h2(r1c0, r1c1);
                } else {
                    size_t vb0 = (bh_ * DH + o) * SS;
                    size_t vb1 = vb0 + SS;
                    g_vth[vb0 + s]     = __float2half_rn(r0c0);
                    g_vth[vb1 + s]     = __float2half_rn(r0c1);
                    g_vth[vb0 + s + 8] = __float2half_rn(r1c0);
                    g_vth[vb1 + s + 8] = __float2half_rn(r1c1);
                }
            }
        }
    }
}

// ---------------------------------------------------------------------------
// Kernel 2: causal flash attention. All operands single fp16 (errors
// dominated by storage rounding), P in regs, cp.async double-buffered,
// ldmatrix fragments. 64 MMAs per 64-key tile.
// ---------------------------------------------------------------------------
#define AQB_H   (128 * QST)                 // Q region, halves
#define KVB_H   (2 * 64 * QST)              // one K/V buffer, halves (Kh,Vh)
#define KVB_B   (KVB_H * 2)                 // 18432 bytes
#define AVH_OFF (64 * QST * 2)              // V offset within buffer
#define ATTN_SMEM_BYTES ((AQB_H + 2 * KVB_H) * 2)   // 55296

__global__ __launch_bounds__(256, 2) void attn_mma_kernel()
{
    extern __shared__ __half asm_[];
    __half* Qh = asm_;
    const uint32_t sb    = sptr(asm_);
    const uint32_t kvb0  = sb + AQB_H * 2;

    const int qt = gridDim.x - 1 - blockIdx.x;   // heavy tiles first
    const int bh = blockIdx.y;
    const int q0 = qt * 128;
    const __half* Qhg = g_qh + (size_t)bh * SS * DH;
    const __half* Khg = g_kh + (size_t)bh * SS * DH;
    const __half* Vhg = g_vth + (size_t)bh * DH * SS;

    const int tid  = threadIdx.x;
    const int warp = tid >> 5, lane = tid & 31;
    const int gid  = lane >> 2, tig = lane & 3;
    const int wr   = warp * 16;

    // ldmatrix lane addressing
    const int arow = (lane & 15), acol = (lane >> 4) << 3;          // A operand
    const int brow = (lane & 7) + ((lane >> 4) << 3);               // B operand
    const int bcol = ((lane >> 3) & 1) << 3;

    const uint32_t qa = sb + ((wr + arow) * QST + acol) * 2;
    uint32_t bofs[4];
#pragma unroll
    for (int np = 0; np < 4; np++)
        bofs[np] = ((np * 16 + brow) * QST + bcol) * 2;

    // stage Q once (pure copy)
    for (int idx = tid; idx < 1024; idx += 256) {
        int r = idx >> 3, d8 = (idx & 7) << 3;
        *(uint4*)&Qh[r * QST + d8] = *(const uint4*)&Qhg[(size_t)(q0 + r) * DH + d8];
    }

    const int nkt = 2 * qt + 2;

    // async stage of K/V tile kt into buffer b
    auto stage_kv = [&](int b, int kt) {
        uint32_t base = kvb0 + b * KVB_B;
        for (int idx = tid; idx < 512; idx += 256) {
            int r = idx >> 3, d8 = (idx & 7) << 3;
            uint32_t so = (r * QST + d8) * 2;
            cpa16(base + so, &Khg[(size_t)(kt * 64 + r) * DH + d8]);
            cpa16(base + AVH_OFF + so, &Vhg[(size_t)r * SS + kt * 64 + d8]);
        }
        CP_COMMIT();
    };

    stage_kv(0, 0);

    float o[8][4] = {};
    float m0 = -1e30f, m1 = -1e30f, l0s = 0.0f, l1s = 0.0f;

    for (int kt = 0; kt < nkt; kt++) {
        CP_WAIT0();
        __syncthreads();                       // tile kt visible; prior compute done
        if (kt + 1 < nkt) stage_kv((kt + 1) & 1, kt + 1);   // overlap with compute

        const uint32_t kb = kvb0 + (kt & 1) * KVB_B;

        // S = Q K^T (single fp16 operands)
        float c[8][4] = {};
#pragma unroll
        for (int ks = 0; ks < 4; ks++) {
            uint32_t ah[4];
            ldmx4(ah, qa + ks * 32);
#pragma unroll
            for (int np = 0; np < 4; np++) {
                uint32_t bh4[4];
                ldmx4(bh4, kb + bofs[np] + ks * 32);
                mma_f16(c[2 * np],     ah[0], ah[1], ah[2], ah[3], bh4[0], bh4[1]);
                mma_f16(c[2 * np + 1], ah[0], ah[1], ah[2], ah[3], bh4[2], bh4[3]);
            }
        }

        // causal mask (diagonal band only)
        const int row0 = q0 + wr + gid, row1 = row0 + 8;
        if (kt >= 2 * qt) {
#pragma unroll
            for (int nt = 0; nt < 8; nt++) {
                int col = kt * 64 + nt * 8 + 2 * tig;
                if (col > row0)     c[nt][0] = -1e30f;
                if (col + 1 > row0) c[nt][1] = -1e30f;
                if (col > row1)     c[nt][2] = -1e30f;
                if (col + 1 > row1) c[nt][3] = -1e30f;
            }
        }

        // online softmax (registers, quad shuffle)
        float mx0 = -1e30f, mx1 = -1e30f;
#pragma unroll
        for (int nt = 0; nt < 8; nt++) {
            mx0 = fmaxf(mx0, fmaxf(c[nt][0], c[nt][1]));
            mx1 = fmaxf(mx1, fmaxf(c[nt][2], c[nt][3]));
        }
        mx0 = fmaxf(mx0, __shfl_xor_sync(0xffffffffu, mx0, 1));
        mx0 = fmaxf(mx0, __shfl_xor_sync(0xffffffffu, mx0, 2));
        mx1 = fmaxf(mx1, __shfl_xor_sync(0xffffffffu, mx1, 1));
        mx1 = fmaxf(mx1, __shfl_xor_sync(0xffffffffu, mx1, 2));
        float mn0 = fmaxf(m0, mx0), mn1 = fmaxf(m1, mx1);
        float a0 = __expf(m0 - mn0), a1 = __expf(m1 - mn1);
        m0 = mn0; m1 = mn1;

        // exp + pack P directly into PV A-fragments
        uint32_t pa[4][4];
        float s0 = 0.0f, s1 = 0.0f;
#pragma unroll
        for (int nt = 0; nt < 8; nt++) {
            __half2 p0 = __floats2half2_rn(__expf(c[nt][0] - mn0),
                                           __expf(c[nt][1] - mn0));
            __half2 p1 = __floats2half2_rn(__expf(c[nt][2] - mn1),
                                           __expf(c[nt][3] - mn1));
            float2 pf0 = __half22float2(p0), pf1 = __half22float2(p1);
            s0 += pf0.x + pf0.y;
            s1 += pf1.x + pf1.y;
            int ks = nt >> 1;
            if ((nt & 1) == 0) { pa[ks][0] = U32(p0); pa[ks][1] = U32(p1); }
            else               { pa[ks][2] = U32(p0); pa[ks][3] = U32(p1); }
        }
        s0 += __shfl_xor_sync(0xffffffffu, s0, 1);
        s0 += __shfl_xor_sync(0xffffffffu, s0, 2);
        s1 += __shfl_xor_sync(0xffffffffu, s1, 1);
        s1 += __shfl_xor_sync(0xffffffffu, s1, 2);
        l0s = l0s * a0 + s0;
        l1s = l1s * a1 + s1;

#pragma unroll
        for (int nt = 0; nt < 8; nt++) {
            o[nt][0] *= a0; o[nt][1] *= a0;
            o[nt][2] *= a1; o[nt][3] *= a1;
        }

        // O += P V (single fp16 V)
#pragma unroll
        for (int ks = 0; ks < 4; ks++) {
#pragma unroll
            for (int np = 0; np < 4; np++) {
                uint32_t bh4[4];
                ldmx4(bh4, kb + AVH_OFF + bofs[np] + ks * 32);
                mma_f16(o[2 * np],     pa[ks][0], pa[ks][1], pa[ks][2], pa[ks][3], bh4[0], bh4[1]);
                mma_f16(o[2 * np + 1], pa[ks][0], pa[ks][1], pa[ks][2], pa[ks][3], bh4[2], bh4[3]);
            }
        }
    }

    // epilogue: normalize, write single-fp16 O [b][s][h*64+d]
    const int bidx = bh / HH, h = bh % HH;
    const float i0 = 1.0f / l0s, i1 = 1.0f / l1s;
    const int r0 = q0 + wr + gid;
#pragma unroll
    for (int nt = 0; nt < 8; nt++) {
        int d = nt * 8 + 2 * tig;
        size_t a0 = ((size_t)bidx * SS + r0) * DM + h * DH + d;
        *(uint32_t*)&g_oh[a0] = f22h2(o[nt][0] * i0, o[nt][1] * i0);
        *(uint32_t*)&g_oh[a0 + 8 * DM] = f22h2(o[nt][2] * i1, o[nt][3] * i1);
    }
}

// ---------------------------------------------------------------------------
// Kernel 3: output projection. Single fp16 A and Wo (1 MMA per pair),
// cp.async double-buffered staging, ldmatrix fragments.
// ---------------------------------------------------------------------------
#define PAB   (128 * QST * 2)               // one region (A or B), bytes
#define PBUF_B (2 * PAB)                    // 36864 per buffer
#define PROJ_SMEM_BYTES (2 * PBUF_B)        // 73728

__global__ __launch_bounds__(256, 2) void proj_mma_kernel(
    const float* __restrict__ bo, float* __restrict__ out)
{
    extern __shared__ __half psm[];
    const uint32_t sb = sptr(psm);

    const int n0 = blockIdx.x * 128;
    const int m0 = blockIdx.y * 128;
    const int tid  = threadIdx.x;
    const int lane = tid & 31, warp = tid >> 5;
    const int wm = (warp >> 2) * 64;
    const int wn = (warp & 3) * 32;
    const int gid = lane >> 2, tig = lane & 3;

    const int arow = (lane & 15), acol = (lane >> 4) << 3;
    const int brow = (lane & 7) + ((lane >> 4) << 3);
    const int bcol = ((lane >> 3) & 1) << 3;

    uint32_t aofs[4], bofs[2];
#pragma unroll
    for (int mt = 0; mt < 4; mt++)
        aofs[mt] = ((wm + mt * 16 + arow) * QST + acol) * 2;
#pragma unroll
    for (int np = 0; np < 2; np++)
        bofs[np] = ((wn + np * 16 + brow) * QST + bcol) * 2;

    auto stage = [&](int b, int k0) {
        uint32_t base = sb + b * PBUF_B;
        for (int idx = tid; idx < 1024; idx += 256) {
            int r = idx >> 3, q8 = (idx & 7) << 3;
            uint32_t so = (r * QST + q8) * 2;
            cpa16(base + so, &g_oh[(size_t)(m0 + r) * DM + k0 + q8]);
            cpa16(base + PAB + so, &g_woh[(size_t)(n0 + r) * DM + k0 + q8]);
        }
        CP_COMMIT();
    };

    stage(0, 0);

    float c[4][4][4] = {};

    for (int kc = 0; kc < 16; kc++) {
        CP_WAIT0();
        __syncthreads();
        if (kc + 1 < 16) stage((kc + 1) & 1, (kc + 1) * 64);

        const uint32_t base = sb + (kc & 1) * PBUF_B;
#pragma unroll
        for (int ks = 0; ks < 4; ks++) {
            uint32_t ah[4][4];
#pragma unroll
            for (int mt = 0; mt < 4; mt++)
                ldmx4(ah[mt], base + aofs[mt] + ks * 32);
#pragma unroll
            for (int np = 0; np < 2; np++) {
                uint32_t bh4[4];
                ldmx4(bh4, base + PAB + bofs[np] + ks * 32);
#pragma unroll
                for (int mt = 0; mt < 4; mt++) {
                    mma_f16(c[mt][2 * np],     ah[mt][0], ah[mt][1], ah[mt][2], ah[mt][3], bh4[0], bh4[1]);
                    mma_f16(c[mt][2 * np + 1], ah[mt][0], ah[mt][1], ah[mt][2], ah[mt][3], bh4[2], bh4[3]);
                }
            }
        }
    }

#pragma unroll
    for (int mt = 0; mt < 4; mt++) {
#pragma unroll
        for (int nt = 0; nt < 4; nt++) {
            int m  = m0 + wm + mt * 16 + gid;
            int n  = n0 + wn + nt * 8 + tig * 2;
            float2 v0, v1;
            v0.x = c[mt][nt][0] + bo[n];
            v0.y = c[mt][nt][1] + bo[n + 1];
            v1.x = c[mt][nt][2] + bo[n];
            v1.y = c[mt][nt][3] + bo[n + 1];
            *(float2*)&out[(size_t)m * DM + n]       = v0;
            *(float2*)&out[(size_t)(m + 8) * DM + n] = v1;
        }
    }
}

// ---------------------------------------------------------------------------
extern "C" void kernel_launch(void* const* d_in, const int* in_sizes, int n_in,
                              void* d_out, int out_size)
{
    const float* x  = (const float*)d_in[0];
    const float* Wq = (const float*)d_in[1];
    const float* bq = (const float*)d_in[2];
    const float* Wk = (const float*)d_in[3];
    const float* bk = (const float*)d_in[4];
    const float* Wv = (const float*)d_in[5];
    const float* bv = (const float*)d_in[6];
    const float* Wo = (const float*)d_in[7];
    const float* bo = (const float*)d_in[8];
    float* out = (float*)d_out;

    cudaFuncSetAttribute(qkv_mma_kernel,
                         cudaFuncAttributeMaxDynamicSharedMemorySize,
                         (int)QKV_SMEM_BYTES);
    cudaFuncSetAttribute(attn_mma_kernel,
                         cudaFuncAttributeMaxDynamicSharedMemorySize,
                         (int)ATTN_SMEM_BYTES);
    cudaFuncSetAttribute(proj_mma_kernel,
                         cudaFuncAttributeMaxDynamicSharedMemorySize,
                         (int)PROJ_SMEM_BYTES);

    wsplit_kernel<<<DM * DM / 1024, 256>>>(Wo);
    qkv_mma_kernel<<<dim3(BB * SS / 128, HH), 256, QKV_SMEM_BYTES>>>(
        x, Wq, bq, Wk, bk, Wv, bv);
    attn_mma_kernel<<<dim3(SS / 128, BB * HH), 256, ATTN_SMEM_BYTES>>>();
    proj_mma_kernel<<<dim3(DM / 128, BB * SS / 128), 256, PROJ_SMEM_BYTES>>>(bo, out);
}